// round 1
// baseline (speedup 1.0000x reference)
#include <cuda_runtime.h>

// ---------------------------------------------------------------------------
// InterleavedHeadAttention — fp32 baseline
//   B=2, S=1024, HID=1024, H=16, P=2, D=64, sv = S*P = 2048
//
// Algebraic restructuring:
//   - head mixing folded into projection weights:
//       Weff[(h,p,d), e] = sum_m alpha[m,h,p] * W[m*64+d, e]
//     => Qm[b][h][n*2+p][d] = sum_e x[b,n,e] * Weff_q[(h,p,d), e]
//   - collapse folded into Wo:
//       Wo_eff[f][(o,d)] = sum_h collapse[h,o] * Wo[f, h*64+d]
//     => out[b,n,f] = sum_{o,d} Attn[b][o>>1][n*2+(o&1)][d] * Wo_eff[f][(o,d)]
// ---------------------------------------------------------------------------

#define NB 2
#define SEQ 1024
#define HIDD 1024
#define NH 16
#define NP 2
#define HD 64
#define SVLEN (SEQ * NP)        // 2048
#define MTOK (NB * SEQ)         // 2048
#define NPROJ (NH * NP * HD)    // 2048
#define ATTN_SCALE 0.125f

#define NEG_INF __int_as_float(0xff800000)

// scratch (device globals; allocation inside kernel_launch is forbidden)
__device__ float g_Weff[3][NPROJ][HIDD];      // 3 x 8.4 MB
__device__ float g_Woeff[HIDD][NPROJ];        // 8.4 MB
__device__ float g_Q[NB * NH][SVLEN][HD];     // 16.8 MB
__device__ float g_K[NB * NH][SVLEN][HD];
__device__ float g_V[NB * NH][SVLEN][HD];
__device__ float g_Aout[NB * NH][SVLEN][HD];

// ---------------------------------------------------------------------------
// Build effective projection weights (q/k/v selected by blockIdx.y)
// ---------------------------------------------------------------------------
__global__ __launch_bounds__(256) void build_weff_k(
    const float* __restrict__ Wq, const float* __restrict__ Wk,
    const float* __restrict__ Wv,
    const float* __restrict__ aq, const float* __restrict__ ak,
    const float* __restrict__ av)
{
    int w = blockIdx.y;
    const float* W = (w == 0) ? Wq : (w == 1) ? Wk : Wv;
    const float* A = (w == 0) ? aq : (w == 1) ? ak : av;
    int idx = blockIdx.x * 256 + threadIdx.x;   // NPROJ*HIDD total
    int r = idx >> 10;            // row (h,p,d)
    int e = idx & 1023;
    int h = r >> 7, p = (r >> 6) & 1, d = r & 63;
    float acc = 0.f;
#pragma unroll
    for (int m = 0; m < NH; m++)
        acc += A[m * (NH * NP) + h * NP + p] * W[(m * HD + d) * HIDD + e];
    g_Weff[w][r][e] = acc;
}

// ---------------------------------------------------------------------------
// Build effective output weights
// ---------------------------------------------------------------------------
__global__ __launch_bounds__(256) void build_woeff_k(
    const float* __restrict__ Wo, const float* __restrict__ cl)
{
    int idx = blockIdx.x * 256 + threadIdx.x;   // HIDD*NPROJ total
    int f = idx >> 11;
    int c = idx & 2047;
    int o = c >> 6, d = c & 63;
    float acc = 0.f;
#pragma unroll
    for (int h = 0; h < NH; h++)
        acc += cl[h * (NH * NP) + o] * Wo[f * HIDD + h * HD + d];
    g_Woeff[f][c] = acc;
}

// ---------------------------------------------------------------------------
// 128x128x8 NT SGEMM, 256 threads, 8x8 per thread.
// MODE 0: A = x (plain), B = g_Weff[which], epilogue scatters into g_Q/K/V.
// MODE 1: A = gather from g_Aout, B = g_Woeff, epilogue writes d_out.
// ---------------------------------------------------------------------------
template <int MODE>
__global__ __launch_bounds__(256, 2) void sgemm_k(
    const float* __restrict__ Ag, int which, float* __restrict__ Cout, int Kdim)
{
    __shared__ float As[8][128];
    __shared__ float Bs[8][128];
    const float* Bw = (MODE == 0) ? &g_Weff[which][0][0] : &g_Woeff[0][0];
    int tid = threadIdx.x;
    int tr = tid >> 4, tc = tid & 15;
    int bm = blockIdx.y * 128, bn = blockIdx.x * 128;
    int larow = tid >> 1;                 // 0..127
    int lak = (tid & 1) * 4;              // 0 or 4

    float acc[8][8];
#pragma unroll
    for (int i = 0; i < 8; i++)
#pragma unroll
        for (int j = 0; j < 8; j++) acc[i][j] = 0.f;

    for (int k0 = 0; k0 < Kdim; k0 += 8) {
        float4 a4;
        if (MODE == 0) {
            a4 = *(const float4*)(Ag + (size_t)(bm + larow) * Kdim + (k0 + lak));
        } else {
            int t = bm + larow;
            int b = t >> 10, n = t & 1023;
            int c = k0 + lak;
            int o = c >> 6, d = c & 63;
            a4 = *(const float4*)(&g_Aout[b * NH + (o >> 1)][n * NP + (o & 1)][d]);
        }
        As[lak + 0][larow] = a4.x; As[lak + 1][larow] = a4.y;
        As[lak + 2][larow] = a4.z; As[lak + 3][larow] = a4.w;
        float4 b4 = *(const float4*)(Bw + (size_t)(bn + larow) * Kdim + (k0 + lak));
        Bs[lak + 0][larow] = b4.x; Bs[lak + 1][larow] = b4.y;
        Bs[lak + 2][larow] = b4.z; Bs[lak + 3][larow] = b4.w;
        __syncthreads();
#pragma unroll
        for (int kk = 0; kk < 8; kk++) {
            float ra[8], rb[8];
            *(float4*)&ra[0] = *(const float4*)&As[kk][tr * 8];
            *(float4*)&ra[4] = *(const float4*)&As[kk][tr * 8 + 4];
            *(float4*)&rb[0] = *(const float4*)&Bs[kk][tc * 8];
            *(float4*)&rb[4] = *(const float4*)&Bs[kk][tc * 8 + 4];
#pragma unroll
            for (int i = 0; i < 8; i++)
#pragma unroll
                for (int j = 0; j < 8; j++)
                    acc[i][j] += ra[i] * rb[j];
        }
        __syncthreads();
    }

    if (MODE == 0) {
        float* dst0 = (which == 0) ? &g_Q[0][0][0]
                    : (which == 1) ? &g_K[0][0][0] : &g_V[0][0][0];
        int r = bn + tc * 8;                   // 8 consecutive cols stay in one d-block
        int h = r >> 7, p = (r >> 6) & 1, d = r & 63;
#pragma unroll
        for (int i = 0; i < 8; i++) {
            int t = bm + tr * 8 + i;
            int b = t >> 10, n = t & 1023;
            float* dst = dst0 + ((size_t)(b * NH + h) * SVLEN + n * NP + p) * HD + d;
            *(float4*)dst       = make_float4(acc[i][0], acc[i][1], acc[i][2], acc[i][3]);
            *(float4*)(dst + 4) = make_float4(acc[i][4], acc[i][5], acc[i][6], acc[i][7]);
        }
    } else {
#pragma unroll
        for (int i = 0; i < 8; i++) {
            int t = bm + tr * 8 + i;
            float* dst = Cout + (size_t)t * HIDD + bn + tc * 8;
            *(float4*)dst       = make_float4(acc[i][0], acc[i][1], acc[i][2], acc[i][3]);
            *(float4*)(dst + 4) = make_float4(acc[i][4], acc[i][5], acc[i][6], acc[i][7]);
        }
    }
}

// ---------------------------------------------------------------------------
// Causal flash attention, fp32 online softmax.
// Block: 256 threads, q-tile 128 rows, k-tile 64 cols, per-thread 8x4 tiles.
// grid = (16 q-tiles, 32 bh). Heavy q-tiles launched first.
// ---------------------------------------------------------------------------
#define PADW 68
#define SMEM_ATTN ((128 + 64 + 64 + 128) * PADW * 4)

__global__ __launch_bounds__(256) void attn_k()
{
    extern __shared__ float sm[];
    float* Qs = sm;                       // [128][PADW]
    float* Ks = Qs + 128 * PADW;          // [64][PADW]
    float* Vs = Ks + 64 * PADW;           // [64][PADW]
    float* Ps = Vs + 64 * PADW;           // [128][PADW]

    int bh = blockIdx.y;
    int qt = (gridDim.x - 1) - blockIdx.x;    // heavy tiles first
    int qstart = qt * 128;
    const float* Qg = &g_Q[bh][0][0];
    const float* Kg = &g_K[bh][0][0];
    const float* Vg = &g_V[bh][0][0];

    int tid = threadIdx.x;
    int tr = tid >> 4;     // 0..15 -> rows tr*8..+7
    int tc = tid & 15;     // cols tc*4..+3

    // load Q tile (128 x 64)
#pragma unroll
    for (int it = 0; it < 8; it++) {
        int chunk = tid + 256 * it;
        int row = chunk >> 4;
        int d0 = (chunk & 15) * 4;
        *(float4*)(Qs + row * PADW + d0) =
            *(const float4*)(Qg + (size_t)(qstart + row) * HD + d0);
    }

    float mrow[8], lrow[8], O[8][4];
#pragma unroll
    for (int i = 0; i < 8; i++) {
        mrow[i] = NEG_INF; lrow[i] = 0.f;
#pragma unroll
        for (int j = 0; j < 4; j++) O[i][j] = 0.f;
    }
    __syncthreads();

    int jmax = 2 * qt + 1;
    for (int jt = 0; jt <= jmax; jt++) {
        int kstart = jt * 64;
        // load K,V tiles (64 x 64 each)
#pragma unroll
        for (int it = 0; it < 4; it++) {
            int chunk = tid + 256 * it;
            int row = chunk >> 4;
            int d0 = (chunk & 15) * 4;
            *(float4*)(Ks + row * PADW + d0) =
                *(const float4*)(Kg + (size_t)(kstart + row) * HD + d0);
            *(float4*)(Vs + row * PADW + d0) =
                *(const float4*)(Vg + (size_t)(kstart + row) * HD + d0);
        }
        __syncthreads();

        // scores: S = Q K^T  (8x4 per thread)
        float s[8][4];
#pragma unroll
        for (int i = 0; i < 8; i++)
#pragma unroll
            for (int j = 0; j < 4; j++) s[i][j] = 0.f;
#pragma unroll 4
        for (int d = 0; d < 64; d++) {
            float ra[8], rb[4];
#pragma unroll
            for (int i = 0; i < 8; i++) ra[i] = Qs[(tr * 8 + i) * PADW + d];
#pragma unroll
            for (int j = 0; j < 4; j++) rb[j] = Ks[(tc * 4 + j) * PADW + d];
#pragma unroll
            for (int i = 0; i < 8; i++)
#pragma unroll
                for (int j = 0; j < 4; j++)
                    s[i][j] += ra[i] * rb[j];
        }
#pragma unroll
        for (int i = 0; i < 8; i++)
#pragma unroll
            for (int j = 0; j < 4; j++) s[i][j] *= ATTN_SCALE;
        // causal mask (only tiles touching the diagonal)
        if (kstart + 63 > qstart + tr * 8) {
#pragma unroll
            for (int i = 0; i < 8; i++)
#pragma unroll
                for (int j = 0; j < 4; j++)
                    if (kstart + tc * 4 + j > qstart + tr * 8 + i) s[i][j] = NEG_INF;
        }

        // online softmax update. Threads sharing tr occupy a contiguous
        // 16-lane half-warp -> xor-shuffles 1,2,4,8 reduce across the row.
        float newm[8], al[8], rsum[8];
#pragma unroll
        for (int i = 0; i < 8; i++) {
            float mx = fmaxf(fmaxf(s[i][0], s[i][1]), fmaxf(s[i][2], s[i][3]));
            mx = fmaxf(mx, __shfl_xor_sync(0xffffffffu, mx, 1));
            mx = fmaxf(mx, __shfl_xor_sync(0xffffffffu, mx, 2));
            mx = fmaxf(mx, __shfl_xor_sync(0xffffffffu, mx, 4));
            mx = fmaxf(mx, __shfl_xor_sync(0xffffffffu, mx, 8));
            newm[i] = fmaxf(mrow[i], mx);
        }
#pragma unroll
        for (int i = 0; i < 8; i++) {
            float rs = 0.f;
#pragma unroll
            for (int j = 0; j < 4; j++) {
                float pv = __expf(s[i][j] - newm[i]);
                Ps[(tr * 8 + i) * PADW + tc * 4 + j] = pv;
                rs += pv;
            }
            rs += __shfl_xor_sync(0xffffffffu, rs, 1);
            rs += __shfl_xor_sync(0xffffffffu, rs, 2);
            rs += __shfl_xor_sync(0xffffffffu, rs, 4);
            rs += __shfl_xor_sync(0xffffffffu, rs, 8);
            rsum[i] = rs;
            al[i] = __expf(mrow[i] - newm[i]);
            lrow[i] = lrow[i] * al[i] + rsum[i];
            mrow[i] = newm[i];
#pragma unroll
            for (int j = 0; j < 4; j++) O[i][j] *= al[i];
        }
        __syncthreads();   // Ps fully written

        // O += P V  (8x4 per thread over d-cols tc*4..+3)
#pragma unroll 4
        for (int c = 0; c < 64; c++) {
            float pa[8], vb[4];
#pragma unroll
            for (int i = 0; i < 8; i++) pa[i] = Ps[(tr * 8 + i) * PADW + c];
#pragma unroll
            for (int j = 0; j < 4; j++) vb[j] = Vs[c * PADW + tc * 4 + j];
#pragma unroll
            for (int i = 0; i < 8; i++)
#pragma unroll
                for (int j = 0; j < 4; j++)
                    O[i][j] += pa[i] * vb[j];
        }
        __syncthreads();   // before K/V/Ps reuse
    }

    float* Ag = &g_Aout[bh][0][0];
#pragma unroll
    for (int i = 0; i < 8; i++) {
        float inv = 1.f / lrow[i];
        *(float4*)(Ag + (size_t)(qstart + tr * 8 + i) * HD + tc * 4) =
            make_float4(O[i][0] * inv, O[i][1] * inv, O[i][2] * inv, O[i][3] * inv);
    }
}

// ---------------------------------------------------------------------------
// launch
// ---------------------------------------------------------------------------
extern "C" void kernel_launch(void* const* d_in, const int* in_sizes, int n_in,
                              void* d_out, int out_size)
{
    const float* x  = (const float*)d_in[0];
    const float* Wq = (const float*)d_in[1];
    const float* Wk = (const float*)d_in[2];
    const float* Wv = (const float*)d_in[3];
    const float* Wo = (const float*)d_in[4];
    const float* aq = (const float*)d_in[5];
    const float* ak = (const float*)d_in[6];
    const float* av = (const float*)d_in[7];
    const float* cl = (const float*)d_in[8];
    float* out = (float*)d_out;

    cudaFuncSetAttribute(attn_k, cudaFuncAttributeMaxDynamicSharedMemorySize,
                         SMEM_ATTN);

    // effective weights (folds head mixing / collapse into GEMM weights)
    build_weff_k<<<dim3((NPROJ * HIDD) / 256, 3), 256>>>(Wq, Wk, Wv, aq, ak, av);
    build_woeff_k<<<(HIDD * NPROJ) / 256, 256>>>(Wo, cl);

    // fused projection + mixing GEMMs -> g_Q/g_K/g_V in [bh][v][d] layout
    sgemm_k<0><<<dim3(NPROJ / 128, MTOK / 128), 256>>>(x, 0, nullptr, HIDD);
    sgemm_k<0><<<dim3(NPROJ / 128, MTOK / 128), 256>>>(x, 1, nullptr, HIDD);
    sgemm_k<0><<<dim3(NPROJ / 128, MTOK / 128), 256>>>(x, 2, nullptr, HIDD);

    // causal SDPA over virtual positions
    attn_k<<<dim3(SVLEN / 128, NB * NH), 256, SMEM_ATTN>>>();

    // collapse + output projection GEMM (A gathered from g_Aout)
    sgemm_k<1><<<dim3(HIDD / 128, MTOK / 128), 256>>>(nullptr, 0, out, NPROJ);
}

// round 3
// speedup vs baseline: 1.5242x; 1.5242x over previous
#include <cuda_runtime.h>
#include <cstdint>

// ---------------------------------------------------------------------------
// InterleavedHeadAttention — round 3: mma.sync tf32 GEMMs + fp32 flash attn
//   (tcgen05 unavailable: harness PTX targets sm_103 baseline, not sm_103a)
//   B=2, S=1024, HID=1024, H=16, P=2, D=64, sv = S*P = 2048
// ---------------------------------------------------------------------------

#define NB 2
#define SEQ 1024
#define HIDD 1024
#define NH 16
#define NP 2
#define HD 64
#define SVLEN (SEQ * NP)        // 2048
#define MTOK (NB * SEQ)         // 2048
#define NPROJ (NH * NP * HD)    // 2048
#define ATTN_SCALE 0.125f

#define NEG_INF __int_as_float(0xff800000)

// scratch (device globals; allocation inside kernel_launch is forbidden)
__device__ float g_Weff[3][NPROJ][HIDD];
__device__ float g_Woeff[HIDD][NPROJ];
__device__ float g_Q[NB * NH][SVLEN][HD];
__device__ float g_K[NB * NH][SVLEN][HD];
__device__ float g_V[NB * NH][SVLEN][HD];
__device__ float g_Aout[NB * NH][SVLEN][HD];

// ---------------------------------------------------------------------------
// helpers
// ---------------------------------------------------------------------------
__device__ __forceinline__ uint32_t smem_u32(const void* p) {
    uint32_t a;
    asm("{ .reg .u64 t; cvta.to.shared.u64 t, %1; cvt.u32.u64 %0, t; }"
        : "=r"(a) : "l"(p));
    return a;
}
__device__ __forceinline__ void cp16(uint32_t s, const void* g) {
    asm volatile("cp.async.cg.shared.global [%0], [%1], 16;" :: "r"(s), "l"(g));
}
#define CP_COMMIT() asm volatile("cp.async.commit_group;" ::: "memory")
#define CP_WAIT(n)  asm volatile("cp.async.wait_group %0;" :: "n"(n) : "memory")

__device__ __forceinline__ uint32_t f2tf32(float f) {
    uint32_t r;
    asm("cvt.rna.tf32.f32 %0, %1;" : "=r"(r) : "f"(f));
    return r;
}
// D = A(16x8) * B(8x8) + D, tf32 inputs, f32 accum
__device__ __forceinline__ void mma_tf32(float* c, const uint32_t* a,
                                         const uint32_t* b) {
    asm volatile(
        "mma.sync.aligned.m16n8k8.row.col.f32.tf32.tf32.f32 "
        "{%0,%1,%2,%3}, {%4,%5,%6,%7}, {%8,%9}, {%0,%1,%2,%3};"
        : "+f"(c[0]), "+f"(c[1]), "+f"(c[2]), "+f"(c[3])
        : "r"(a[0]), "r"(a[1]), "r"(a[2]), "r"(a[3]), "r"(b[0]), "r"(b[1]));
}

// ---------------------------------------------------------------------------
// Build effective projection weights (q/k/v by blockIdx.y)
// ---------------------------------------------------------------------------
__global__ __launch_bounds__(256) void build_weff_k(
    const float* __restrict__ Wq, const float* __restrict__ Wk,
    const float* __restrict__ Wv,
    const float* __restrict__ aq, const float* __restrict__ ak,
    const float* __restrict__ av)
{
    int w = blockIdx.y;
    const float* W = (w == 0) ? Wq : (w == 1) ? Wk : Wv;
    const float* A = (w == 0) ? aq : (w == 1) ? ak : av;
    int idx = blockIdx.x * 256 + threadIdx.x;
    int r = idx >> 10;
    int e = idx & 1023;
    int h = r >> 7, p = (r >> 6) & 1, d = r & 63;
    float acc = 0.f;
#pragma unroll
    for (int m = 0; m < NH; m++)
        acc += A[m * (NH * NP) + h * NP + p] * W[(m * HD + d) * HIDD + e];
    g_Weff[w][r][e] = acc;
}

__global__ __launch_bounds__(256) void build_woeff_k(
    const float* __restrict__ Wo, const float* __restrict__ cl)
{
    int idx = blockIdx.x * 256 + threadIdx.x;
    int f = idx >> 11;
    int c = idx & 2047;
    int o = c >> 6, d = c & 63;
    float acc = 0.f;
#pragma unroll
    for (int h = 0; h < NH; h++)
        acc += cl[h * (NH * NP) + o] * Wo[f * HIDD + h * HD + d];
    g_Woeff[f][c] = acc;
}

// ---------------------------------------------------------------------------
// tf32 mma.sync NT GEMM: C[M,N] = A[M,K] * B[N,K]^T
//   CTA 128x128, 8 warps (4 along M x 2 along N), warp tile 32x64.
//   K chunked 32, 2-stage cp.async double buffer.
//   Smem tiles row-major, ld = 36 floats (144B, 16B aligned, conflict-free).
// MODE 0: A = x, B = g_Weff[blockIdx.z]; epilogue scatters into g_Q/K/V.
// MODE 1: A = gather from g_Aout, B = g_Woeff; epilogue writes Cout.
// ---------------------------------------------------------------------------
#define KC 32
#define LDT 36                               // floats per smem row
#define TILE_F (128 * LDT)                   // floats per tile
#define STG_F (2 * TILE_F)                   // A + B per stage
#define NSTG 2
#define SMEM_MMAGEMM (NSTG * STG_F * 4)

template <int MODE>
__global__ __launch_bounds__(256, 2) void mmagemm_k(
    const float* __restrict__ Ag, float* __restrict__ Cout, int Kdim)
{
    extern __shared__ __align__(16) float smf[];
    const int tid = threadIdx.x, wid = tid >> 5, lane = tid & 31;
    const int wm = (wid & 3) * 32;           // warp row offset in CTA tile
    const int wn = (wid >> 2) * 64;          // warp col offset
    const int bn = blockIdx.x * 128, bm = blockIdx.y * 128;
    const int which = blockIdx.z;
    const float* Bw = (MODE == 0) ? &g_Weff[which][0][0] : &g_Woeff[0][0];

    const uint32_t sb = smem_u32(smf);
    const int lrow = tid >> 1;               // 0..127 load row
    const int lc0 = (tid & 1) * 4;           // first 16B chunk (of 8)

    // token decode for MODE 1 gather (row = lrow)
    int gb = 0, gn = 0;
    if (MODE == 1) { int t = bm + lrow; gb = t >> 10; gn = t & 1023; }

    auto issue = [&](int kc, int s) {
        int k0 = kc * KC;
        uint32_t sa = sb + (uint32_t)(s * STG_F) * 4;
        uint32_t sbB = sa + TILE_F * 4;
        uint32_t soff = (uint32_t)lrow * (LDT * 4) + lc0 * 16;
        if (MODE == 0) {
            const float* asrc = Ag + (size_t)(bm + lrow) * Kdim + k0 + lc0 * 4;
#pragma unroll
            for (int c = 0; c < 4; c++)
                cp16(sa + soff + c * 16, asrc + c * 4);
        } else {
#pragma unroll
            for (int c = 0; c < 4; c++) {
                int col = k0 + (lc0 + c) * 4;
                int o = col >> 6, dd = col & 63;
                cp16(sa + soff + c * 16,
                     &g_Aout[gb * NH + (o >> 1)][gn * NP + (o & 1)][dd]);
            }
        }
        const float* bsrc = Bw + (size_t)(bn + lrow) * Kdim + k0 + lc0 * 4;
#pragma unroll
        for (int c = 0; c < 4; c++)
            cp16(sbB + soff + c * 16, bsrc + c * 4);
    };

    float acc[2][8][4];
#pragma unroll
    for (int mt = 0; mt < 2; mt++)
#pragma unroll
        for (int nt = 0; nt < 8; nt++)
#pragma unroll
            for (int j = 0; j < 4; j++) acc[mt][nt][j] = 0.f;

    const int NKC = Kdim / KC;
    issue(0, 0); CP_COMMIT();
    issue(1, 1); CP_COMMIT();

    const int fr = lane >> 2;                // fragment row group 0..7
    const int fc = lane & 3;                 // fragment k sub-index 0..3

    for (int kc = 0; kc < NKC; kc++) {
        int s = kc & 1;
        CP_WAIT(1);
        __syncthreads();
        const float* As = smf + s * STG_F;
        const float* Bs = As + TILE_F;

#pragma unroll
        for (int k8 = 0; k8 < 4; k8++) {
            int kb = k8 * 8;
            uint32_t afr[2][4], bfr[8][2];
#pragma unroll
            for (int mt = 0; mt < 2; mt++) {
                const float* ap = As + (wm + mt * 16 + fr) * LDT + kb + fc;
                afr[mt][0] = f2tf32(ap[0]);
                afr[mt][1] = f2tf32(ap[8 * LDT]);
                afr[mt][2] = f2tf32(ap[4]);
                afr[mt][3] = f2tf32(ap[8 * LDT + 4]);
            }
#pragma unroll
            for (int nt = 0; nt < 8; nt++) {
                const float* bp = Bs + (wn + nt * 8 + fr) * LDT + kb + fc;
                bfr[nt][0] = f2tf32(bp[0]);
                bfr[nt][1] = f2tf32(bp[4]);
            }
#pragma unroll
            for (int mt = 0; mt < 2; mt++)
#pragma unroll
                for (int nt = 0; nt < 8; nt++)
                    mma_tf32(acc[mt][nt], afr[mt], bfr[nt]);
        }
        __syncthreads();
        int kn = kc + NSTG;
        if (kn < NKC) issue(kn, kn & 1);
        CP_COMMIT();
    }

    // ---- epilogue ----
    // C fragment: c0 (row fr, col 2*fc), c1 (col+1), c2 (row fr+8), c3.
#pragma unroll
    for (int mt = 0; mt < 2; mt++) {
#pragma unroll
        for (int half = 0; half < 2; half++) {
            int row = bm + wm + mt * 16 + fr + half * 8;
#pragma unroll
            for (int nt = 0; nt < 8; nt++) {
                int col = bn + wn + nt * 8 + 2 * fc;
                float v0 = acc[mt][nt][half * 2 + 0];
                float v1 = acc[mt][nt][half * 2 + 1];
                if (MODE == 0) {
                    float* dst0 = (which == 0) ? &g_Q[0][0][0]
                                : (which == 1) ? &g_K[0][0][0] : &g_V[0][0][0];
                    int b = row >> 10, n = row & 1023;
                    int h = col >> 7, p = (col >> 6) & 1, d = col & 63;
                    float* dst = dst0 +
                        ((size_t)(b * NH + h) * SVLEN + n * NP + p) * HD + d;
                    *(float2*)dst = make_float2(v0, v1);
                } else {
                    *(float2*)(Cout + (size_t)row * HIDD + col) =
                        make_float2(v0, v1);
                }
            }
        }
    }
}

// ---------------------------------------------------------------------------
// Causal flash attention, fp32 online softmax (unchanged, known-correct).
// ---------------------------------------------------------------------------
#define PADW 68
#define SMEM_ATTN ((128 + 64 + 64 + 128) * PADW * 4)

__global__ __launch_bounds__(256) void attn_k()
{
    extern __shared__ float sm[];
    float* Qs = sm;
    float* Ks = Qs + 128 * PADW;
    float* Vs = Ks + 64 * PADW;
    float* Ps = Vs + 64 * PADW;

    int bh = blockIdx.y;
    int qt = (gridDim.x - 1) - blockIdx.x;
    int qstart = qt * 128;
    const float* Qg = &g_Q[bh][0][0];
    const float* Kg = &g_K[bh][0][0];
    const float* Vg = &g_V[bh][0][0];

    int tid = threadIdx.x;
    int tr = tid >> 4;
    int tc = tid & 15;

#pragma unroll
    for (int it = 0; it < 8; it++) {
        int chunk = tid + 256 * it;
        int row = chunk >> 4;
        int d0 = (chunk & 15) * 4;
        *(float4*)(Qs + row * PADW + d0) =
            *(const float4*)(Qg + (size_t)(qstart + row) * HD + d0);
    }

    float mrow[8], lrow[8], O[8][4];
#pragma unroll
    for (int i = 0; i < 8; i++) {
        mrow[i] = NEG_INF; lrow[i] = 0.f;
#pragma unroll
        for (int j = 0; j < 4; j++) O[i][j] = 0.f;
    }
    __syncthreads();

    int jmax = 2 * qt + 1;
    for (int jt = 0; jt <= jmax; jt++) {
        int kstart = jt * 64;
#pragma unroll
        for (int it = 0; it < 4; it++) {
            int chunk = tid + 256 * it;
            int row = chunk >> 4;
            int d0 = (chunk & 15) * 4;
            *(float4*)(Ks + row * PADW + d0) =
                *(const float4*)(Kg + (size_t)(kstart + row) * HD + d0);
            *(float4*)(Vs + row * PADW + d0) =
                *(const float4*)(Vg + (size_t)(kstart + row) * HD + d0);
        }
        __syncthreads();

        float s[8][4];
#pragma unroll
        for (int i = 0; i < 8; i++)
#pragma unroll
            for (int j = 0; j < 4; j++) s[i][j] = 0.f;
#pragma unroll 4
        for (int d = 0; d < 64; d++) {
            float ra[8], rb[4];
#pragma unroll
            for (int i = 0; i < 8; i++) ra[i] = Qs[(tr * 8 + i) * PADW + d];
#pragma unroll
            for (int j = 0; j < 4; j++) rb[j] = Ks[(tc * 4 + j) * PADW + d];
#pragma unroll
            for (int i = 0; i < 8; i++)
#pragma unroll
                for (int j = 0; j < 4; j++)
                    s[i][j] += ra[i] * rb[j];
        }
#pragma unroll
        for (int i = 0; i < 8; i++)
#pragma unroll
            for (int j = 0; j < 4; j++) s[i][j] *= ATTN_SCALE;
        if (kstart + 63 > qstart + tr * 8) {
#pragma unroll
            for (int i = 0; i < 8; i++)
#pragma unroll
                for (int j = 0; j < 4; j++)
                    if (kstart + tc * 4 + j > qstart + tr * 8 + i) s[i][j] = NEG_INF;
        }

        float newm[8], al[8], rsum[8];
#pragma unroll
        for (int i = 0; i < 8; i++) {
            float mx = fmaxf(fmaxf(s[i][0], s[i][1]), fmaxf(s[i][2], s[i][3]));
            mx = fmaxf(mx, __shfl_xor_sync(0xffffffffu, mx, 1));
            mx = fmaxf(mx, __shfl_xor_sync(0xffffffffu, mx, 2));
            mx = fmaxf(mx, __shfl_xor_sync(0xffffffffu, mx, 4));
            mx = fmaxf(mx, __shfl_xor_sync(0xffffffffu, mx, 8));
            newm[i] = fmaxf(mrow[i], mx);
        }
#pragma unroll
        for (int i = 0; i < 8; i++) {
            float rs = 0.f;
#pragma unroll
            for (int j = 0; j < 4; j++) {
                float pv = __expf(s[i][j] - newm[i]);
                Ps[(tr * 8 + i) * PADW + tc * 4 + j] = pv;
                rs += pv;
            }
            rs += __shfl_xor_sync(0xffffffffu, rs, 1);
            rs += __shfl_xor_sync(0xffffffffu, rs, 2);
            rs += __shfl_xor_sync(0xffffffffu, rs, 4);
            rs += __shfl_xor_sync(0xffffffffu, rs, 8);
            rsum[i] = rs;
            al[i] = __expf(mrow[i] - newm[i]);
            lrow[i] = lrow[i] * al[i] + rsum[i];
            mrow[i] = newm[i];
#pragma unroll
            for (int j = 0; j < 4; j++) O[i][j] *= al[i];
        }
        __syncthreads();

#pragma unroll 4
        for (int c = 0; c < 64; c++) {
            float pa[8], vb[4];
#pragma unroll
            for (int i = 0; i < 8; i++) pa[i] = Ps[(tr * 8 + i) * PADW + c];
#pragma unroll
            for (int j = 0; j < 4; j++) vb[j] = Vs[c * PADW + tc * 4 + j];
#pragma unroll
            for (int i = 0; i < 8; i++)
#pragma unroll
                for (int j = 0; j < 4; j++)
                    O[i][j] += pa[i] * vb[j];
        }
        __syncthreads();
    }

    float* Ag = &g_Aout[bh][0][0];
#pragma unroll
    for (int i = 0; i < 8; i++) {
        float inv = 1.f / lrow[i];
        *(float4*)(Ag + (size_t)(qstart + tr * 8 + i) * HD + tc * 4) =
            make_float4(O[i][0] * inv, O[i][1] * inv, O[i][2] * inv, O[i][3] * inv);
    }
}

// ---------------------------------------------------------------------------
// launch
// ---------------------------------------------------------------------------
extern "C" void kernel_launch(void* const* d_in, const int* in_sizes, int n_in,
                              void* d_out, int out_size)
{
    const float* x  = (const float*)d_in[0];
    const float* Wq = (const float*)d_in[1];
    const float* Wk = (const float*)d_in[2];
    const float* Wv = (const float*)d_in[3];
    const float* Wo = (const float*)d_in[4];
    const float* aq = (const float*)d_in[5];
    const float* ak = (const float*)d_in[6];
    const float* av = (const float*)d_in[7];
    const float* cl = (const float*)d_in[8];
    float* out = (float*)d_out;

    cudaFuncSetAttribute(mmagemm_k<0>, cudaFuncAttributeMaxDynamicSharedMemorySize, SMEM_MMAGEMM);
    cudaFuncSetAttribute(mmagemm_k<1>, cudaFuncAttributeMaxDynamicSharedMemorySize, SMEM_MMAGEMM);
    cudaFuncSetAttribute(attn_k, cudaFuncAttributeMaxDynamicSharedMemorySize, SMEM_ATTN);

    build_weff_k<<<dim3((NPROJ * HIDD) / 256, 3), 256>>>(Wq, Wk, Wv, aq, ak, av);
    build_woeff_k<<<(HIDD * NPROJ) / 256, 256>>>(Wo, cl);

    // fused projection + mixing GEMMs (q/k/v via blockIdx.z)
    mmagemm_k<0><<<dim3(NPROJ / 128, MTOK / 128, 3), 256, SMEM_MMAGEMM>>>(x, nullptr, HIDD);

    // causal SDPA over virtual positions
    attn_k<<<dim3(SVLEN / 128, NB * NH), 256, SMEM_ATTN>>>();

    // collapse + output projection GEMM
    mmagemm_k<1><<<dim3(HIDD / 128, MTOK / 128, 1), 256, SMEM_MMAGEMM>>>(nullptr, out, NPROJ);
}

// round 4
// speedup vs baseline: 2.8460x; 1.8672x over previous
#include <cuda_runtime.h>
#include <cstdint>

// ---------------------------------------------------------------------------
// InterleavedHeadAttention — round 4: mma.sync tf32 GEMMs + mma.sync tf32
// flash attention. (tcgen05 unavailable: harness targets sm_103 baseline.)
//   B=2, S=1024, HID=1024, H=16, P=2, D=64, sv = S*P = 2048
// ---------------------------------------------------------------------------

#define NB 2
#define SEQ 1024
#define HIDD 1024
#define NH 16
#define NP 2
#define HD 64
#define SVLEN (SEQ * NP)        // 2048
#define MTOK (NB * SEQ)         // 2048
#define NPROJ (NH * NP * HD)    // 2048
#define ATTN_SCALE 0.125f

#define NEG_INF __int_as_float(0xff800000)

// scratch (device globals; allocation inside kernel_launch is forbidden)
__device__ float g_Weff[3][NPROJ][HIDD];
__device__ float g_Woeff[HIDD][NPROJ];
__device__ float g_Q[NB * NH][SVLEN][HD];
__device__ float g_K[NB * NH][SVLEN][HD];
__device__ float g_V[NB * NH][SVLEN][HD];
__device__ float g_Aout[NB * NH][SVLEN][HD];

// ---------------------------------------------------------------------------
// helpers
// ---------------------------------------------------------------------------
__device__ __forceinline__ void cp16(uint32_t s, const void* g) {
    asm volatile("cp.async.cg.shared.global [%0], [%1], 16;" :: "r"(s), "l"(g));
}
__device__ __forceinline__ uint32_t smem_u32(const void* p) {
    uint32_t a;
    asm("{ .reg .u64 t; cvta.to.shared.u64 t, %1; cvt.u32.u64 %0, t; }"
        : "=r"(a) : "l"(p));
    return a;
}
#define CP_COMMIT() asm volatile("cp.async.commit_group;" ::: "memory")
#define CP_WAIT(n)  asm volatile("cp.async.wait_group %0;" :: "n"(n) : "memory")

__device__ __forceinline__ uint32_t f2tf32(float f) {
    uint32_t r;
    asm("cvt.rna.tf32.f32 %0, %1;" : "=r"(r) : "f"(f));
    return r;
}
__device__ __forceinline__ float f2tf32f(float f) {
    return __uint_as_float(f2tf32(f));
}
// D = A(16x8) * B(8x8) + D, tf32 inputs, f32 accum
__device__ __forceinline__ void mma_tf32(float* c, const uint32_t* a,
                                         const uint32_t* b) {
    asm volatile(
        "mma.sync.aligned.m16n8k8.row.col.f32.tf32.tf32.f32 "
        "{%0,%1,%2,%3}, {%4,%5,%6,%7}, {%8,%9}, {%0,%1,%2,%3};"
        : "+f"(c[0]), "+f"(c[1]), "+f"(c[2]), "+f"(c[3])
        : "r"(a[0]), "r"(a[1]), "r"(a[2]), "r"(a[3]), "r"(b[0]), "r"(b[1]));
}

// ---------------------------------------------------------------------------
// Build effective projection weights (q/k/v by blockIdx.y)
// ---------------------------------------------------------------------------
__global__ __launch_bounds__(256) void build_weff_k(
    const float* __restrict__ Wq, const float* __restrict__ Wk,
    const float* __restrict__ Wv,
    const float* __restrict__ aq, const float* __restrict__ ak,
    const float* __restrict__ av)
{
    int w = blockIdx.y;
    const float* W = (w == 0) ? Wq : (w == 1) ? Wk : Wv;
    const float* A = (w == 0) ? aq : (w == 1) ? ak : av;
    int idx = blockIdx.x * 256 + threadIdx.x;
    int r = idx >> 10;
    int e = idx & 1023;
    int h = r >> 7, p = (r >> 6) & 1, d = r & 63;
    float acc = 0.f;
#pragma unroll
    for (int m = 0; m < NH; m++)
        acc += A[m * (NH * NP) + h * NP + p] * W[(m * HD + d) * HIDD + e];
    g_Weff[w][r][e] = acc;
}

__global__ __launch_bounds__(256) void build_woeff_k(
    const float* __restrict__ Wo, const float* __restrict__ cl)
{
    int idx = blockIdx.x * 256 + threadIdx.x;
    int f = idx >> 11;
    int c = idx & 2047;
    int o = c >> 6, d = c & 63;
    float acc = 0.f;
#pragma unroll
    for (int h = 0; h < NH; h++)
        acc += cl[h * (NH * NP) + o] * Wo[f * HIDD + h * HD + d];
    g_Woeff[f][c] = acc;
}

// ---------------------------------------------------------------------------
// tf32 mma.sync NT GEMM (unchanged from round 3, verified)
// ---------------------------------------------------------------------------
#define KC 32
#define LDT 36
#define TILE_F (128 * LDT)
#define STG_F (2 * TILE_F)
#define NSTG 2
#define SMEM_MMAGEMM (NSTG * STG_F * 4)

template <int MODE>
__global__ __launch_bounds__(256, 2) void mmagemm_k(
    const float* __restrict__ Ag, float* __restrict__ Cout, int Kdim)
{
    extern __shared__ __align__(16) float smf[];
    const int tid = threadIdx.x, wid = tid >> 5, lane = tid & 31;
    const int wm = (wid & 3) * 32;
    const int wn = (wid >> 2) * 64;
    const int bn = blockIdx.x * 128, bm = blockIdx.y * 128;
    const int which = blockIdx.z;
    const float* Bw = (MODE == 0) ? &g_Weff[which][0][0] : &g_Woeff[0][0];

    const uint32_t sb = smem_u32(smf);
    const int lrow = tid >> 1;
    const int lc0 = (tid & 1) * 4;

    int gb = 0, gn = 0;
    if (MODE == 1) { int t = bm + lrow; gb = t >> 10; gn = t & 1023; }

    auto issue = [&](int kc, int s) {
        int k0 = kc * KC;
        uint32_t sa = sb + (uint32_t)(s * STG_F) * 4;
        uint32_t sbB = sa + TILE_F * 4;
        uint32_t soff = (uint32_t)lrow * (LDT * 4) + lc0 * 16;
        if (MODE == 0) {
            const float* asrc = Ag + (size_t)(bm + lrow) * Kdim + k0 + lc0 * 4;
#pragma unroll
            for (int c = 0; c < 4; c++)
                cp16(sa + soff + c * 16, asrc + c * 4);
        } else {
#pragma unroll
            for (int c = 0; c < 4; c++) {
                int col = k0 + (lc0 + c) * 4;
                int o = col >> 6, dd = col & 63;
                cp16(sa + soff + c * 16,
                     &g_Aout[gb * NH + (o >> 1)][gn * NP + (o & 1)][dd]);
            }
        }
        const float* bsrc = Bw + (size_t)(bn + lrow) * Kdim + k0 + lc0 * 4;
#pragma unroll
        for (int c = 0; c < 4; c++)
            cp16(sbB + soff + c * 16, bsrc + c * 4);
    };

    float acc[2][8][4];
#pragma unroll
    for (int mt = 0; mt < 2; mt++)
#pragma unroll
        for (int nt = 0; nt < 8; nt++)
#pragma unroll
            for (int j = 0; j < 4; j++) acc[mt][nt][j] = 0.f;

    const int NKC = Kdim / KC;
    issue(0, 0); CP_COMMIT();
    issue(1, 1); CP_COMMIT();

    const int fr = lane >> 2;
    const int fc = lane & 3;

    for (int kc = 0; kc < NKC; kc++) {
        int s = kc & 1;
        CP_WAIT(1);
        __syncthreads();
        const float* As = smf + s * STG_F;
        const float* Bs = As + TILE_F;

#pragma unroll
        for (int k8 = 0; k8 < 4; k8++) {
            int kb = k8 * 8;
            uint32_t afr[2][4], bfr[8][2];
#pragma unroll
            for (int mt = 0; mt < 2; mt++) {
                const float* ap = As + (wm + mt * 16 + fr) * LDT + kb + fc;
                afr[mt][0] = f2tf32(ap[0]);
                afr[mt][1] = f2tf32(ap[8 * LDT]);
                afr[mt][2] = f2tf32(ap[4]);
                afr[mt][3] = f2tf32(ap[8 * LDT + 4]);
            }
#pragma unroll
            for (int nt = 0; nt < 8; nt++) {
                const float* bp = Bs + (wn + nt * 8 + fr) * LDT + kb + fc;
                bfr[nt][0] = f2tf32(bp[0]);
                bfr[nt][1] = f2tf32(bp[4]);
            }
#pragma unroll
            for (int mt = 0; mt < 2; mt++)
#pragma unroll
                for (int nt = 0; nt < 8; nt++)
                    mma_tf32(acc[mt][nt], afr[mt], bfr[nt]);
        }
        __syncthreads();
        int kn = kc + NSTG;
        if (kn < NKC) issue(kn, kn & 1);
        CP_COMMIT();
    }

#pragma unroll
    for (int mt = 0; mt < 2; mt++) {
#pragma unroll
        for (int half = 0; half < 2; half++) {
            int row = bm + wm + mt * 16 + fr + half * 8;
#pragma unroll
            for (int nt = 0; nt < 8; nt++) {
                int col = bn + wn + nt * 8 + 2 * fc;
                float v0 = acc[mt][nt][half * 2 + 0];
                float v1 = acc[mt][nt][half * 2 + 1];
                if (MODE == 0) {
                    float* dst0 = (which == 0) ? &g_Q[0][0][0]
                                : (which == 1) ? &g_K[0][0][0] : &g_V[0][0][0];
                    int b = row >> 10, n = row & 1023;
                    int h = col >> 7, p = (col >> 6) & 1, d = col & 63;
                    float* dst = dst0 +
                        ((size_t)(b * NH + h) * SVLEN + n * NP + p) * HD + d;
                    *(float2*)dst = make_float2(v0, v1);
                } else {
                    *(float2*)(Cout + (size_t)row * HIDD + col) =
                        make_float2(v0, v1);
                }
            }
        }
    }
}

// ---------------------------------------------------------------------------
// Causal flash attention with mma.sync tf32 for QK^T and PV.
//   256 threads / 8 warps, q-tile 128 (16 rows per warp), k-tile 64.
//   Smem: Qs/Ks/Ps stride 68 (conflict-free frag loads), Vs kv-major
//   stride 72 (conflict-free B-frag loads). All operands tf32-rounded at
//   smem-store time; accumulators fp32.
// ---------------------------------------------------------------------------
#define ALD 68
#define VLD 72
#define SMEM_ATTN ((128 * ALD + 64 * ALD + 64 * VLD + 128 * ALD) * 4)

__global__ __launch_bounds__(256, 2) void attn_k()
{
    extern __shared__ float sm[];
    float* Qs = sm;                       // [128][ALD]
    float* Ks = Qs + 128 * ALD;           // [64][ALD]
    float* Vs = Ks + 64 * ALD;            // [64][VLD]  (kv-major)
    float* Ps = Vs + 64 * VLD;            // [128][ALD]

    const int bh = blockIdx.y;
    const int qt = (gridDim.x - 1) - blockIdx.x;    // heavy tiles first
    const int qstart = qt * 128;
    const float* Qg = &g_Q[bh][0][0];
    const float* Kg = &g_K[bh][0][0];
    const float* Vg = &g_V[bh][0][0];

    const int tid = threadIdx.x;
    const int wq = tid >> 5;              // warp -> rows [wq*16, wq*16+16)
    const int lane = tid & 31;
    const int fr = lane >> 2;             // 0..7
    const int fc = lane & 3;              // 0..3
    const int r0 = wq * 16 + fr;          // local row (c0,c1)
    const int r1 = r0 + 8;                // local row (c2,c3)

    // load Q tile (128 x 64), tf32-round at store
#pragma unroll
    for (int it = 0; it < 8; it++) {
        int chunk = tid + 256 * it;
        int row = chunk >> 4;
        int d0 = (chunk & 15) * 4;
        float4 v = *(const float4*)(Qg + (size_t)(qstart + row) * HD + d0);
        float* dst = Qs + row * ALD + d0;
        dst[0] = f2tf32f(v.x); dst[1] = f2tf32f(v.y);
        dst[2] = f2tf32f(v.z); dst[3] = f2tf32f(v.w);
    }

    float O[8][4];
    float m0 = NEG_INF, m1 = NEG_INF, l0 = 0.f, l1 = 0.f;
#pragma unroll
    for (int nt = 0; nt < 8; nt++)
#pragma unroll
        for (int j = 0; j < 4; j++) O[nt][j] = 0.f;
    __syncthreads();

    const int jmax = 2 * qt + 1;
    for (int jt = 0; jt <= jmax; jt++) {
        const int kstart = jt * 64;
        // load K (row-major) and V (kv-major) tiles, tf32-rounded
#pragma unroll
        for (int it = 0; it < 4; it++) {
            int chunk = tid + 256 * it;
            int row = chunk >> 4;
            int d0 = (chunk & 15) * 4;
            float4 kv4 = *(const float4*)(Kg + (size_t)(kstart + row) * HD + d0);
            float* kd = Ks + row * ALD + d0;
            kd[0] = f2tf32f(kv4.x); kd[1] = f2tf32f(kv4.y);
            kd[2] = f2tf32f(kv4.z); kd[3] = f2tf32f(kv4.w);
            float4 vv4 = *(const float4*)(Vg + (size_t)(kstart + row) * HD + d0);
            float* vd = Vs + row * VLD + d0;
            vd[0] = f2tf32f(vv4.x); vd[1] = f2tf32f(vv4.y);
            vd[2] = f2tf32f(vv4.z); vd[3] = f2tf32f(vv4.w);
        }
        __syncthreads();

        // ---- S = Q K^T via MMA: warp computes 16x64 ----
        float s[8][4];
#pragma unroll
        for (int nt = 0; nt < 8; nt++)
#pragma unroll
            for (int j = 0; j < 4; j++) s[nt][j] = 0.f;
#pragma unroll
        for (int k8 = 0; k8 < 8; k8++) {
            int kb = k8 * 8;
            uint32_t afr[4], bfr[8][2];
            const float* ap = Qs + r0 * ALD + kb + fc;
            afr[0] = __float_as_uint(ap[0]);
            afr[1] = __float_as_uint(ap[8 * ALD]);
            afr[2] = __float_as_uint(ap[4]);
            afr[3] = __float_as_uint(ap[8 * ALD + 4]);
#pragma unroll
            for (int nt = 0; nt < 8; nt++) {
                const float* bp = Ks + (nt * 8 + fr) * ALD + kb + fc;
                bfr[nt][0] = __float_as_uint(bp[0]);
                bfr[nt][1] = __float_as_uint(bp[4]);
            }
#pragma unroll
            for (int nt = 0; nt < 8; nt++)
                mma_tf32(s[nt], afr, bfr[nt]);
        }
#pragma unroll
        for (int nt = 0; nt < 8; nt++)
#pragma unroll
            for (int j = 0; j < 4; j++) s[nt][j] *= ATTN_SCALE;

        // causal mask
        if (kstart + 63 > qstart + wq * 16) {
            int gr0 = qstart + r0, gr1 = qstart + r1;
#pragma unroll
            for (int nt = 0; nt < 8; nt++) {
                int c0 = kstart + nt * 8 + 2 * fc;
                if (c0 > gr0)     s[nt][0] = NEG_INF;
                if (c0 + 1 > gr0) s[nt][1] = NEG_INF;
                if (c0 > gr1)     s[nt][2] = NEG_INF;
                if (c0 + 1 > gr1) s[nt][3] = NEG_INF;
            }
        }

        // ---- online softmax on fragments (rows fr / fr+8) ----
        float mx0 = NEG_INF, mx1 = NEG_INF;
#pragma unroll
        for (int nt = 0; nt < 8; nt++) {
            mx0 = fmaxf(mx0, fmaxf(s[nt][0], s[nt][1]));
            mx1 = fmaxf(mx1, fmaxf(s[nt][2], s[nt][3]));
        }
        mx0 = fmaxf(mx0, __shfl_xor_sync(0xffffffffu, mx0, 1));
        mx0 = fmaxf(mx0, __shfl_xor_sync(0xffffffffu, mx0, 2));
        mx1 = fmaxf(mx1, __shfl_xor_sync(0xffffffffu, mx1, 1));
        mx1 = fmaxf(mx1, __shfl_xor_sync(0xffffffffu, mx1, 2));
        float newm0 = fmaxf(m0, mx0), newm1 = fmaxf(m1, mx1);
        float al0 = __expf(m0 - newm0), al1 = __expf(m1 - newm1);

        float rs0 = 0.f, rs1 = 0.f;
#pragma unroll
        for (int nt = 0; nt < 8; nt++) {
            float p0 = __expf(s[nt][0] - newm0);
            float p1 = __expf(s[nt][1] - newm0);
            float p2 = __expf(s[nt][2] - newm1);
            float p3 = __expf(s[nt][3] - newm1);
            rs0 += p0 + p1; rs1 += p2 + p3;
            int col = nt * 8 + 2 * fc;
            *(float2*)(Ps + r0 * ALD + col) = make_float2(f2tf32f(p0), f2tf32f(p1));
            *(float2*)(Ps + r1 * ALD + col) = make_float2(f2tf32f(p2), f2tf32f(p3));
        }
        rs0 += __shfl_xor_sync(0xffffffffu, rs0, 1);
        rs0 += __shfl_xor_sync(0xffffffffu, rs0, 2);
        rs1 += __shfl_xor_sync(0xffffffffu, rs1, 1);
        rs1 += __shfl_xor_sync(0xffffffffu, rs1, 2);
        l0 = l0 * al0 + rs0; l1 = l1 * al1 + rs1;
        m0 = newm0; m1 = newm1;
#pragma unroll
        for (int nt = 0; nt < 8; nt++) {
            O[nt][0] *= al0; O[nt][1] *= al0;
            O[nt][2] *= al1; O[nt][3] *= al1;
        }
        __syncwarp();   // Ps rows for this warp written by this warp only

        // ---- O += P V via MMA (A from Ps, B from Vs kv-major) ----
#pragma unroll
        for (int k8 = 0; k8 < 8; k8++) {
            int kb = k8 * 8;
            uint32_t afr[4], bfr[8][2];
            const float* ap = Ps + r0 * ALD + kb + fc;
            afr[0] = __float_as_uint(ap[0]);
            afr[1] = __float_as_uint(ap[8 * ALD]);
            afr[2] = __float_as_uint(ap[4]);
            afr[3] = __float_as_uint(ap[8 * ALD + 4]);
#pragma unroll
            for (int nt = 0; nt < 8; nt++) {
                const float* bp = Vs + (kb + fc) * VLD + nt * 8 + fr;
                bfr[nt][0] = __float_as_uint(bp[0]);
                bfr[nt][1] = __float_as_uint(bp[4 * VLD]);
            }
#pragma unroll
            for (int nt = 0; nt < 8; nt++)
                mma_tf32(O[nt], afr, bfr[nt]);
        }
        __syncthreads();   // before K/V overwrite next iteration
    }

    // epilogue: normalize and store
    float inv0 = 1.f / l0, inv1 = 1.f / l1;
    float* Ag = &g_Aout[bh][0][0];
#pragma unroll
    for (int nt = 0; nt < 8; nt++) {
        int col = nt * 8 + 2 * fc;
        *(float2*)(Ag + (size_t)(qstart + r0) * HD + col) =
            make_float2(O[nt][0] * inv0, O[nt][1] * inv0);
        *(float2*)(Ag + (size_t)(qstart + r1) * HD + col) =
            make_float2(O[nt][2] * inv1, O[nt][3] * inv1);
    }
}

// ---------------------------------------------------------------------------
// launch
// ---------------------------------------------------------------------------
extern "C" void kernel_launch(void* const* d_in, const int* in_sizes, int n_in,
                              void* d_out, int out_size)
{
    const float* x  = (const float*)d_in[0];
    const float* Wq = (const float*)d_in[1];
    const float* Wk = (const float*)d_in[2];
    const float* Wv = (const float*)d_in[3];
    const float* Wo = (const float*)d_in[4];
    const float* aq = (const float*)d_in[5];
    const float* ak = (const float*)d_in[6];
    const float* av = (const float*)d_in[7];
    const float* cl = (const float*)d_in[8];
    float* out = (float*)d_out;

    cudaFuncSetAttribute(mmagemm_k<0>, cudaFuncAttributeMaxDynamicSharedMemorySize, SMEM_MMAGEMM);
    cudaFuncSetAttribute(mmagemm_k<1>, cudaFuncAttributeMaxDynamicSharedMemorySize, SMEM_MMAGEMM);
    cudaFuncSetAttribute(attn_k, cudaFuncAttributeMaxDynamicSharedMemorySize, SMEM_ATTN);

    build_weff_k<<<dim3((NPROJ * HIDD) / 256, 3), 256>>>(Wq, Wk, Wv, aq, ak, av);
    build_woeff_k<<<(HIDD * NPROJ) / 256, 256>>>(Wo, cl);

    // fused projection + mixing GEMMs (q/k/v via blockIdx.z)
    mmagemm_k<0><<<dim3(NPROJ / 128, MTOK / 128, 3), 256, SMEM_MMAGEMM>>>(x, nullptr, HIDD);

    // causal SDPA over virtual positions (tensorized)
    attn_k<<<dim3(SVLEN / 128, NB * NH), 256, SMEM_ATTN>>>();

    // collapse + output projection GEMM
    mmagemm_k<1><<<dim3(HIDD / 128, MTOK / 128, 1), 256, SMEM_MMAGEMM>>>(nullptr, out, NPROJ);
}

// round 5
// speedup vs baseline: 2.9335x; 1.0307x over previous
#include <cuda_runtime.h>
#include <cstdint>

// ---------------------------------------------------------------------------
// InterleavedHeadAttention — round 5
//   - all mma.sync tf32 operands pre-rounded at producer-write time (no cvt
//     in any mainloop), ATTN_SCALE folded into Weff_q
//   - projection GEMM: CTA 128x256, warp 64x64, 3-stage cp.async
//   - attention: q-tile 256, warp 32 rows, cp.async loads
//   - weight builds restructured to read W once
//   B=2, S=1024, HID=1024, H=16, P=2, D=64, sv=2048
// ---------------------------------------------------------------------------

#define NB 2
#define SEQ 1024
#define HIDD 1024
#define NH 16
#define NP 2
#define HD 64
#define SVLEN (SEQ * NP)        // 2048
#define MTOK (NB * SEQ)         // 2048
#define NPROJ (NH * NP * HD)    // 2048
#define ATTN_SCALE 0.125f

#define NEG_INF __int_as_float(0xff800000)

__device__ float g_Weff[3][NPROJ][HIDD];
__device__ float g_Woeff[HIDD][NPROJ];
__device__ float g_Xr[MTOK][HIDD];
__device__ float g_Q[NB * NH][SVLEN][HD];
__device__ float g_K[NB * NH][SVLEN][HD];
__device__ float g_V[NB * NH][SVLEN][HD];
__device__ float g_Aout[NB * NH][SVLEN][HD];

// ---------------------------------------------------------------------------
// helpers
// ---------------------------------------------------------------------------
__device__ __forceinline__ void cp16(uint32_t s, const void* g) {
    asm volatile("cp.async.cg.shared.global [%0], [%1], 16;" :: "r"(s), "l"(g));
}
__device__ __forceinline__ uint32_t smem_u32(const void* p) {
    uint32_t a;
    asm("{ .reg .u64 t; cvta.to.shared.u64 t, %1; cvt.u32.u64 %0, t; }"
        : "=r"(a) : "l"(p));
    return a;
}
#define CP_COMMIT() asm volatile("cp.async.commit_group;" ::: "memory")
#define CP_WAIT(n)  asm volatile("cp.async.wait_group %0;" :: "n"(n) : "memory")

__device__ __forceinline__ uint32_t f2tf32(float f) {
    uint32_t r;
    asm("cvt.rna.tf32.f32 %0, %1;" : "=r"(r) : "f"(f));
    return r;
}
__device__ __forceinline__ float f2tf32f(float f) {
    return __uint_as_float(f2tf32(f));
}
__device__ __forceinline__ void mma_tf32(float* c, const uint32_t* a,
                                         const uint32_t* b) {
    asm volatile(
        "mma.sync.aligned.m16n8k8.row.col.f32.tf32.tf32.f32 "
        "{%0,%1,%2,%3}, {%4,%5,%6,%7}, {%8,%9}, {%0,%1,%2,%3};"
        : "+f"(c[0]), "+f"(c[1]), "+f"(c[2]), "+f"(c[3])
        : "r"(a[0]), "r"(a[1]), "r"(a[2]), "r"(a[3]), "r"(b[0]), "r"(b[1]));
}

// ---------------------------------------------------------------------------
// x staging: tf32-round once
// ---------------------------------------------------------------------------
__global__ __launch_bounds__(256) void round_x_k(const float* __restrict__ x)
{
    int idx = blockIdx.x * 256 + threadIdx.x;
    (&g_Xr[0][0])[idx] = f2tf32f(x[idx]);
}

// ---------------------------------------------------------------------------
// Effective projection weights, W read once. Thread owns one (d,e) pair:
//   Weff[(h,p)*64+d][e] = sum_m alpha[m][(h,p)] * W[m*64+d][e]
// w==0 additionally folds ATTN_SCALE. Output tf32-rounded.
// ---------------------------------------------------------------------------
__global__ __launch_bounds__(256) void build_weff_k(
    const float* __restrict__ Wq, const float* __restrict__ Wk,
    const float* __restrict__ Wv,
    const float* __restrict__ aq, const float* __restrict__ ak,
    const float* __restrict__ av)
{
    int w = blockIdx.y;
    const float* W = (w == 0) ? Wq : (w == 1) ? Wk : Wv;
    const float* A = (w == 0) ? aq : (w == 1) ? ak : av;
    __shared__ float sA[NH * 32];           // [m][(h,p)]
    int tid = threadIdx.x;
    sA[tid] = A[tid];
    sA[tid + 256] = A[tid + 256];
    __syncthreads();

    int idx = blockIdx.x * 256 + tid;       // over 64*1024
    int d = idx >> 10, e = idx & 1023;
    float wv[NH];
#pragma unroll
    for (int m = 0; m < NH; m++)
        wv[m] = W[(m * HD + d) * HIDD + e];
    float scale = (w == 0) ? ATTN_SCALE : 1.0f;
#pragma unroll
    for (int hp = 0; hp < 32; hp++) {
        float acc = 0.f;
#pragma unroll
        for (int m = 0; m < NH; m++)
            acc += sA[m * 32 + hp] * wv[m];
        g_Weff[w][hp * HD + d][e] = f2tf32f(acc * scale);
    }
}

// ---------------------------------------------------------------------------
// Effective output weights, Wo read once. Thread owns (f,d):
//   Woeff[f][o*64+d] = sum_h cl[h][o] * Wo[f][h*64+d]
// ---------------------------------------------------------------------------
__global__ __launch_bounds__(256) void build_woeff_k(
    const float* __restrict__ Wo, const float* __restrict__ cl)
{
    __shared__ float sC[NH * 32];           // [h][o]
    int tid = threadIdx.x;
    sC[tid] = cl[tid];
    sC[tid + 256] = cl[tid + 256];
    __syncthreads();

    int idx = blockIdx.x * 256 + tid;       // over 1024*64
    int f = idx >> 6, d = idx & 63;
    float wv[NH];
#pragma unroll
    for (int h = 0; h < NH; h++)
        wv[h] = Wo[f * HIDD + h * HD + d];
#pragma unroll
    for (int o = 0; o < 32; o++) {
        float acc = 0.f;
#pragma unroll
        for (int h = 0; h < NH; h++)
            acc += sC[h * 32 + o] * wv[h];
        g_Woeff[f][o * HD + d] = f2tf32f(acc);
    }
}

// ---------------------------------------------------------------------------
// Projection GEMM: C[M=2048, N=2048] = Xr * Weff[z]^T, K=1024.
//   CTA 128x256, 8 warps (2 M x 4 N), warp 64x64, 3-stage cp.async.
//   Operands pre-rounded; epilogue scatters tf32-rounded into g_Q/K/V.
// ---------------------------------------------------------------------------
#define LDT 36
#define GA_AF (128 * LDT)
#define GA_BF (256 * LDT)
#define GA_STGF (GA_AF + GA_BF)
#define NSTGA 3
#define SMEM_GA (NSTGA * GA_STGF * 4)

__global__ __launch_bounds__(256, 1) void gemmA_k()
{
    extern __shared__ __align__(16) float smf[];
    const int tid = threadIdx.x, wid = tid >> 5, lane = tid & 31;
    const int wm = (wid & 1) * 64;
    const int wn = (wid >> 1) * 64;
    const int bn = blockIdx.x * 256, bm = blockIdx.y * 128;
    const int which = blockIdx.z;
    const float* Aw = &g_Xr[0][0];
    const float* Bw = &g_Weff[which][0][0];
    const uint32_t sb = smem_u32(smf);
    const int fr = lane >> 2, fc = lane & 3;

    const int lrow = tid >> 1, lhalf = tid & 1;

    auto issue = [&](int kc, int s) {
        int k0 = kc * 32;
        uint32_t sa = sb + (uint32_t)(s * GA_STGF) * 4;
        uint32_t sbB = sa + GA_AF * 4;
        const float* asrc = Aw + (size_t)(bm + lrow) * HIDD + k0 + lhalf * 16;
        uint32_t aoff = sa + (uint32_t)lrow * (LDT * 4) + lhalf * 64;
#pragma unroll
        for (int c = 0; c < 4; c++)
            cp16(aoff + c * 16, asrc + c * 4);
        const float* bsrc = Bw + (size_t)(bn + tid) * HIDD + k0;
        uint32_t boff = sbB + (uint32_t)tid * (LDT * 4);
#pragma unroll
        for (int c = 0; c < 8; c++)
            cp16(boff + c * 16, bsrc + c * 4);
    };

    float acc[4][8][4];
#pragma unroll
    for (int mt = 0; mt < 4; mt++)
#pragma unroll
        for (int nt = 0; nt < 8; nt++)
#pragma unroll
            for (int j = 0; j < 4; j++) acc[mt][nt][j] = 0.f;

    issue(0, 0); CP_COMMIT();
    issue(1, 1); CP_COMMIT();
    issue(2, 2); CP_COMMIT();

    const int NKC = HIDD / 32;
    for (int kc = 0; kc < NKC; kc++) {
        int s = kc % NSTGA;
        CP_WAIT(2);
        __syncthreads();
        const float* As = smf + s * GA_STGF;
        const float* Bs = As + GA_AF;
#pragma unroll
        for (int k8 = 0; k8 < 4; k8++) {
            int kb = k8 * 8;
            uint32_t afr[4][4], bfr[8][2];
#pragma unroll
            for (int mt = 0; mt < 4; mt++) {
                const float* ap = As + (wm + mt * 16 + fr) * LDT + kb + fc;
                afr[mt][0] = __float_as_uint(ap[0]);
                afr[mt][1] = __float_as_uint(ap[8 * LDT]);
                afr[mt][2] = __float_as_uint(ap[4]);
                afr[mt][3] = __float_as_uint(ap[8 * LDT + 4]);
            }
#pragma unroll
            for (int nt = 0; nt < 8; nt++) {
                const float* bp = Bs + (wn + nt * 8 + fr) * LDT + kb + fc;
                bfr[nt][0] = __float_as_uint(bp[0]);
                bfr[nt][1] = __float_as_uint(bp[4]);
            }
#pragma unroll
            for (int mt = 0; mt < 4; mt++)
#pragma unroll
                for (int nt = 0; nt < 8; nt++)
                    mma_tf32(acc[mt][nt], afr[mt], bfr[nt]);
        }
        __syncthreads();
        int kn = kc + NSTGA;
        if (kn < NKC) issue(kn, kn % NSTGA);
        CP_COMMIT();
    }

    float* dst0 = (which == 0) ? &g_Q[0][0][0]
                : (which == 1) ? &g_K[0][0][0] : &g_V[0][0][0];
#pragma unroll
    for (int mt = 0; mt < 4; mt++) {
#pragma unroll
        for (int half = 0; half < 2; half++) {
            int row = bm + wm + mt * 16 + fr + half * 8;
            int b = row >> 10, n = row & 1023;
#pragma unroll
            for (int nt = 0; nt < 8; nt++) {
                int col = bn + wn + nt * 8 + 2 * fc;
                int h = col >> 7, p = (col >> 6) & 1, d = col & 63;
                float* dst = dst0 +
                    ((size_t)(b * NH + h) * SVLEN + n * NP + p) * HD + d;
                *(float2*)dst = make_float2(
                    f2tf32f(acc[mt][nt][half * 2 + 0]),
                    f2tf32f(acc[mt][nt][half * 2 + 1]));
            }
        }
    }
}

// ---------------------------------------------------------------------------
// Output GEMM: out[2048,1024] = gather(g_Aout) * Woeff^T, K=2048.
//   CTA 128x128, 8 warps (4 M x 2 N), 2-stage (verified round-3 structure,
//   cvt removed — operands pre-rounded).
// ---------------------------------------------------------------------------
#define GO_TF (128 * LDT)
#define GO_STGF (2 * GO_TF)
#define SMEM_GO (2 * GO_STGF * 4)

__global__ __launch_bounds__(256, 2) void gemmO_k(float* __restrict__ Cout)
{
    extern __shared__ __align__(16) float smf[];
    const int tid = threadIdx.x, wid = tid >> 5, lane = tid & 31;
    const int wm = (wid & 3) * 32;
    const int wn = (wid >> 2) * 64;
    const int bn = blockIdx.x * 128, bm = blockIdx.y * 128;
    const float* Bw = &g_Woeff[0][0];
    const uint32_t sb = smem_u32(smf);
    const int lrow = tid >> 1;
    const int lc0 = (tid & 1) * 4;
    const int fr = lane >> 2, fc = lane & 3;

    int t = bm + lrow;
    int gb = t >> 10, gn = t & 1023;

    auto issue = [&](int kc, int s) {
        int k0 = kc * 32;
        uint32_t sa = sb + (uint32_t)(s * GO_STGF) * 4;
        uint32_t sbB = sa + GO_TF * 4;
        uint32_t soff = (uint32_t)lrow * (LDT * 4) + lc0 * 16;
#pragma unroll
        for (int c = 0; c < 4; c++) {
            int col = k0 + (lc0 + c) * 4;
            int o = col >> 6, dd = col & 63;
            cp16(sa + soff + c * 16,
                 &g_Aout[gb * NH + (o >> 1)][gn * NP + (o & 1)][dd]);
        }
        const float* bsrc = Bw + (size_t)(bn + lrow) * NPROJ + k0 + lc0 * 4;
#pragma unroll
        for (int c = 0; c < 4; c++)
            cp16(sbB + soff + c * 16, bsrc + c * 4);
    };

    float acc[2][8][4];
#pragma unroll
    for (int mt = 0; mt < 2; mt++)
#pragma unroll
        for (int nt = 0; nt < 8; nt++)
#pragma unroll
            for (int j = 0; j < 4; j++) acc[mt][nt][j] = 0.f;

    issue(0, 0); CP_COMMIT();
    issue(1, 1); CP_COMMIT();

    const int NKC = NPROJ / 32;
    for (int kc = 0; kc < NKC; kc++) {
        int s = kc & 1;
        CP_WAIT(1);
        __syncthreads();
        const float* As = smf + s * GO_STGF;
        const float* Bs = As + GO_TF;
#pragma unroll
        for (int k8 = 0; k8 < 4; k8++) {
            int kb = k8 * 8;
            uint32_t afr[2][4], bfr[8][2];
#pragma unroll
            for (int mt = 0; mt < 2; mt++) {
                const float* ap = As + (wm + mt * 16 + fr) * LDT + kb + fc;
                afr[mt][0] = __float_as_uint(ap[0]);
                afr[mt][1] = __float_as_uint(ap[8 * LDT]);
                afr[mt][2] = __float_as_uint(ap[4]);
                afr[mt][3] = __float_as_uint(ap[8 * LDT + 4]);
            }
#pragma unroll
            for (int nt = 0; nt < 8; nt++) {
                const float* bp = Bs + (wn + nt * 8 + fr) * LDT + kb + fc;
                bfr[nt][0] = __float_as_uint(bp[0]);
                bfr[nt][1] = __float_as_uint(bp[4]);
            }
#pragma unroll
            for (int mt = 0; mt < 2; mt++)
#pragma unroll
                for (int nt = 0; nt < 8; nt++)
                    mma_tf32(acc[mt][nt], afr[mt], bfr[nt]);
        }
        __syncthreads();
        int kn = kc + 2;
        if (kn < NKC) issue(kn, kn & 1);
        CP_COMMIT();
    }

#pragma unroll
    for (int mt = 0; mt < 2; mt++) {
#pragma unroll
        for (int half = 0; half < 2; half++) {
            int row = bm + wm + mt * 16 + fr + half * 8;
#pragma unroll
            for (int nt = 0; nt < 8; nt++) {
                int col = bn + wn + nt * 8 + 2 * fc;
                *(float2*)(Cout + (size_t)row * HIDD + col) = make_float2(
                    acc[mt][nt][half * 2 + 0], acc[mt][nt][half * 2 + 1]);
            }
        }
    }
}

// ---------------------------------------------------------------------------
// Causal flash attention: q-tile 256, 8 warps x 32 rows, k-tile 64.
//   mma.sync tf32 for QK^T and PV, cp.async loads (operands pre-rounded,
//   scale folded into Weff_q).
// ---------------------------------------------------------------------------
#define ALD 68
#define VLD 72
#define QTILE 256
#define SMEM_ATTN ((QTILE * ALD * 2 + 64 * ALD + 64 * VLD) * 4)

__global__ __launch_bounds__(256, 1) void attn_k()
{
    extern __shared__ __align__(16) float sm[];
    float* Qs = sm;                         // [256][ALD]
    float* Ks = Qs + QTILE * ALD;           // [64][ALD]
    float* Vs = Ks + 64 * ALD;              // [64][VLD] (kv-major)
    float* Ps = Vs + 64 * VLD;              // [256][ALD]
    const uint32_t sQ = smem_u32(Qs), sK = smem_u32(Ks), sV = smem_u32(Vs);

    const int bh = blockIdx.y;
    const int qt = (gridDim.x - 1) - blockIdx.x;    // heavy tiles first
    const int qstart = qt * QTILE;
    const float* Qg = &g_Q[bh][0][0];
    const float* Kg = &g_K[bh][0][0];
    const float* Vg = &g_V[bh][0][0];

    const int tid = threadIdx.x;
    const int wq = tid >> 5;
    const int lane = tid & 31;
    const int fr = lane >> 2;
    const int fc = lane & 3;

    // Q tile loads (pre-rounded -> raw cp.async)
#pragma unroll
    for (int it = 0; it < 16; it++) {
        int chunk = tid + 256 * it;
        int row = chunk >> 4;
        int c4 = chunk & 15;
        cp16(sQ + (uint32_t)row * (ALD * 4) + c4 * 16,
             Qg + (size_t)(qstart + row) * HD + c4 * 4);
    }
    CP_COMMIT();

    float O[2][8][4];
    float mr[2][2], lr[2][2];
#pragma unroll
    for (int mt = 0; mt < 2; mt++) {
        mr[mt][0] = NEG_INF; mr[mt][1] = NEG_INF;
        lr[mt][0] = 0.f; lr[mt][1] = 0.f;
#pragma unroll
        for (int nt = 0; nt < 8; nt++)
#pragma unroll
            for (int j = 0; j < 4; j++) O[mt][nt][j] = 0.f;
    }

    const int jmax = 4 * qt + 3;
    for (int jt = 0; jt <= jmax; jt++) {
        const int kstart = jt * 64;
#pragma unroll
        for (int it = 0; it < 4; it++) {
            int chunk = tid + 256 * it;
            int row = chunk >> 4;
            int c4 = chunk & 15;
            cp16(sK + (uint32_t)row * (ALD * 4) + c4 * 16,
                 Kg + (size_t)(kstart + row) * HD + c4 * 4);
            cp16(sV + (uint32_t)row * (VLD * 4) + c4 * 16,
                 Vg + (size_t)(kstart + row) * HD + c4 * 4);
        }
        CP_COMMIT();
        CP_WAIT(0);
        __syncthreads();

        // ---- S = Q K^T ----
        float s[2][8][4];
#pragma unroll
        for (int mt = 0; mt < 2; mt++)
#pragma unroll
            for (int nt = 0; nt < 8; nt++)
#pragma unroll
                for (int j = 0; j < 4; j++) s[mt][nt][j] = 0.f;
#pragma unroll
        for (int k8 = 0; k8 < 8; k8++) {
            int kb = k8 * 8;
            uint32_t afr[2][4], bfr[8][2];
#pragma unroll
            for (int mt = 0; mt < 2; mt++) {
                const float* ap = Qs + (wq * 32 + mt * 16 + fr) * ALD + kb + fc;
                afr[mt][0] = __float_as_uint(ap[0]);
                afr[mt][1] = __float_as_uint(ap[8 * ALD]);
                afr[mt][2] = __float_as_uint(ap[4]);
                afr[mt][3] = __float_as_uint(ap[8 * ALD + 4]);
            }
#pragma unroll
            for (int nt = 0; nt < 8; nt++) {
                const float* bp = Ks + (nt * 8 + fr) * ALD + kb + fc;
                bfr[nt][0] = __float_as_uint(bp[0]);
                bfr[nt][1] = __float_as_uint(bp[4]);
            }
#pragma unroll
            for (int mt = 0; mt < 2; mt++)
#pragma unroll
                for (int nt = 0; nt < 8; nt++)
                    mma_tf32(s[mt][nt], afr[mt], bfr[nt]);
        }

        // causal mask
#pragma unroll
        for (int mt = 0; mt < 2; mt++) {
            int base = qstart + wq * 32 + mt * 16;
            if (kstart + 63 > base) {
                int gr0 = base + fr, gr1 = gr0 + 8;
#pragma unroll
                for (int nt = 0; nt < 8; nt++) {
                    int c0 = kstart + nt * 8 + 2 * fc;
                    if (c0 > gr0)     s[mt][nt][0] = NEG_INF;
                    if (c0 + 1 > gr0) s[mt][nt][1] = NEG_INF;
                    if (c0 > gr1)     s[mt][nt][2] = NEG_INF;
                    if (c0 + 1 > gr1) s[mt][nt][3] = NEG_INF;
                }
            }
        }

        // ---- online softmax ----
#pragma unroll
        for (int mt = 0; mt < 2; mt++) {
            float mx0 = NEG_INF, mx1 = NEG_INF;
#pragma unroll
            for (int nt = 0; nt < 8; nt++) {
                mx0 = fmaxf(mx0, fmaxf(s[mt][nt][0], s[mt][nt][1]));
                mx1 = fmaxf(mx1, fmaxf(s[mt][nt][2], s[mt][nt][3]));
            }
            mx0 = fmaxf(mx0, __shfl_xor_sync(0xffffffffu, mx0, 1));
            mx0 = fmaxf(mx0, __shfl_xor_sync(0xffffffffu, mx0, 2));
            mx1 = fmaxf(mx1, __shfl_xor_sync(0xffffffffu, mx1, 1));
            mx1 = fmaxf(mx1, __shfl_xor_sync(0xffffffffu, mx1, 2));
            float newm0 = fmaxf(mr[mt][0], mx0);
            float newm1 = fmaxf(mr[mt][1], mx1);
            float al0 = __expf(mr[mt][0] - newm0);
            float al1 = __expf(mr[mt][1] - newm1);

            float rs0 = 0.f, rs1 = 0.f;
            int r0 = wq * 32 + mt * 16 + fr, r1 = r0 + 8;
#pragma unroll
            for (int nt = 0; nt < 8; nt++) {
                float p0 = __expf(s[mt][nt][0] - newm0);
                float p1 = __expf(s[mt][nt][1] - newm0);
                float p2 = __expf(s[mt][nt][2] - newm1);
                float p3 = __expf(s[mt][nt][3] - newm1);
                rs0 += p0 + p1; rs1 += p2 + p3;
                int col = nt * 8 + 2 * fc;
                *(float2*)(Ps + r0 * ALD + col) =
                    make_float2(f2tf32f(p0), f2tf32f(p1));
                *(float2*)(Ps + r1 * ALD + col) =
                    make_float2(f2tf32f(p2), f2tf32f(p3));
            }
            rs0 += __shfl_xor_sync(0xffffffffu, rs0, 1);
            rs0 += __shfl_xor_sync(0xffffffffu, rs0, 2);
            rs1 += __shfl_xor_sync(0xffffffffu, rs1, 1);
            rs1 += __shfl_xor_sync(0xffffffffu, rs1, 2);
            lr[mt][0] = lr[mt][0] * al0 + rs0;
            lr[mt][1] = lr[mt][1] * al1 + rs1;
            mr[mt][0] = newm0; mr[mt][1] = newm1;
#pragma unroll
            for (int nt = 0; nt < 8; nt++) {
                O[mt][nt][0] *= al0; O[mt][nt][1] *= al0;
                O[mt][nt][2] *= al1; O[mt][nt][3] *= al1;
            }
        }
        __syncwarp();   // Ps rows warp-private

        // ---- O += P V ----
#pragma unroll
        for (int k8 = 0; k8 < 8; k8++) {
            int kb = k8 * 8;
            uint32_t afr[2][4], bfr[8][2];
#pragma unroll
            for (int mt = 0; mt < 2; mt++) {
                const float* ap = Ps + (wq * 32 + mt * 16 + fr) * ALD + kb + fc;
                afr[mt][0] = __float_as_uint(ap[0]);
                afr[mt][1] = __float_as_uint(ap[8 * ALD]);
                afr[mt][2] = __float_as_uint(ap[4]);
                afr[mt][3] = __float_as_uint(ap[8 * ALD + 4]);
            }
#pragma unroll
            for (int nt = 0; nt < 8; nt++) {
                const float* bp = Vs + (kb + fc) * VLD + nt * 8 + fr;
                bfr[nt][0] = __float_as_uint(bp[0]);
                bfr[nt][1] = __float_as_uint(bp[4 * VLD]);
            }
#pragma unroll
            for (int mt = 0; mt < 2; mt++)
#pragma unroll
                for (int nt = 0; nt < 8; nt++)
                    mma_tf32(O[mt][nt], afr[mt], bfr[nt]);
        }
        __syncthreads();   // before K/V overwrite next iteration
    }

    // epilogue: normalize, tf32-round (consumed by gemmO), store
    float* Ag = &g_Aout[bh][0][0];
#pragma unroll
    for (int mt = 0; mt < 2; mt++) {
        float inv0 = 1.f / lr[mt][0];
        float inv1 = 1.f / lr[mt][1];
        int r0 = qstart + wq * 32 + mt * 16 + fr, r1 = r0 + 8;
#pragma unroll
        for (int nt = 0; nt < 8; nt++) {
            int col = nt * 8 + 2 * fc;
            *(float2*)(Ag + (size_t)r0 * HD + col) = make_float2(
                f2tf32f(O[mt][nt][0] * inv0), f2tf32f(O[mt][nt][1] * inv0));
            *(float2*)(Ag + (size_t)r1 * HD + col) = make_float2(
                f2tf32f(O[mt][nt][2] * inv1), f2tf32f(O[mt][nt][3] * inv1));
        }
    }
}

// ---------------------------------------------------------------------------
// launch
// ---------------------------------------------------------------------------
extern "C" void kernel_launch(void* const* d_in, const int* in_sizes, int n_in,
                              void* d_out, int out_size)
{
    const float* x  = (const float*)d_in[0];
    const float* Wq = (const float*)d_in[1];
    const float* Wk = (const float*)d_in[2];
    const float* Wv = (const float*)d_in[3];
    const float* Wo = (const float*)d_in[4];
    const float* aq = (const float*)d_in[5];
    const float* ak = (const float*)d_in[6];
    const float* av = (const float*)d_in[7];
    const float* cl = (const float*)d_in[8];
    float* out = (float*)d_out;

    cudaFuncSetAttribute(gemmA_k, cudaFuncAttributeMaxDynamicSharedMemorySize, SMEM_GA);
    cudaFuncSetAttribute(gemmO_k, cudaFuncAttributeMaxDynamicSharedMemorySize, SMEM_GO);
    cudaFuncSetAttribute(attn_k, cudaFuncAttributeMaxDynamicSharedMemorySize, SMEM_ATTN);

    round_x_k<<<(MTOK * HIDD) / 256, 256>>>(x);
    build_weff_k<<<dim3((HD * HIDD) / 256, 3), 256>>>(Wq, Wk, Wv, aq, ak, av);
    build_woeff_k<<<(HIDD * HD) / 256, 256>>>(Wo, cl);

    // projections + head mixing (q/k/v via z)
    gemmA_k<<<dim3(NPROJ / 256, MTOK / 128, 3), 256, SMEM_GA>>>();

    // causal SDPA over virtual positions
    attn_k<<<dim3(SVLEN / QTILE, NB * NH), 256, SMEM_ATTN>>>();

    // collapse + output projection
    gemmO_k<<<dim3(HIDD / 128, MTOK / 128), 256, SMEM_GO>>>(out);
}

// round 6
// speedup vs baseline: 2.9435x; 1.0034x over previous
#include <cuda_runtime.h>
#include <cstdint>

// ---------------------------------------------------------------------------
// InterleavedHeadAttention — round 6
//   - k-dim permutation (u -> 2(u&3)+(u>>2) within 8-groups) on every GEMM
//     contraction operand => all mma fragment loads become single LDS.64
//   - gemmA back to 128x128 / warp 32x64, 2 CTAs/SM
//   - attention: double-buffered K/V cp.async + halved QK fragment LDS
//   B=2, S=1024, HID=1024, H=16, P=2, D=64, sv=2048
// ---------------------------------------------------------------------------

#define NB 2
#define SEQ 1024
#define HIDD 1024
#define NH 16
#define NP 2
#define HD 64
#define SVLEN (SEQ * NP)        // 2048
#define MTOK (NB * SEQ)         // 2048
#define NPROJ (NH * NP * HD)    // 2048
#define ATTN_SCALE 0.125f

#define NEG_INF __int_as_float(0xff800000)

// k-permuted storage layouts (within each 8-col group of the contraction dim)
__device__ float g_Weff[3][NPROJ][HIDD];   // e-permuted
__device__ float g_Woeff[HIDD][NPROJ];     // (o,d): d-permuted
__device__ float g_Xr[MTOK][HIDD];         // e-permuted, tf32-rounded
__device__ float g_Q[NB * NH][SVLEN][HD];  // d-permuted
__device__ float g_K[NB * NH][SVLEN][HD];  // d-permuted
__device__ float g_V[NB * NH][SVLEN][HD];  // natural d
__device__ float g_Aout[NB * NH][SVLEN][HD]; // d-permuted (k of gemmO)

// ---------------------------------------------------------------------------
// helpers
// ---------------------------------------------------------------------------
__device__ __forceinline__ int permc(int c) {     // within-8 k permutation
    int u = c & 7;
    return (c & ~7) + ((u & 3) * 2) + (u >> 2);
}
__device__ __forceinline__ void cp16(uint32_t s, const void* g) {
    asm volatile("cp.async.cg.shared.global [%0], [%1], 16;" :: "r"(s), "l"(g));
}
__device__ __forceinline__ uint32_t smem_u32(const void* p) {
    uint32_t a;
    asm("{ .reg .u64 t; cvta.to.shared.u64 t, %1; cvt.u32.u64 %0, t; }"
        : "=r"(a) : "l"(p));
    return a;
}
#define CP_COMMIT() asm volatile("cp.async.commit_group;" ::: "memory")
#define CP_WAIT(n)  asm volatile("cp.async.wait_group %0;" :: "n"(n) : "memory")

__device__ __forceinline__ uint32_t f2tf32(float f) {
    uint32_t r;
    asm("cvt.rna.tf32.f32 %0, %1;" : "=r"(r) : "f"(f));
    return r;
}
__device__ __forceinline__ float f2tf32f(float f) {
    return __uint_as_float(f2tf32(f));
}
__device__ __forceinline__ void mma_tf32(float* c, const uint32_t* a,
                                         const uint32_t* b) {
    asm volatile(
        "mma.sync.aligned.m16n8k8.row.col.f32.tf32.tf32.f32 "
        "{%0,%1,%2,%3}, {%4,%5,%6,%7}, {%8,%9}, {%0,%1,%2,%3};"
        : "+f"(c[0]), "+f"(c[1]), "+f"(c[2]), "+f"(c[3])
        : "r"(a[0]), "r"(a[1]), "r"(a[2]), "r"(a[3]), "r"(b[0]), "r"(b[1]));
}

// ---------------------------------------------------------------------------
// x staging: tf32-round + e-permute
// ---------------------------------------------------------------------------
__global__ __launch_bounds__(256) void round_x_k(const float* __restrict__ x)
{
    int idx = blockIdx.x * 256 + threadIdx.x;
    int r = idx >> 10, e = idx & 1023;
    g_Xr[r][permc(e)] = f2tf32f(x[idx]);
}

// ---------------------------------------------------------------------------
// Effective projection weights (W read once); e-permuted, tf32, scale folded
// ---------------------------------------------------------------------------
__global__ __launch_bounds__(256) void build_weff_k(
    const float* __restrict__ Wq, const float* __restrict__ Wk,
    const float* __restrict__ Wv,
    const float* __restrict__ aq, const float* __restrict__ ak,
    const float* __restrict__ av)
{
    int w = blockIdx.y;
    const float* W = (w == 0) ? Wq : (w == 1) ? Wk : Wv;
    const float* A = (w == 0) ? aq : (w == 1) ? ak : av;
    __shared__ float sA[NH * 32];
    int tid = threadIdx.x;
    sA[tid] = A[tid];
    sA[tid + 256] = A[tid + 256];
    __syncthreads();

    int idx = blockIdx.x * 256 + tid;       // over 64*1024
    int d = idx >> 10, e = idx & 1023;
    int ep = permc(e);
    float wv[NH];
#pragma unroll
    for (int m = 0; m < NH; m++)
        wv[m] = W[(m * HD + d) * HIDD + e];
    float scale = (w == 0) ? ATTN_SCALE : 1.0f;
#pragma unroll
    for (int hp = 0; hp < 32; hp++) {
        float acc = 0.f;
#pragma unroll
        for (int m = 0; m < NH; m++)
            acc += sA[m * 32 + hp] * wv[m];
        g_Weff[w][hp * HD + d][ep] = f2tf32f(acc * scale);
    }
}

// ---------------------------------------------------------------------------
// Effective output weights (Wo read once); d-permuted, tf32
// ---------------------------------------------------------------------------
__global__ __launch_bounds__(256) void build_woeff_k(
    const float* __restrict__ Wo, const float* __restrict__ cl)
{
    __shared__ float sC[NH * 32];
    int tid = threadIdx.x;
    sC[tid] = cl[tid];
    sC[tid + 256] = cl[tid + 256];
    __syncthreads();

    int idx = blockIdx.x * 256 + tid;       // over 1024*64
    int f = idx >> 6, d = idx & 63;
    int dp = permc(d);
    float wv[NH];
#pragma unroll
    for (int h = 0; h < NH; h++)
        wv[h] = Wo[f * HIDD + h * HD + d];
#pragma unroll
    for (int o = 0; o < 32; o++) {
        float acc = 0.f;
#pragma unroll
        for (int h = 0; h < NH; h++)
            acc += sC[h * 32 + o] * wv[h];
        g_Woeff[f][o * HD + dp] = f2tf32f(acc);
    }
}

// ---------------------------------------------------------------------------
// Projection GEMM: C[2048,2048] = Xr * Weff[z]^T, K=1024.
//   CTA 128x128, 8 warps (4M x 2N), warp 32x64, LDT=40, 2-stage, 2 CTAs/SM.
//   Fragment loads are single LDS.64 thanks to k-permuted storage.
// ---------------------------------------------------------------------------
#define LDT 40
#define G_TF (128 * LDT)
#define G_STGF (2 * G_TF)
#define SMEM_G (2 * G_STGF * 4)

__global__ __launch_bounds__(256, 2) void gemmA_k()
{
    extern __shared__ __align__(16) float smf[];
    const int tid = threadIdx.x, wid = tid >> 5, lane = tid & 31;
    const int wm = (wid & 3) * 32;
    const int wn = (wid >> 2) * 64;
    const int bn = blockIdx.x * 128, bm = blockIdx.y * 128;
    const int which = blockIdx.z;
    const float* Aw = &g_Xr[0][0];
    const float* Bw = &g_Weff[which][0][0];
    const uint32_t sb = smem_u32(smf);
    const int fr = lane >> 2, fc = lane & 3;
    const int lrow = tid >> 1;
    const int lc0 = (tid & 1) * 4;

    auto issue = [&](int kc, int s) {
        int k0 = kc * 32;
        uint32_t sa = sb + (uint32_t)(s * G_STGF) * 4;
        uint32_t sbB = sa + G_TF * 4;
        uint32_t soff = (uint32_t)lrow * (LDT * 4) + lc0 * 16;
        const float* asrc = Aw + (size_t)(bm + lrow) * HIDD + k0 + lc0 * 4;
#pragma unroll
        for (int c = 0; c < 4; c++)
            cp16(sa + soff + c * 16, asrc + c * 4);
        const float* bsrc = Bw + (size_t)(bn + lrow) * HIDD + k0 + lc0 * 4;
#pragma unroll
        for (int c = 0; c < 4; c++)
            cp16(sbB + soff + c * 16, bsrc + c * 4);
    };

    float acc[2][8][4];
#pragma unroll
    for (int mt = 0; mt < 2; mt++)
#pragma unroll
        for (int nt = 0; nt < 8; nt++)
#pragma unroll
            for (int j = 0; j < 4; j++) acc[mt][nt][j] = 0.f;

    issue(0, 0); CP_COMMIT();
    issue(1, 1); CP_COMMIT();

    const int NKC = HIDD / 32;
    for (int kc = 0; kc < NKC; kc++) {
        int s = kc & 1;
        CP_WAIT(1);
        __syncthreads();
        const float* As = smf + s * G_STGF;
        const float* Bs = As + G_TF;
#pragma unroll
        for (int k8 = 0; k8 < 4; k8++) {
            int kb = k8 * 8;
            uint32_t afr[2][4], bfr[8][2];
#pragma unroll
            for (int mt = 0; mt < 2; mt++) {
                float2 a0 = *(const float2*)(As + (wm + mt * 16 + fr) * LDT + kb + 2 * fc);
                float2 a1 = *(const float2*)(As + (wm + mt * 16 + fr + 8) * LDT + kb + 2 * fc);
                afr[mt][0] = __float_as_uint(a0.x);
                afr[mt][1] = __float_as_uint(a1.x);
                afr[mt][2] = __float_as_uint(a0.y);
                afr[mt][3] = __float_as_uint(a1.y);
            }
#pragma unroll
            for (int nt = 0; nt < 8; nt++) {
                float2 b = *(const float2*)(Bs + (wn + nt * 8 + fr) * LDT + kb + 2 * fc);
                bfr[nt][0] = __float_as_uint(b.x);
                bfr[nt][1] = __float_as_uint(b.y);
            }
#pragma unroll
            for (int mt = 0; mt < 2; mt++)
#pragma unroll
                for (int nt = 0; nt < 8; nt++)
                    mma_tf32(acc[mt][nt], afr[mt], bfr[nt]);
        }
        __syncthreads();
        int kn = kc + 2;
        if (kn < NKC) issue(kn, kn & 1);
        CP_COMMIT();
    }

    // epilogue: tf32-round; Q/K stored d-permuted (scalar), V natural (vec)
    float* dst0 = (which == 0) ? &g_Q[0][0][0]
                : (which == 1) ? &g_K[0][0][0] : &g_V[0][0][0];
    const int u0 = 2 * fc;              // d&7 of col0
    const int dp0off = ((u0 & 3) * 2) + (u0 >> 2);
    const int u1 = 2 * fc + 1;
    const int dp1off = ((u1 & 3) * 2) + (u1 >> 2);
#pragma unroll
    for (int mt = 0; mt < 2; mt++) {
#pragma unroll
        for (int half = 0; half < 2; half++) {
            int row = bm + wm + mt * 16 + fr + half * 8;
            int b = row >> 10, n = row & 1023;
#pragma unroll
            for (int nt = 0; nt < 8; nt++) {
                int col = bn + wn + nt * 8 + 2 * fc;
                int h = col >> 7, p = (col >> 6) & 1;
                int d = col & 63;
                float v0 = f2tf32f(acc[mt][nt][half * 2 + 0]);
                float v1 = f2tf32f(acc[mt][nt][half * 2 + 1]);
                float* dst = dst0 +
                    ((size_t)(b * NH + h) * SVLEN + n * NP + p) * HD;
                if (which == 2) {
                    *(float2*)(dst + d) = make_float2(v0, v1);
                } else {
                    int dbase = d & ~7;
                    dst[dbase + dp0off] = v0;
                    dst[dbase + dp1off] = v1;
                }
            }
        }
    }
}

// ---------------------------------------------------------------------------
// Output GEMM: out[2048,1024] = gather(g_Aout) * Woeff^T, K=2048.
//   Same tile plan; both operands k-permuted in storage.
// ---------------------------------------------------------------------------
__global__ __launch_bounds__(256, 2) void gemmO_k(float* __restrict__ Cout)
{
    extern __shared__ __align__(16) float smf[];
    const int tid = threadIdx.x, wid = tid >> 5, lane = tid & 31;
    const int wm = (wid & 3) * 32;
    const int wn = (wid >> 2) * 64;
    const int bn = blockIdx.x * 128, bm = blockIdx.y * 128;
    const float* Bw = &g_Woeff[0][0];
    const uint32_t sb = smem_u32(smf);
    const int fr = lane >> 2, fc = lane & 3;
    const int lrow = tid >> 1;
    const int lc0 = (tid & 1) * 4;

    int t = bm + lrow;
    int gb = t >> 10, gn = t & 1023;

    auto issue = [&](int kc, int s) {
        int k0 = kc * 32;
        uint32_t sa = sb + (uint32_t)(s * G_STGF) * 4;
        uint32_t sbB = sa + G_TF * 4;
        uint32_t soff = (uint32_t)lrow * (LDT * 4) + lc0 * 16;
#pragma unroll
        for (int c = 0; c < 4; c++) {
            int col = k0 + (lc0 + c) * 4;           // storage position
            int o = col >> 6, dd = col & 63;        // group-invariant decode
            cp16(sa + soff + c * 16,
                 &g_Aout[gb * NH + (o >> 1)][gn * NP + (o & 1)][dd]);
        }
        const float* bsrc = Bw + (size_t)(bn + lrow) * NPROJ + k0 + lc0 * 4;
#pragma unroll
        for (int c = 0; c < 4; c++)
            cp16(sbB + soff + c * 16, bsrc + c * 4);
    };

    float acc[2][8][4];
#pragma unroll
    for (int mt = 0; mt < 2; mt++)
#pragma unroll
        for (int nt = 0; nt < 8; nt++)
#pragma unroll
            for (int j = 0; j < 4; j++) acc[mt][nt][j] = 0.f;

    issue(0, 0); CP_COMMIT();
    issue(1, 1); CP_COMMIT();

    const int NKC = NPROJ / 32;
    for (int kc = 0; kc < NKC; kc++) {
        int s = kc & 1;
        CP_WAIT(1);
        __syncthreads();
        const float* As = smf + s * G_STGF;
        const float* Bs = As + G_TF;
#pragma unroll
        for (int k8 = 0; k8 < 4; k8++) {
            int kb = k8 * 8;
            uint32_t afr[2][4], bfr[8][2];
#pragma unroll
            for (int mt = 0; mt < 2; mt++) {
                float2 a0 = *(const float2*)(As + (wm + mt * 16 + fr) * LDT + kb + 2 * fc);
                float2 a1 = *(const float2*)(As + (wm + mt * 16 + fr + 8) * LDT + kb + 2 * fc);
                afr[mt][0] = __float_as_uint(a0.x);
                afr[mt][1] = __float_as_uint(a1.x);
                afr[mt][2] = __float_as_uint(a0.y);
                afr[mt][3] = __float_as_uint(a1.y);
            }
#pragma unroll
            for (int nt = 0; nt < 8; nt++) {
                float2 b = *(const float2*)(Bs + (wn + nt * 8 + fr) * LDT + kb + 2 * fc);
                bfr[nt][0] = __float_as_uint(b.x);
                bfr[nt][1] = __float_as_uint(b.y);
            }
#pragma unroll
            for (int mt = 0; mt < 2; mt++)
#pragma unroll
                for (int nt = 0; nt < 8; nt++)
                    mma_tf32(acc[mt][nt], afr[mt], bfr[nt]);
        }
        __syncthreads();
        int kn = kc + 2;
        if (kn < NKC) issue(kn, kn & 1);
        CP_COMMIT();
    }

#pragma unroll
    for (int mt = 0; mt < 2; mt++) {
#pragma unroll
        for (int half = 0; half < 2; half++) {
            int row = bm + wm + mt * 16 + fr + half * 8;
#pragma unroll
            for (int nt = 0; nt < 8; nt++) {
                int col = bn + wn + nt * 8 + 2 * fc;
                *(float2*)(Cout + (size_t)row * HIDD + col) = make_float2(
                    acc[mt][nt][half * 2 + 0], acc[mt][nt][half * 2 + 1]);
            }
        }
    }
}

// ---------------------------------------------------------------------------
// Causal flash attention: q-tile 256, 8 warps x 32 rows, k-tile 64.
//   Q/K d-permuted (float2 fragment loads), double-buffered K/V cp.async.
// ---------------------------------------------------------------------------
#define ALD 72
#define VLD 72
#define QTILE 256
#define KVF (64 * ALD)
#define SMEM_ATTN ((QTILE * ALD * 2 + 4 * KVF) * 4)

__global__ __launch_bounds__(256, 1) void attn_k()
{
    extern __shared__ __align__(16) float sm[];
    float* Qs = sm;                          // [256][ALD]
    float* Ps = Qs + QTILE * ALD;            // [256][ALD]
    float* KVs = Ps + QTILE * ALD;           // 2 x (Ks[64][ALD], Vs[64][VLD])
    const uint32_t sQ = smem_u32(Qs);
    const uint32_t sKV = smem_u32(KVs);

    const int bh = blockIdx.y;
    const int qt = (gridDim.x - 1) - blockIdx.x;    // heavy tiles first
    const int qstart = qt * QTILE;
    const float* Qg = &g_Q[bh][0][0];
    const float* Kg = &g_K[bh][0][0];
    const float* Vg = &g_V[bh][0][0];

    const int tid = threadIdx.x;
    const int wq = tid >> 5;
    const int lane = tid & 31;
    const int fr = lane >> 2;
    const int fc = lane & 3;

    // Q tile (pre-rounded, pre-permuted -> raw cp.async)
#pragma unroll
    for (int it = 0; it < 16; it++) {
        int chunk = tid + 256 * it;
        int row = chunk >> 4;
        int c4 = chunk & 15;
        cp16(sQ + (uint32_t)row * (ALD * 4) + c4 * 16,
             Qg + (size_t)(qstart + row) * HD + c4 * 4);
    }
    CP_COMMIT();

    auto issue_kv = [&](int jt) {
        int buf = jt & 1;
        uint32_t sK = sKV + (uint32_t)(buf * 2 * KVF) * 4;
        uint32_t sV = sK + KVF * 4;
        int kstart = jt * 64;
#pragma unroll
        for (int it = 0; it < 4; it++) {
            int chunk = tid + 256 * it;
            int row = chunk >> 4;
            int c4 = chunk & 15;
            cp16(sK + (uint32_t)row * (ALD * 4) + c4 * 16,
                 Kg + (size_t)(kstart + row) * HD + c4 * 4);
            cp16(sV + (uint32_t)row * (VLD * 4) + c4 * 16,
                 Vg + (size_t)(kstart + row) * HD + c4 * 4);
        }
    };

    float O[2][8][4];
    float mr[2][2], lr[2][2];
#pragma unroll
    for (int mt = 0; mt < 2; mt++) {
        mr[mt][0] = NEG_INF; mr[mt][1] = NEG_INF;
        lr[mt][0] = 0.f; lr[mt][1] = 0.f;
#pragma unroll
        for (int nt = 0; nt < 8; nt++)
#pragma unroll
            for (int j = 0; j < 4; j++) O[mt][nt][j] = 0.f;
    }

    const int jmax = 4 * qt + 3;
    issue_kv(0); CP_COMMIT();

    for (int jt = 0; jt <= jmax; jt++) {
        const int kstart = jt * 64;
        const int buf = jt & 1;
        const float* Ks = KVs + buf * 2 * KVF;
        const float* Vs = Ks + KVF;

        if (jt < jmax) issue_kv(jt + 1);
        CP_COMMIT();
        CP_WAIT(1);          // current tile (and Q on jt=0) complete
        __syncthreads();

        // ---- S = Q K^T ----
        float s[2][8][4];
#pragma unroll
        for (int mt = 0; mt < 2; mt++)
#pragma unroll
            for (int nt = 0; nt < 8; nt++)
#pragma unroll
                for (int j = 0; j < 4; j++) s[mt][nt][j] = 0.f;
#pragma unroll
        for (int k8 = 0; k8 < 8; k8++) {
            int kb = k8 * 8;
            uint32_t afr[2][4], bfr[8][2];
#pragma unroll
            for (int mt = 0; mt < 2; mt++) {
                float2 a0 = *(const float2*)(Qs + (wq * 32 + mt * 16 + fr) * ALD + kb + 2 * fc);
                float2 a1 = *(const float2*)(Qs + (wq * 32 + mt * 16 + fr + 8) * ALD + kb + 2 * fc);
                afr[mt][0] = __float_as_uint(a0.x);
                afr[mt][1] = __float_as_uint(a1.x);
                afr[mt][2] = __float_as_uint(a0.y);
                afr[mt][3] = __float_as_uint(a1.y);
            }
#pragma unroll
            for (int nt = 0; nt < 8; nt++) {
                float2 b = *(const float2*)(Ks + (nt * 8 + fr) * ALD + kb + 2 * fc);
                bfr[nt][0] = __float_as_uint(b.x);
                bfr[nt][1] = __float_as_uint(b.y);
            }
#pragma unroll
            for (int mt = 0; mt < 2; mt++)
#pragma unroll
                for (int nt = 0; nt < 8; nt++)
                    mma_tf32(s[mt][nt], afr[mt], bfr[nt]);
        }

        // causal mask
#pragma unroll
        for (int mt = 0; mt < 2; mt++) {
            int base = qstart + wq * 32 + mt * 16;
            if (kstart + 63 > base) {
                int gr0 = base + fr, gr1 = gr0 + 8;
#pragma unroll
                for (int nt = 0; nt < 8; nt++) {
                    int c0 = kstart + nt * 8 + 2 * fc;
                    if (c0 > gr0)     s[mt][nt][0] = NEG_INF;
                    if (c0 + 1 > gr0) s[mt][nt][1] = NEG_INF;
                    if (c0 > gr1)     s[mt][nt][2] = NEG_INF;
                    if (c0 + 1 > gr1) s[mt][nt][3] = NEG_INF;
                }
            }
        }

        // ---- online softmax ----
#pragma unroll
        for (int mt = 0; mt < 2; mt++) {
            float mx0 = NEG_INF, mx1 = NEG_INF;
#pragma unroll
            for (int nt = 0; nt < 8; nt++) {
                mx0 = fmaxf(mx0, fmaxf(s[mt][nt][0], s[mt][nt][1]));
                mx1 = fmaxf(mx1, fmaxf(s[mt][nt][2], s[mt][nt][3]));
            }
            mx0 = fmaxf(mx0, __shfl_xor_sync(0xffffffffu, mx0, 1));
            mx0 = fmaxf(mx0, __shfl_xor_sync(0xffffffffu, mx0, 2));
            mx1 = fmaxf(mx1, __shfl_xor_sync(0xffffffffu, mx1, 1));
            mx1 = fmaxf(mx1, __shfl_xor_sync(0xffffffffu, mx1, 2));
            float newm0 = fmaxf(mr[mt][0], mx0);
            float newm1 = fmaxf(mr[mt][1], mx1);
            float al0 = __expf(mr[mt][0] - newm0);
            float al1 = __expf(mr[mt][1] - newm1);

            float rs0 = 0.f, rs1 = 0.f;
            int r0 = wq * 32 + mt * 16 + fr, r1 = r0 + 8;
#pragma unroll
            for (int nt = 0; nt < 8; nt++) {
                float p0 = __expf(s[mt][nt][0] - newm0);
                float p1 = __expf(s[mt][nt][1] - newm0);
                float p2 = __expf(s[mt][nt][2] - newm1);
                float p3 = __expf(s[mt][nt][3] - newm1);
                rs0 += p0 + p1; rs1 += p2 + p3;
                int col = nt * 8 + 2 * fc;
                *(float2*)(Ps + r0 * ALD + col) =
                    make_float2(f2tf32f(p0), f2tf32f(p1));
                *(float2*)(Ps + r1 * ALD + col) =
                    make_float2(f2tf32f(p2), f2tf32f(p3));
            }
            rs0 += __shfl_xor_sync(0xffffffffu, rs0, 1);
            rs0 += __shfl_xor_sync(0xffffffffu, rs0, 2);
            rs1 += __shfl_xor_sync(0xffffffffu, rs1, 1);
            rs1 += __shfl_xor_sync(0xffffffffu, rs1, 2);
            lr[mt][0] = lr[mt][0] * al0 + rs0;
            lr[mt][1] = lr[mt][1] * al1 + rs1;
            mr[mt][0] = newm0; mr[mt][1] = newm1;
#pragma unroll
            for (int nt = 0; nt < 8; nt++) {
                O[mt][nt][0] *= al0; O[mt][nt][1] *= al0;
                O[mt][nt][2] *= al1; O[mt][nt][3] *= al1;
            }
        }
        __syncwarp();   // Ps rows warp-private

        // ---- O += P V (P natural layout; V natural d) ----
#pragma unroll
        for (int k8 = 0; k8 < 8; k8++) {
            int kb = k8 * 8;
            uint32_t afr[2][4], bfr[8][2];
#pragma unroll
            for (int mt = 0; mt < 2; mt++) {
                const float* ap = Ps + (wq * 32 + mt * 16 + fr) * ALD + kb + fc;
                afr[mt][0] = __float_as_uint(ap[0]);
                afr[mt][1] = __float_as_uint(ap[8 * ALD]);
                afr[mt][2] = __float_as_uint(ap[4]);
                afr[mt][3] = __float_as_uint(ap[8 * ALD + 4]);
            }
#pragma unroll
            for (int nt = 0; nt < 8; nt++) {
                const float* bp = Vs + (kb + fc) * VLD + nt * 8 + fr;
                bfr[nt][0] = __float_as_uint(bp[0]);
                bfr[nt][1] = __float_as_uint(bp[4 * VLD]);
            }
#pragma unroll
            for (int mt = 0; mt < 2; mt++)
#pragma unroll
                for (int nt = 0; nt < 8; nt++)
                    mma_tf32(O[mt][nt], afr[mt], bfr[nt]);
        }
        __syncthreads();   // done with buf before its re-fill next+1 iter
    }

    // epilogue: normalize, tf32-round, store d-PERMUTED (gemmO's k layout)
    float* Ag = &g_Aout[bh][0][0];
    const int u0 = 2 * fc, u1 = 2 * fc + 1;
    const int dp0off = ((u0 & 3) * 2) + (u0 >> 2);
    const int dp1off = ((u1 & 3) * 2) + (u1 >> 2);
#pragma unroll
    for (int mt = 0; mt < 2; mt++) {
        float inv0 = 1.f / lr[mt][0];
        float inv1 = 1.f / lr[mt][1];
        int r0 = qstart + wq * 32 + mt * 16 + fr, r1 = r0 + 8;
#pragma unroll
        for (int nt = 0; nt < 8; nt++) {
            int dbase = nt * 8;
            Ag[(size_t)r0 * HD + dbase + dp0off] = f2tf32f(O[mt][nt][0] * inv0);
            Ag[(size_t)r0 * HD + dbase + dp1off] = f2tf32f(O[mt][nt][1] * inv0);
            Ag[(size_t)r1 * HD + dbase + dp0off] = f2tf32f(O[mt][nt][2] * inv1);
            Ag[(size_t)r1 * HD + dbase + dp1off] = f2tf32f(O[mt][nt][3] * inv1);
        }
    }
}

// ---------------------------------------------------------------------------
// launch
// ---------------------------------------------------------------------------
extern "C" void kernel_launch(void* const* d_in, const int* in_sizes, int n_in,
                              void* d_out, int out_size)
{
    const float* x  = (const float*)d_in[0];
    const float* Wq = (const float*)d_in[1];
    const float* Wk = (const float*)d_in[2];
    const float* Wv = (const float*)d_in[3];
    const float* Wo = (const float*)d_in[4];
    const float* aq = (const float*)d_in[5];
    const float* ak = (const float*)d_in[6];
    const float* av = (const float*)d_in[7];
    const float* cl = (const float*)d_in[8];
    float* out = (float*)d_out;

    cudaFuncSetAttribute(gemmA_k, cudaFuncAttributeMaxDynamicSharedMemorySize, SMEM_G);
    cudaFuncSetAttribute(gemmO_k, cudaFuncAttributeMaxDynamicSharedMemorySize, SMEM_G);
    cudaFuncSetAttribute(attn_k, cudaFuncAttributeMaxDynamicSharedMemorySize, SMEM_ATTN);

    round_x_k<<<(MTOK * HIDD) / 256, 256>>>(x);
    build_weff_k<<<dim3((HD * HIDD) / 256, 3), 256>>>(Wq, Wk, Wv, aq, ak, av);
    build_woeff_k<<<(HIDD * HD) / 256, 256>>>(Wo, cl);

    // projections + head mixing (q/k/v via z)
    gemmA_k<<<dim3(NPROJ / 128, MTOK / 128, 3), 256, SMEM_G>>>();

    // causal SDPA over virtual positions
    attn_k<<<dim3(SVLEN / QTILE, NB * NH), 256, SMEM_ATTN>>>();

    // collapse + output projection
    gemmO_k<<<dim3(HIDD / 128, MTOK / 128), 256, SMEM_G>>>(out);
}

// round 7
// speedup vs baseline: 4.6924x; 1.5941x over previous
#include <cuda_runtime.h>
#include <cuda_fp16.h>
#include <cstdint>

// ---------------------------------------------------------------------------
// InterleavedHeadAttention — round 7: fp16 m16n8k16 everywhere (fp32 accum).
//   fp16 mantissa == tf32 mantissa (10 bits) -> rel_err preserved, but
//   2x arithmetic per MMA instruction, half the smem traffic.
//   k-dim 16-group permutation (pair q -> slot 2(q&3)+(q>>2)) => A-frag =
//   2x LDS.64, B-frag = 1x LDS.64.
//   B=2, S=1024, HID=1024, H=16, P=2, D=64, sv=2048
// ---------------------------------------------------------------------------

#define NB 2
#define SEQ 1024
#define HIDD 1024
#define NH 16
#define NP 2
#define HD 64
#define SVLEN (SEQ * NP)        // 2048
#define MTOK (NB * SEQ)         // 2048
#define NPROJ (NH * NP * HD)    // 2048
#define ATTN_SCALE 0.125f

#define NEG_INF __int_as_float(0xff800000)

// fp16, k-permuted storage
__device__ __half g_Weff[3][NPROJ][HIDD];    // e-perm16
__device__ __half g_Woeff[HIDD][NPROJ];      // (o,d): d-perm16
__device__ __half g_Xr[MTOK][HIDD];          // e-perm16
__device__ __half g_Q[NB * NH][SVLEN][HD];   // d-perm16
__device__ __half g_K[NB * NH][SVLEN][HD];   // d-perm16
__device__ __half g_Vt[NB * NH][HD][SVLEN];  // transposed, kv-perm16
__device__ __half g_Aout[NB * NH][SVLEN][HD];// d-perm16

// ---------------------------------------------------------------------------
// helpers
// ---------------------------------------------------------------------------
__device__ __forceinline__ int perm16(int c) {       // full element perm
    int u = c & 15, q = u >> 1, b = u & 1;
    return (c & ~15) + 4 * (q & 3) + 2 * (q >> 2) + b;
}
__device__ __forceinline__ int perm16p(int c) {      // even c: pair start pos
    int q = (c & 15) >> 1;
    return (c & ~15) + 4 * (q & 3) + 2 * (q >> 2);
}
__device__ __forceinline__ void cp16(uint32_t s, const void* g) {
    asm volatile("cp.async.cg.shared.global [%0], [%1], 16;" :: "r"(s), "l"(g));
}
__device__ __forceinline__ uint32_t smem_u32(const void* p) {
    uint32_t a;
    asm("{ .reg .u64 t; cvta.to.shared.u64 t, %1; cvt.u32.u64 %0, t; }"
        : "=r"(a) : "l"(p));
    return a;
}
#define CP_COMMIT() asm volatile("cp.async.commit_group;" ::: "memory")
#define CP_WAIT(n)  asm volatile("cp.async.wait_group %0;" :: "n"(n) : "memory")

__device__ __forceinline__ void st_h2(__half* p, float a, float b) {
    *(__half2*)p = __float22half2_rn(make_float2(a, b));
}
// D(16x8) += A(16x16) * B(16x8), f16 in, f32 accum
__device__ __forceinline__ void mma_f16(float* c, const uint32_t* a,
                                        const uint32_t* b) {
    asm volatile(
        "mma.sync.aligned.m16n8k16.row.col.f32.f16.f16.f32 "
        "{%0,%1,%2,%3}, {%4,%5,%6,%7}, {%8,%9}, {%0,%1,%2,%3};"
        : "+f"(c[0]), "+f"(c[1]), "+f"(c[2]), "+f"(c[3])
        : "r"(a[0]), "r"(a[1]), "r"(a[2]), "r"(a[3]), "r"(b[0]), "r"(b[1]));
}

// ---------------------------------------------------------------------------
// producers: x staging + effective weights (fp16, permuted)
// ---------------------------------------------------------------------------
__global__ __launch_bounds__(256) void round_x_k(const float* __restrict__ x)
{
    int idx = blockIdx.x * 256 + threadIdx.x;
    int r = idx >> 10, e = idx & 1023;
    g_Xr[r][perm16(e)] = __float2half_rn(x[idx]);
}

__global__ __launch_bounds__(256) void build_weff_k(
    const float* __restrict__ Wq, const float* __restrict__ Wk,
    const float* __restrict__ Wv,
    const float* __restrict__ aq, const float* __restrict__ ak,
    const float* __restrict__ av)
{
    int w = blockIdx.y;
    const float* W = (w == 0) ? Wq : (w == 1) ? Wk : Wv;
    const float* A = (w == 0) ? aq : (w == 1) ? ak : av;
    __shared__ float sA[NH * 32];
    int tid = threadIdx.x;
    sA[tid] = A[tid];
    sA[tid + 256] = A[tid + 256];
    __syncthreads();

    int idx = blockIdx.x * 256 + tid;       // over 64*1024
    int d = idx >> 10, e = idx & 1023;
    int ep = perm16(e);
    float wv[NH];
#pragma unroll
    for (int m = 0; m < NH; m++)
        wv[m] = W[(m * HD + d) * HIDD + e];
    float scale = (w == 0) ? ATTN_SCALE : 1.0f;
#pragma unroll
    for (int hp = 0; hp < 32; hp++) {
        float acc = 0.f;
#pragma unroll
        for (int m = 0; m < NH; m++)
            acc += sA[m * 32 + hp] * wv[m];
        g_Weff[w][hp * HD + d][ep] = __float2half_rn(acc * scale);
    }
}

__global__ __launch_bounds__(256) void build_woeff_k(
    const float* __restrict__ Wo, const float* __restrict__ cl)
{
    __shared__ float sC[NH * 32];
    int tid = threadIdx.x;
    sC[tid] = cl[tid];
    sC[tid + 256] = cl[tid + 256];
    __syncthreads();

    int idx = blockIdx.x * 256 + tid;       // over 1024*64
    int f = idx >> 6, d = idx & 63;
    int dp = perm16(d);
    float wv[NH];
#pragma unroll
    for (int h = 0; h < NH; h++)
        wv[h] = Wo[f * HIDD + h * HD + d];
#pragma unroll
    for (int o = 0; o < 32; o++) {
        float acc = 0.f;
#pragma unroll
        for (int h = 0; h < NH; h++)
            acc += sC[h * 32 + o] * wv[h];
        g_Woeff[f][o * HD + dp] = __float2half_rn(acc);
    }
}

// ---------------------------------------------------------------------------
// Projection GEMM (fp16): C[2048,2048] = Xr * Weff[z]^T, K=1024.
//   CTA 128x128, 8 warps (4M x 2N), warp 32x64. KC=64 halves, 2-stage.
//   LDH=72 halves (144B rows: conflict-free LDS.64).
// ---------------------------------------------------------------------------
#define LDH 72
#define G_TILEH (128 * LDH)              // halves per tile
#define G_STGH (2 * G_TILEH)
#define SMEM_G (2 * G_STGH * 2)          // bytes

__global__ __launch_bounds__(256, 2) void gemmA_k()
{
    extern __shared__ __align__(16) __half smh[];
    const int tid = threadIdx.x, wid = tid >> 5, lane = tid & 31;
    const int wm = (wid & 3) * 32;
    const int wn = (wid >> 2) * 64;
    const int bn = blockIdx.x * 128, bm = blockIdx.y * 128;
    const int which = blockIdx.z;
    const __half* Aw = &g_Xr[0][0];
    const __half* Bw = &g_Weff[which][0][0];
    const uint32_t sb = smem_u32(smh);
    const int fr = lane >> 2, fc = lane & 3;
    const int lrow = tid >> 1;
    const int lhh = (tid & 1) * 32;      // halves

    auto issue = [&](int kc, int s) {
        int k0 = kc * 64;
        uint32_t sa = sb + (uint32_t)(s * G_STGH) * 2;
        uint32_t sbB = sa + G_TILEH * 2;
        uint32_t soff = (uint32_t)lrow * (LDH * 2) + lhh * 2;
        const __half* asrc = Aw + (size_t)(bm + lrow) * HIDD + k0 + lhh;
#pragma unroll
        for (int c = 0; c < 4; c++)
            cp16(sa + soff + c * 16, asrc + c * 8);
        const __half* bsrc = Bw + (size_t)(bn + lrow) * HIDD + k0 + lhh;
#pragma unroll
        for (int c = 0; c < 4; c++)
            cp16(sbB + soff + c * 16, bsrc + c * 8);
    };

    float acc[2][8][4];
#pragma unroll
    for (int mt = 0; mt < 2; mt++)
#pragma unroll
        for (int nt = 0; nt < 8; nt++)
#pragma unroll
            for (int j = 0; j < 4; j++) acc[mt][nt][j] = 0.f;

    issue(0, 0); CP_COMMIT();
    issue(1, 1); CP_COMMIT();

    const int NKC = HIDD / 64;
    for (int kc = 0; kc < NKC; kc++) {
        int s = kc & 1;
        CP_WAIT(1);
        __syncthreads();
        const __half* As = smh + s * G_STGH;
        const __half* Bs = As + G_TILEH;
#pragma unroll
        for (int k16 = 0; k16 < 4; k16++) {
            int kb = k16 * 16;
            uint32_t afr[2][4], bfr[8][2];
#pragma unroll
            for (int mt = 0; mt < 2; mt++) {
                uint2 a0 = *(const uint2*)(As + (wm + mt * 16 + fr) * LDH + kb + 4 * fc);
                uint2 a1 = *(const uint2*)(As + (wm + mt * 16 + fr + 8) * LDH + kb + 4 * fc);
                afr[mt][0] = a0.x; afr[mt][1] = a1.x;
                afr[mt][2] = a0.y; afr[mt][3] = a1.y;
            }
#pragma unroll
            for (int nt = 0; nt < 8; nt++) {
                uint2 b = *(const uint2*)(Bs + (wn + nt * 8 + fr) * LDH + kb + 4 * fc);
                bfr[nt][0] = b.x; bfr[nt][1] = b.y;
            }
#pragma unroll
            for (int mt = 0; mt < 2; mt++)
#pragma unroll
                for (int nt = 0; nt < 8; nt++)
                    mma_f16(acc[mt][nt], afr[mt], bfr[nt]);
        }
        __syncthreads();
        int kn = kc + 2;
        if (kn < NKC) issue(kn, kn & 1);
        CP_COMMIT();
    }

    // ---- epilogue ----
    if (which == 2) {
        // V: store transposed into g_Vt[bh][d][kv_perm]
        int h = bn >> 7, p = (wn >> 6) & 1;   // constant per warp tile
#pragma unroll
        for (int mt = 0; mt < 2; mt++) {
#pragma unroll
            for (int half_ = 0; half_ < 2; half_++) {
                int row = bm + wm + mt * 16 + fr + half_ * 8;
                int b = row >> 10, n = row & 1023;
                int kvp = perm16(n * NP + p);
                __half* Vt = &g_Vt[b * NH + h][0][0];
#pragma unroll
                for (int nt = 0; nt < 8; nt++) {
                    int d = nt * 8 + 2 * fc;          // local 0..63
                    Vt[(size_t)d * SVLEN + kvp] =
                        __float2half_rn(acc[mt][nt][half_ * 2 + 0]);
                    Vt[(size_t)(d + 1) * SVLEN + kvp] =
                        __float2half_rn(acc[mt][nt][half_ * 2 + 1]);
                }
            }
        }
    } else {
        __half* dst0 = (which == 0) ? &g_Q[0][0][0] : &g_K[0][0][0];
#pragma unroll
        for (int mt = 0; mt < 2; mt++) {
#pragma unroll
            for (int half_ = 0; half_ < 2; half_++) {
                int row = bm + wm + mt * 16 + fr + half_ * 8;
                int b = row >> 10, n = row & 1023;
#pragma unroll
                for (int nt = 0; nt < 8; nt++) {
                    int col = bn + wn + nt * 8 + 2 * fc;
                    int h = col >> 7, p = (col >> 6) & 1;
                    int pos = perm16p(col & 63);
                    __half* dst = dst0 +
                        ((size_t)(b * NH + h) * SVLEN + n * NP + p) * HD + pos;
                    st_h2(dst, acc[mt][nt][half_ * 2 + 0],
                               acc[mt][nt][half_ * 2 + 1]);
                }
            }
        }
    }
}

// ---------------------------------------------------------------------------
// Output GEMM (fp16): out[2048,1024] = gather(g_Aout) * Woeff^T, K=2048.
// ---------------------------------------------------------------------------
__global__ __launch_bounds__(256, 2) void gemmO_k(float* __restrict__ Cout)
{
    extern __shared__ __align__(16) __half smh[];
    const int tid = threadIdx.x, wid = tid >> 5, lane = tid & 31;
    const int wm = (wid & 3) * 32;
    const int wn = (wid >> 2) * 64;
    const int bn = blockIdx.x * 128, bm = blockIdx.y * 128;
    const __half* Bw = &g_Woeff[0][0];
    const uint32_t sb = smem_u32(smh);
    const int fr = lane >> 2, fc = lane & 3;
    const int lrow = tid >> 1;
    const int lhh = (tid & 1) * 32;

    int t = bm + lrow;
    int gb = t >> 10, gn = t & 1023;

    auto issue = [&](int kc, int s) {
        int k0 = kc * 64;
        uint32_t sa = sb + (uint32_t)(s * G_STGH) * 2;
        uint32_t sbB = sa + G_TILEH * 2;
        uint32_t soff = (uint32_t)lrow * (LDH * 2) + lhh * 2;
#pragma unroll
        for (int c = 0; c < 4; c++) {
            int col = k0 + lhh + c * 8;            // storage position
            int o = col >> 6, dd = col & 63;
            cp16(sa + soff + c * 16,
                 &g_Aout[gb * NH + (o >> 1)][gn * NP + (o & 1)][dd]);
        }
        const __half* bsrc = Bw + (size_t)(bn + lrow) * NPROJ + k0 + lhh;
#pragma unroll
        for (int c = 0; c < 4; c++)
            cp16(sbB + soff + c * 16, bsrc + c * 8);
    };

    float acc[2][8][4];
#pragma unroll
    for (int mt = 0; mt < 2; mt++)
#pragma unroll
        for (int nt = 0; nt < 8; nt++)
#pragma unroll
            for (int j = 0; j < 4; j++) acc[mt][nt][j] = 0.f;

    issue(0, 0); CP_COMMIT();
    issue(1, 1); CP_COMMIT();

    const int NKC = NPROJ / 64;
    for (int kc = 0; kc < NKC; kc++) {
        int s = kc & 1;
        CP_WAIT(1);
        __syncthreads();
        const __half* As = smh + s * G_STGH;
        const __half* Bs = As + G_TILEH;
#pragma unroll
        for (int k16 = 0; k16 < 4; k16++) {
            int kb = k16 * 16;
            uint32_t afr[2][4], bfr[8][2];
#pragma unroll
            for (int mt = 0; mt < 2; mt++) {
                uint2 a0 = *(const uint2*)(As + (wm + mt * 16 + fr) * LDH + kb + 4 * fc);
                uint2 a1 = *(const uint2*)(As + (wm + mt * 16 + fr + 8) * LDH + kb + 4 * fc);
                afr[mt][0] = a0.x; afr[mt][1] = a1.x;
                afr[mt][2] = a0.y; afr[mt][3] = a1.y;
            }
#pragma unroll
            for (int nt = 0; nt < 8; nt++) {
                uint2 b = *(const uint2*)(Bs + (wn + nt * 8 + fr) * LDH + kb + 4 * fc);
                bfr[nt][0] = b.x; bfr[nt][1] = b.y;
            }
#pragma unroll
            for (int mt = 0; mt < 2; mt++)
#pragma unroll
                for (int nt = 0; nt < 8; nt++)
                    mma_f16(acc[mt][nt], afr[mt], bfr[nt]);
        }
        __syncthreads();
        int kn = kc + 2;
        if (kn < NKC) issue(kn, kn & 1);
        CP_COMMIT();
    }

#pragma unroll
    for (int mt = 0; mt < 2; mt++) {
#pragma unroll
        for (int half_ = 0; half_ < 2; half_++) {
            int row = bm + wm + mt * 16 + fr + half_ * 8;
#pragma unroll
            for (int nt = 0; nt < 8; nt++) {
                int col = bn + wn + nt * 8 + 2 * fc;
                *(float2*)(Cout + (size_t)row * HIDD + col) = make_float2(
                    acc[mt][nt][half_ * 2 + 0], acc[mt][nt][half_ * 2 + 1]);
            }
        }
    }
}

// ---------------------------------------------------------------------------
// Causal flash attention (fp16 MMA): q-tile 128 (warp 16 rows), k-tile 64,
// double-buffered K/Vt, 2 CTAs/SM.
// ---------------------------------------------------------------------------
#define QLD 72
#define Q_H (128 * QLD)
#define KV_H (64 * QLD)
#define SMEM_ATTN ((2 * Q_H + 4 * KV_H) * 2)

__global__ __launch_bounds__(256, 2) void attn_k()
{
    extern __shared__ __align__(16) __half smA[];
    __half* Qs = smA;                     // [128][QLD]
    __half* Ps = Qs + Q_H;                // [128][QLD]
    __half* KVs = Ps + Q_H;               // 2 x (Ks[64][QLD], Vts[64][QLD])
    const uint32_t sQ = smem_u32(Qs);
    const uint32_t sKV = smem_u32(KVs);

    const int bh = blockIdx.y;
    const int qt = (gridDim.x - 1) - blockIdx.x;   // heavy tiles first
    const int qstart = qt * 128;
    const __half* Qg = &g_Q[bh][0][0];
    const __half* Kg = &g_K[bh][0][0];
    const __half* Vtg = &g_Vt[bh][0][0];

    const int tid = threadIdx.x;
    const int wq = tid >> 5;
    const int lane = tid & 31;
    const int fr = lane >> 2;
    const int fc = lane & 3;
    const int r0 = wq * 16 + fr, r1 = r0 + 8;

    // Q tile: 128 rows x 64 halves (8 chunks/row)
#pragma unroll
    for (int it = 0; it < 4; it++) {
        int chunk = tid + 256 * it;
        int row = chunk >> 3;
        int c = chunk & 7;
        cp16(sQ + (uint32_t)row * (QLD * 2) + c * 16,
             Qg + (size_t)(qstart + row) * HD + c * 8);
    }
    CP_COMMIT();

    auto issue_kv = [&](int jt) {
        int buf = jt & 1;
        uint32_t sK = sKV + (uint32_t)(buf * 2 * KV_H) * 2;
        uint32_t sV = sK + KV_H * 2;
        int kstart = jt * 64;
#pragma unroll
        for (int it = 0; it < 2; it++) {
            int chunk = tid + 256 * it;
            int row = chunk >> 3;
            int c = chunk & 7;
            cp16(sK + (uint32_t)row * (QLD * 2) + c * 16,
                 Kg + (size_t)(kstart + row) * HD + c * 8);
            cp16(sV + (uint32_t)row * (QLD * 2) + c * 16,
                 Vtg + (size_t)row * SVLEN + kstart + c * 8);
        }
    };

    float O[8][4];
    float m0 = NEG_INF, m1 = NEG_INF, l0 = 0.f, l1 = 0.f;
#pragma unroll
    for (int nt = 0; nt < 8; nt++)
#pragma unroll
        for (int j = 0; j < 4; j++) O[nt][j] = 0.f;

    const int jmax = 2 * qt + 1;
    issue_kv(0); CP_COMMIT();

    for (int jt = 0; jt <= jmax; jt++) {
        const int kstart = jt * 64;
        const int buf = jt & 1;
        const __half* Ks = KVs + buf * 2 * KV_H;
        const __half* Vts = Ks + KV_H;

        if (jt < jmax) issue_kv(jt + 1);
        CP_COMMIT();
        CP_WAIT(1);
        __syncthreads();

        // ---- S = Q K^T ----
        float s[8][4];
#pragma unroll
        for (int nt = 0; nt < 8; nt++)
#pragma unroll
            for (int j = 0; j < 4; j++) s[nt][j] = 0.f;
#pragma unroll
        for (int k16 = 0; k16 < 4; k16++) {
            int kb = k16 * 16;
            uint32_t afr[4], bfr[8][2];
            uint2 a0 = *(const uint2*)(Qs + r0 * QLD + kb + 4 * fc);
            uint2 a1 = *(const uint2*)(Qs + r1 * QLD + kb + 4 * fc);
            afr[0] = a0.x; afr[1] = a1.x; afr[2] = a0.y; afr[3] = a1.y;
#pragma unroll
            for (int nt = 0; nt < 8; nt++) {
                uint2 b = *(const uint2*)(Ks + (nt * 8 + fr) * QLD + kb + 4 * fc);
                bfr[nt][0] = b.x; bfr[nt][1] = b.y;
            }
#pragma unroll
            for (int nt = 0; nt < 8; nt++)
                mma_f16(s[nt], afr, bfr[nt]);
        }

        // causal mask
        if (kstart + 63 > qstart + wq * 16) {
            int gr0 = qstart + r0, gr1 = gr0 + 8;
#pragma unroll
            for (int nt = 0; nt < 8; nt++) {
                int c0 = kstart + nt * 8 + 2 * fc;
                if (c0 > gr0)     s[nt][0] = NEG_INF;
                if (c0 + 1 > gr0) s[nt][1] = NEG_INF;
                if (c0 > gr1)     s[nt][2] = NEG_INF;
                if (c0 + 1 > gr1) s[nt][3] = NEG_INF;
            }
        }

        // ---- online softmax ----
        float mx0 = NEG_INF, mx1 = NEG_INF;
#pragma unroll
        for (int nt = 0; nt < 8; nt++) {
            mx0 = fmaxf(mx0, fmaxf(s[nt][0], s[nt][1]));
            mx1 = fmaxf(mx1, fmaxf(s[nt][2], s[nt][3]));
        }
        mx0 = fmaxf(mx0, __shfl_xor_sync(0xffffffffu, mx0, 1));
        mx0 = fmaxf(mx0, __shfl_xor_sync(0xffffffffu, mx0, 2));
        mx1 = fmaxf(mx1, __shfl_xor_sync(0xffffffffu, mx1, 1));
        mx1 = fmaxf(mx1, __shfl_xor_sync(0xffffffffu, mx1, 2));
        float newm0 = fmaxf(m0, mx0), newm1 = fmaxf(m1, mx1);
        float al0 = __expf(m0 - newm0), al1 = __expf(m1 - newm1);

        float rs0 = 0.f, rs1 = 0.f;
#pragma unroll
        for (int nt = 0; nt < 8; nt++) {
            float p0 = __expf(s[nt][0] - newm0);
            float p1 = __expf(s[nt][1] - newm0);
            float p2 = __expf(s[nt][2] - newm1);
            float p3 = __expf(s[nt][3] - newm1);
            rs0 += p0 + p1; rs1 += p2 + p3;
            // kv-permuted P store (pairs stay adjacent)
            int u = (nt * 8 + 2 * fc) & 15;
            int q = u >> 1;
            int colp = ((nt >> 1) * 16) + 4 * (q & 3) + 2 * (q >> 2);
            st_h2(Ps + r0 * QLD + colp, p0, p1);
            st_h2(Ps + r1 * QLD + colp, p2, p3);
        }
        rs0 += __shfl_xor_sync(0xffffffffu, rs0, 1);
        rs0 += __shfl_xor_sync(0xffffffffu, rs0, 2);
        rs1 += __shfl_xor_sync(0xffffffffu, rs1, 1);
        rs1 += __shfl_xor_sync(0xffffffffu, rs1, 2);
        l0 = l0 * al0 + rs0; l1 = l1 * al1 + rs1;
        m0 = newm0; m1 = newm1;
#pragma unroll
        for (int nt = 0; nt < 8; nt++) {
            O[nt][0] *= al0; O[nt][1] *= al0;
            O[nt][2] *= al1; O[nt][3] *= al1;
        }
        __syncwarp();   // Ps rows warp-private

        // ---- O += P V (A from Ps kv-perm, B from Vts kv-perm) ----
#pragma unroll
        for (int k16 = 0; k16 < 4; k16++) {
            int kb = k16 * 16;
            uint32_t afr[4], bfr[8][2];
            uint2 a0 = *(const uint2*)(Ps + r0 * QLD + kb + 4 * fc);
            uint2 a1 = *(const uint2*)(Ps + r1 * QLD + kb + 4 * fc);
            afr[0] = a0.x; afr[1] = a1.x; afr[2] = a0.y; afr[3] = a1.y;
#pragma unroll
            for (int nt = 0; nt < 8; nt++) {
                uint2 b = *(const uint2*)(Vts + (nt * 8 + fr) * QLD + kb + 4 * fc);
                bfr[nt][0] = b.x; bfr[nt][1] = b.y;
            }
#pragma unroll
            for (int nt = 0; nt < 8; nt++)
                mma_f16(O[nt], afr, bfr[nt]);
        }
        __syncthreads();   // done with buf before its re-fill next iter
    }

    // epilogue: normalize, store d-permuted fp16 into g_Aout
    __half* Ag = &g_Aout[bh][0][0];
    float inv0 = 1.f / l0, inv1 = 1.f / l1;
#pragma unroll
    for (int nt = 0; nt < 8; nt++) {
        int pos = perm16p(nt * 8 + 2 * fc);
        st_h2(Ag + (size_t)(qstart + r0) * HD + pos,
              O[nt][0] * inv0, O[nt][1] * inv0);
        st_h2(Ag + (size_t)(qstart + r1) * HD + pos,
              O[nt][2] * inv1, O[nt][3] * inv1);
    }
}

// ---------------------------------------------------------------------------
// launch
// ---------------------------------------------------------------------------
extern "C" void kernel_launch(void* const* d_in, const int* in_sizes, int n_in,
                              void* d_out, int out_size)
{
    const float* x  = (const float*)d_in[0];
    const float* Wq = (const float*)d_in[1];
    const float* Wk = (const float*)d_in[2];
    const float* Wv = (const float*)d_in[3];
    const float* Wo = (const float*)d_in[4];
    const float* aq = (const float*)d_in[5];
    const float* ak = (const float*)d_in[6];
    const float* av = (const float*)d_in[7];
    const float* cl = (const float*)d_in[8];
    float* out = (float*)d_out;

    cudaFuncSetAttribute(gemmA_k, cudaFuncAttributeMaxDynamicSharedMemorySize, SMEM_G);
    cudaFuncSetAttribute(gemmO_k, cudaFuncAttributeMaxDynamicSharedMemorySize, SMEM_G);
    cudaFuncSetAttribute(attn_k, cudaFuncAttributeMaxDynamicSharedMemorySize, SMEM_ATTN);

    round_x_k<<<(MTOK * HIDD) / 256, 256>>>(x);
    build_weff_k<<<dim3((HD * HIDD) / 256, 3), 256>>>(Wq, Wk, Wv, aq, ak, av);
    build_woeff_k<<<(HIDD * HD) / 256, 256>>>(Wo, cl);

    // projections + head mixing (q/k/v via z)
    gemmA_k<<<dim3(NPROJ / 128, MTOK / 128, 3), 256, SMEM_G>>>();

    // causal SDPA over virtual positions
    attn_k<<<dim3(SVLEN / 128, NB * NH), 256, SMEM_ATTN>>>();

    // collapse + output projection
    gemmO_k<<<dim3(HIDD / 128, MTOK / 128), 256, SMEM_G>>>(out);
}

// round 10
// speedup vs baseline: 5.1916x; 1.1064x over previous
#include <cuda_runtime.h>
#include <cuda_fp16.h>
#include <cstdint>

// ---------------------------------------------------------------------------
// InterleavedHeadAttention — round 8: fp16 m16n8k16, restructured pipelines.
//   - GEMMs: 3-stage cp.async, ONE __syncthreads per k-chunk, issue overlaps
//     compute of two chunks.
//   - attention: P kept in registers (S-fragment == PV A-fragment), 3-buffer
//     KV ring, one barrier per kv-tile. V transposed natural-kv.
//   B=2, S=1024, HID=1024, H=16, P=2, D=64, sv=2048
// ---------------------------------------------------------------------------

#define NB 2
#define SEQ 1024
#define HIDD 1024
#define NH 16
#define NP 2
#define HD 64
#define SVLEN (SEQ * NP)        // 2048
#define MTOK (NB * SEQ)         // 2048
#define NPROJ (NH * NP * HD)    // 2048
#define ATTN_SCALE 0.125f

#define NEG_INF __int_as_float(0xff800000)

// fp16 storage; Q/K/Xr/Weff/Woeff/Aout are k-permuted (perm16), Vt natural
__device__ __half g_Weff[3][NPROJ][HIDD];    // e-perm16
__device__ __half g_Woeff[HIDD][NPROJ];      // (o,d): d-perm16
__device__ __half g_Xr[MTOK][HIDD];          // e-perm16
__device__ __half g_Q[NB * NH][SVLEN][HD];   // d-perm16
__device__ __half g_K[NB * NH][SVLEN][HD];   // d-perm16
__device__ __half g_Vt[NB * NH][HD][SVLEN];  // transposed, natural kv
__device__ __half g_Aout[NB * NH][SVLEN][HD];// d-perm16

// ---------------------------------------------------------------------------
// helpers
// ---------------------------------------------------------------------------
__device__ __forceinline__ int perm16(int c) {       // full element perm
    int u = c & 15, q = u >> 1, b = u & 1;
    return (c & ~15) + 4 * (q & 3) + 2 * (q >> 2) + b;
}
__device__ __forceinline__ int perm16p(int c) {      // even c: pair start pos
    int q = (c & 15) >> 1;
    return (c & ~15) + 4 * (q & 3) + 2 * (q >> 2);
}
__device__ __forceinline__ void cp16(uint32_t s, const void* g) {
    asm volatile("cp.async.cg.shared.global [%0], [%1], 16;" :: "r"(s), "l"(g));
}
__device__ __forceinline__ uint32_t smem_u32(const void* p) {
    uint32_t a;
    asm("{ .reg .u64 t; cvta.to.shared.u64 t, %1; cvt.u32.u64 %0, t; }"
        : "=r"(a) : "l"(p));
    return a;
}
#define CP_COMMIT() asm volatile("cp.async.commit_group;" ::: "memory")
#define CP_WAIT(n)  asm volatile("cp.async.wait_group %0;" :: "n"(n) : "memory")

__device__ __forceinline__ void st_h2(__half* p, float a, float b) {
    *(__half2*)p = __float22half2_rn(make_float2(a, b));
}
__device__ __forceinline__ uint32_t pack_h2(float a, float b) {
    __half2 h = __float22half2_rn(make_float2(a, b));
    return *(uint32_t*)&h;
}
// D(16x8) += A(16x16) * B(16x8), f16 in, f32 accum
__device__ __forceinline__ void mma_f16(float* c, const uint32_t* a,
                                        const uint32_t* b) {
    asm volatile(
        "mma.sync.aligned.m16n8k16.row.col.f32.f16.f16.f32 "
        "{%0,%1,%2,%3}, {%4,%5,%6,%7}, {%8,%9}, {%0,%1,%2,%3};"
        : "+f"(c[0]), "+f"(c[1]), "+f"(c[2]), "+f"(c[3])
        : "r"(a[0]), "r"(a[1]), "r"(a[2]), "r"(a[3]), "r"(b[0]), "r"(b[1]));
}

// ---------------------------------------------------------------------------
// producers
// ---------------------------------------------------------------------------
__global__ __launch_bounds__(256) void round_x_k(const float* __restrict__ x)
{
    int idx = blockIdx.x * 256 + threadIdx.x;
    int r = idx >> 10, e = idx & 1023;
    g_Xr[r][perm16(e)] = __float2half_rn(x[idx]);
}

__global__ __launch_bounds__(256) void build_weff_k(
    const float* __restrict__ Wq, const float* __restrict__ Wk,
    const float* __restrict__ Wv,
    const float* __restrict__ aq, const float* __restrict__ ak,
    const float* __restrict__ av)
{
    int w = blockIdx.y;
    const float* W = (w == 0) ? Wq : (w == 1) ? Wk : Wv;
    const float* A = (w == 0) ? aq : (w == 1) ? ak : av;
    __shared__ float sA[NH * 32];
    int tid = threadIdx.x;
    sA[tid] = A[tid];
    sA[tid + 256] = A[tid + 256];
    __syncthreads();

    int idx = blockIdx.x * 256 + tid;       // over 64*1024
    int d = idx >> 10, e = idx & 1023;
    int ep = perm16(e);
    float wv[NH];
#pragma unroll
    for (int m = 0; m < NH; m++)
        wv[m] = W[(m * HD + d) * HIDD + e];
    float scale = (w == 0) ? ATTN_SCALE : 1.0f;
#pragma unroll
    for (int hp = 0; hp < 32; hp++) {
        float acc = 0.f;
#pragma unroll
        for (int m = 0; m < NH; m++)
            acc += sA[m * 32 + hp] * wv[m];
        g_Weff[w][hp * HD + d][ep] = __float2half_rn(acc * scale);
    }
}

__global__ __launch_bounds__(256) void build_woeff_k(
    const float* __restrict__ Wo, const float* __restrict__ cl)
{
    __shared__ float sC[NH * 32];
    int tid = threadIdx.x;
    sC[tid] = cl[tid];
    sC[tid + 256] = cl[tid + 256];
    __syncthreads();

    int idx = blockIdx.x * 256 + tid;       // over 1024*64
    int f = idx >> 6, d = idx & 63;
    int dp = perm16(d);
    float wv[NH];
#pragma unroll
    for (int h = 0; h < NH; h++)
        wv[h] = Wo[f * HIDD + h * HD + d];
#pragma unroll
    for (int o = 0; o < 32; o++) {
        float acc = 0.f;
#pragma unroll
        for (int h = 0; h < NH; h++)
            acc += sC[h * 32 + o] * wv[h];
        g_Woeff[f][o * HD + dp] = __float2half_rn(acc);
    }
}

// ---------------------------------------------------------------------------
// Projection GEMM (fp16): C[2048,2048] = Xr * Weff[z]^T, K=1024.
//   CTA 128x128, 8 warps (4M x 2N), warp 32x64, KC=64, 3-stage pipeline,
//   ONE barrier per chunk. LDH=72 halves.
// ---------------------------------------------------------------------------
#define LDH 72
#define G_TILEH (128 * LDH)              // halves per tile
#define G_STGH (2 * G_TILEH)
#define NSTG 3
#define SMEM_G (NSTG * G_STGH * 2)       // bytes (108 KB)

__global__ __launch_bounds__(256, 2) void gemmA_k()
{
    extern __shared__ __align__(16) __half smh[];
    const int tid = threadIdx.x, wid = tid >> 5, lane = tid & 31;
    const int wm = (wid & 3) * 32;
    const int wn = (wid >> 2) * 64;
    const int bn = blockIdx.x * 128, bm = blockIdx.y * 128;
    const int which = blockIdx.z;
    const __half* Aw = &g_Xr[0][0];
    const __half* Bw = &g_Weff[which][0][0];
    const uint32_t sb = smem_u32(smh);
    const int fr = lane >> 2, fc = lane & 3;
    const int lrow = tid >> 1;
    const int lhh = (tid & 1) * 32;      // halves

    auto issue = [&](int kc) {
        int s = kc % NSTG;
        int k0 = kc * 64;
        uint32_t sa = sb + (uint32_t)(s * G_STGH) * 2;
        uint32_t sbB = sa + G_TILEH * 2;
        uint32_t soff = (uint32_t)lrow * (LDH * 2) + lhh * 2;
        const __half* asrc = Aw + (size_t)(bm + lrow) * HIDD + k0 + lhh;
#pragma unroll
        for (int c = 0; c < 4; c++)
            cp16(sa + soff + c * 16, asrc + c * 8);
        const __half* bsrc = Bw + (size_t)(bn + lrow) * HIDD + k0 + lhh;
#pragma unroll
        for (int c = 0; c < 4; c++)
            cp16(sbB + soff + c * 16, bsrc + c * 8);
    };

    float acc[2][8][4];
#pragma unroll
    for (int mt = 0; mt < 2; mt++)
#pragma unroll
        for (int nt = 0; nt < 8; nt++)
#pragma unroll
            for (int j = 0; j < 4; j++) acc[mt][nt][j] = 0.f;

    issue(0); CP_COMMIT();
    issue(1); CP_COMMIT();

    const int NKC = HIDD / 64;
    for (int kc = 0; kc < NKC; kc++) {
        CP_WAIT(1);           // chunk kc complete (mine)
        __syncthreads();      // everyone's complete+visible; all done with kc-1
        if (kc + 2 < NKC) issue(kc + 2);
        CP_COMMIT();          // uniform group count
        const __half* As = smh + (kc % NSTG) * G_STGH;
        const __half* Bs = As + G_TILEH;
#pragma unroll
        for (int k16 = 0; k16 < 4; k16++) {
            int kb = k16 * 16;
            uint32_t afr[2][4], bfr[8][2];
#pragma unroll
            for (int mt = 0; mt < 2; mt++) {
                uint2 a0 = *(const uint2*)(As + (wm + mt * 16 + fr) * LDH + kb + 4 * fc);
                uint2 a1 = *(const uint2*)(As + (wm + mt * 16 + fr + 8) * LDH + kb + 4 * fc);
                afr[mt][0] = a0.x; afr[mt][1] = a1.x;
                afr[mt][2] = a0.y; afr[mt][3] = a1.y;
            }
#pragma unroll
            for (int nt = 0; nt < 8; nt++) {
                uint2 b = *(const uint2*)(Bs + (wn + nt * 8 + fr) * LDH + kb + 4 * fc);
                bfr[nt][0] = b.x; bfr[nt][1] = b.y;
            }
#pragma unroll
            for (int mt = 0; mt < 2; mt++)
#pragma unroll
                for (int nt = 0; nt < 8; nt++)
                    mma_f16(acc[mt][nt], afr[mt], bfr[nt]);
        }
    }

    // ---- epilogue ----
    if (which == 2) {
        // V: store transposed natural kv into g_Vt[bh][d][kv]
        int h = bn >> 7, p = (wn >> 6) & 1;
#pragma unroll
        for (int mt = 0; mt < 2; mt++) {
#pragma unroll
            for (int half_ = 0; half_ < 2; half_++) {
                int row = bm + wm + mt * 16 + fr + half_ * 8;
                int b = row >> 10, n = row & 1023;
                int kv = n * NP + p;
                __half* Vt = &g_Vt[b * NH + h][0][0];
#pragma unroll
                for (int nt = 0; nt < 8; nt++) {
                    int d = nt * 8 + 2 * fc;          // local 0..63
                    Vt[(size_t)d * SVLEN + kv] =
                        __float2half_rn(acc[mt][nt][half_ * 2 + 0]);
                    Vt[(size_t)(d + 1) * SVLEN + kv] =
                        __float2half_rn(acc[mt][nt][half_ * 2 + 1]);
                }
            }
        }
    } else {
        __half* dst0 = (which == 0) ? &g_Q[0][0][0] : &g_K[0][0][0];
#pragma unroll
        for (int mt = 0; mt < 2; mt++) {
#pragma unroll
            for (int half_ = 0; half_ < 2; half_++) {
                int row = bm + wm + mt * 16 + fr + half_ * 8;
                int b = row >> 10, n = row & 1023;
#pragma unroll
                for (int nt = 0; nt < 8; nt++) {
                    int col = bn + wn + nt * 8 + 2 * fc;
                    int h = col >> 7, p = (col >> 6) & 1;
                    int pos = perm16p(col & 63);
                    __half* dst = dst0 +
                        ((size_t)(b * NH + h) * SVLEN + n * NP + p) * HD + pos;
                    st_h2(dst, acc[mt][nt][half_ * 2 + 0],
                               acc[mt][nt][half_ * 2 + 1]);
                }
            }
        }
    }
}

// ---------------------------------------------------------------------------
// Output GEMM (fp16): out[2048,1024] = gather(g_Aout) * Woeff^T, K=2048.
//   Same 3-stage, one-barrier structure.
// ---------------------------------------------------------------------------
__global__ __launch_bounds__(256, 2) void gemmO_k(float* __restrict__ Cout)
{
    extern __shared__ __align__(16) __half smh[];
    const int tid = threadIdx.x, wid = tid >> 5, lane = tid & 31;
    const int wm = (wid & 3) * 32;
    const int wn = (wid >> 2) * 64;
    const int bn = blockIdx.x * 128, bm = blockIdx.y * 128;
    const __half* Bw = &g_Woeff[0][0];
    const uint32_t sb = smem_u32(smh);
    const int fr = lane >> 2, fc = lane & 3;
    const int lrow = tid >> 1;
    const int lhh = (tid & 1) * 32;

    int t = bm + lrow;
    int gb = t >> 10, gn = t & 1023;

    auto issue = [&](int kc) {
        int s = kc % NSTG;
        int k0 = kc * 64;
        uint32_t sa = sb + (uint32_t)(s * G_STGH) * 2;
        uint32_t sbB = sa + G_TILEH * 2;
        uint32_t soff = (uint32_t)lrow * (LDH * 2) + lhh * 2;
#pragma unroll
        for (int c = 0; c < 4; c++) {
            int col = k0 + lhh + c * 8;            // storage position
            int o = col >> 6, dd = col & 63;
            cp16(sa + soff + c * 16,
                 &g_Aout[gb * NH + (o >> 1)][gn * NP + (o & 1)][dd]);
        }
        const __half* bsrc = Bw + (size_t)(bn + lrow) * NPROJ + k0 + lhh;
#pragma unroll
        for (int c = 0; c < 4; c++)
            cp16(sbB + soff + c * 16, bsrc + c * 8);
    };

    float acc[2][8][4];
#pragma unroll
    for (int mt = 0; mt < 2; mt++)
#pragma unroll
        for (int nt = 0; nt < 8; nt++)
#pragma unroll
            for (int j = 0; j < 4; j++) acc[mt][nt][j] = 0.f;

    issue(0); CP_COMMIT();
    issue(1); CP_COMMIT();

    const int NKC = NPROJ / 64;
    for (int kc = 0; kc < NKC; kc++) {
        CP_WAIT(1);
        __syncthreads();
        if (kc + 2 < NKC) issue(kc + 2);
        CP_COMMIT();
        const __half* As = smh + (kc % NSTG) * G_STGH;
        const __half* Bs = As + G_TILEH;
#pragma unroll
        for (int k16 = 0; k16 < 4; k16++) {
            int kb = k16 * 16;
            uint32_t afr[2][4], bfr[8][2];
#pragma unroll
            for (int mt = 0; mt < 2; mt++) {
                uint2 a0 = *(const uint2*)(As + (wm + mt * 16 + fr) * LDH + kb + 4 * fc);
                uint2 a1 = *(const uint2*)(As + (wm + mt * 16 + fr + 8) * LDH + kb + 4 * fc);
                afr[mt][0] = a0.x; afr[mt][1] = a1.x;
                afr[mt][2] = a0.y; afr[mt][3] = a1.y;
            }
#pragma unroll
            for (int nt = 0; nt < 8; nt++) {
                uint2 b = *(const uint2*)(Bs + (wn + nt * 8 + fr) * LDH + kb + 4 * fc);
                bfr[nt][0] = b.x; bfr[nt][1] = b.y;
            }
#pragma unroll
            for (int mt = 0; mt < 2; mt++)
#pragma unroll
                for (int nt = 0; nt < 8; nt++)
                    mma_f16(acc[mt][nt], afr[mt], bfr[nt]);
        }
    }

#pragma unroll
    for (int mt = 0; mt < 2; mt++) {
#pragma unroll
        for (int half_ = 0; half_ < 2; half_++) {
            int row = bm + wm + mt * 16 + fr + half_ * 8;
#pragma unroll
            for (int nt = 0; nt < 8; nt++) {
                int col = bn + wn + nt * 8 + 2 * fc;
                *(float2*)(Cout + (size_t)row * HIDD + col) = make_float2(
                    acc[mt][nt][half_ * 2 + 0], acc[mt][nt][half_ * 2 + 1]);
            }
        }
    }
}

// ---------------------------------------------------------------------------
// Causal flash attention (fp16 MMA): q-tile 128 (warp 16 rows), k-tile 64,
//   3-buffer KV ring, one barrier per tile, P in registers.
// ---------------------------------------------------------------------------
#define QLD 72
#define Q_H (128 * QLD)
#define KV_H (64 * QLD)                   // per K or V tile
#define SMEM_ATTN ((Q_H + 6 * KV_H) * 2)  // 73,728 B

__global__ __launch_bounds__(256, 2) void attn_k()
{
    extern __shared__ __align__(16) __half smA[];
    __half* Qs = smA;                     // [128][QLD] (d-perm16)
    __half* KVs = Qs + Q_H;               // 3 x (Ks[64][QLD], Vts[64][QLD])
    const uint32_t sQ = smem_u32(Qs);
    const uint32_t sKV = smem_u32(KVs);

    const int bh = blockIdx.y;
    const int qt = (gridDim.x - 1) - blockIdx.x;   // heavy tiles first
    const int qstart = qt * 128;
    const __half* Qg = &g_Q[bh][0][0];
    const __half* Kg = &g_K[bh][0][0];
    const __half* Vtg = &g_Vt[bh][0][0];

    const int tid = threadIdx.x;
    const int wq = tid >> 5;
    const int lane = tid & 31;
    const int fr = lane >> 2;
    const int fc = lane & 3;
    const int r0 = wq * 16 + fr, r1 = r0 + 8;

    auto issue_kv = [&](int jt) {
        int buf = jt % 3;
        uint32_t sK = sKV + (uint32_t)(buf * 2 * KV_H) * 2;
        uint32_t sV = sK + KV_H * 2;
        int kstart = jt * 64;
#pragma unroll
        for (int it = 0; it < 2; it++) {
            int chunk = tid + 256 * it;
            int row = chunk >> 3;
            int c = chunk & 7;
            cp16(sK + (uint32_t)row * (QLD * 2) + c * 16,
                 Kg + (size_t)(kstart + row) * HD + c * 8);
            cp16(sV + (uint32_t)row * (QLD * 2) + c * 16,
                 Vtg + (size_t)row * SVLEN + kstart + c * 8);
        }
    };

    // prologue: Q + kv0 in group0, kv1 in group1
#pragma unroll
    for (int it = 0; it < 4; it++) {
        int chunk = tid + 256 * it;
        int row = chunk >> 3;
        int c = chunk & 7;
        cp16(sQ + (uint32_t)row * (QLD * 2) + c * 16,
             Qg + (size_t)(qstart + row) * HD + c * 8);
    }
    issue_kv(0); CP_COMMIT();
    issue_kv(1); CP_COMMIT();

    float O[8][4];
    float m0 = NEG_INF, m1 = NEG_INF, l0 = 0.f, l1 = 0.f;
#pragma unroll
    for (int nt = 0; nt < 8; nt++)
#pragma unroll
        for (int j = 0; j < 4; j++) O[nt][j] = 0.f;

    const int jmax = 2 * qt + 1;
    for (int jt = 0; jt <= jmax; jt++) {
        const int kstart = jt * 64;
        CP_WAIT(1);           // tile jt (and Q at jt=0) complete
        __syncthreads();      // visible to all; all warps done with jt-1
        if (jt + 2 <= jmax) issue_kv(jt + 2);
        CP_COMMIT();
        const __half* Ks = KVs + (jt % 3) * 2 * KV_H;
        const __half* Vts = Ks + KV_H;

        // ---- S = Q K^T (both d-perm16, contraction invariant) ----
        float s[8][4];
#pragma unroll
        for (int nt = 0; nt < 8; nt++)
#pragma unroll
            for (int j = 0; j < 4; j++) s[nt][j] = 0.f;
#pragma unroll
        for (int k16 = 0; k16 < 4; k16++) {
            int kb = k16 * 16;
            uint32_t afr[4], bfr[8][2];
            uint2 a0 = *(const uint2*)(Qs + r0 * QLD + kb + 4 * fc);
            uint2 a1 = *(const uint2*)(Qs + r1 * QLD + kb + 4 * fc);
            afr[0] = a0.x; afr[1] = a1.x; afr[2] = a0.y; afr[3] = a1.y;
#pragma unroll
            for (int nt = 0; nt < 8; nt++) {
                uint2 b = *(const uint2*)(Ks + (nt * 8 + fr) * QLD + kb + 4 * fc);
                bfr[nt][0] = b.x; bfr[nt][1] = b.y;
            }
#pragma unroll
            for (int nt = 0; nt < 8; nt++)
                mma_f16(s[nt], afr, bfr[nt]);
        }

        // causal mask
        if (kstart + 63 > qstart + wq * 16) {
            int gr0 = qstart + r0, gr1 = gr0 + 8;
#pragma unroll
            for (int nt = 0; nt < 8; nt++) {
                int c0 = kstart + nt * 8 + 2 * fc;
                if (c0 > gr0)     s[nt][0] = NEG_INF;
                if (c0 + 1 > gr0) s[nt][1] = NEG_INF;
                if (c0 > gr1)     s[nt][2] = NEG_INF;
                if (c0 + 1 > gr1) s[nt][3] = NEG_INF;
            }
        }

        // ---- online softmax; P packed straight into MMA A-fragments ----
        float mx0 = NEG_INF, mx1 = NEG_INF;
#pragma unroll
        for (int nt = 0; nt < 8; nt++) {
            mx0 = fmaxf(mx0, fmaxf(s[nt][0], s[nt][1]));
            mx1 = fmaxf(mx1, fmaxf(s[nt][2], s[nt][3]));
        }
        mx0 = fmaxf(mx0, __shfl_xor_sync(0xffffffffu, mx0, 1));
        mx0 = fmaxf(mx0, __shfl_xor_sync(0xffffffffu, mx0, 2));
        mx1 = fmaxf(mx1, __shfl_xor_sync(0xffffffffu, mx1, 1));
        mx1 = fmaxf(mx1, __shfl_xor_sync(0xffffffffu, mx1, 2));
        float newm0 = fmaxf(m0, mx0), newm1 = fmaxf(m1, mx1);
        float al0 = __expf(m0 - newm0), al1 = __expf(m1 - newm1);

        uint32_t pfr[4][4];           // [k16][4 regs] PV A-fragments
        float rs0 = 0.f, rs1 = 0.f;
#pragma unroll
        for (int nt = 0; nt < 8; nt++) {
            float p0 = __expf(s[nt][0] - newm0);
            float p1 = __expf(s[nt][1] - newm0);
            float p2 = __expf(s[nt][2] - newm1);
            float p3 = __expf(s[nt][3] - newm1);
            rs0 += p0 + p1; rs1 += p2 + p3;
            int t16 = nt >> 1, hi = nt & 1;
            pfr[t16][hi * 2 + 0] = pack_h2(p0, p1);   // row r0
            pfr[t16][hi * 2 + 1] = pack_h2(p2, p3);   // row r1
        }
        rs0 += __shfl_xor_sync(0xffffffffu, rs0, 1);
        rs0 += __shfl_xor_sync(0xffffffffu, rs0, 2);
        rs1 += __shfl_xor_sync(0xffffffffu, rs1, 1);
        rs1 += __shfl_xor_sync(0xffffffffu, rs1, 2);
        l0 = l0 * al0 + rs0; l1 = l1 * al1 + rs1;
        m0 = newm0; m1 = newm1;
#pragma unroll
        for (int nt = 0; nt < 8; nt++) {
            O[nt][0] *= al0; O[nt][1] *= al0;
            O[nt][2] *= al1; O[nt][3] *= al1;
        }

        // ---- O += P V (A in regs; B from Vts natural kv, 2x LDS.32) ----
#pragma unroll
        for (int k16 = 0; k16 < 4; k16++) {
            int kb = k16 * 16;
            uint32_t bfr[8][2];
#pragma unroll
            for (int nt = 0; nt < 8; nt++) {
                const __half* bp = Vts + (nt * 8 + fr) * QLD + kb + 2 * fc;
                bfr[nt][0] = *(const uint32_t*)(bp);
                bfr[nt][1] = *(const uint32_t*)(bp + 8);
            }
#pragma unroll
            for (int nt = 0; nt < 8; nt++)
                mma_f16(O[nt], pfr[k16], bfr[nt]);
        }
        // no trailing barrier: next iteration's top barrier protects buffers
    }

    // epilogue: normalize, store d-permuted fp16 into g_Aout
    __half* Ag = &g_Aout[bh][0][0];
    float inv0 = 1.f / l0, inv1 = 1.f / l1;
#pragma unroll
    for (int nt = 0; nt < 8; nt++) {
        int pos = perm16p(nt * 8 + 2 * fc);
        st_h2(Ag + (size_t)(qstart + r0) * HD + pos,
              O[nt][0] * inv0, O[nt][1] * inv0);
        st_h2(Ag + (size_t)(qstart + r1) * HD + pos,
              O[nt][2] * inv1, O[nt][3] * inv1);
    }
}

// ---------------------------------------------------------------------------
// launch
// ---------------------------------------------------------------------------
extern "C" void kernel_launch(void* const* d_in, const int* in_sizes, int n_in,
                              void* d_out, int out_size)
{
    const float* x  = (const float*)d_in[0];
    const float* Wq = (const float*)d_in[1];
    const float* Wk = (const float*)d_in[2];
    const float* Wv = (const float*)d_in[3];
    const float* Wo = (const float*)d_in[4];
    const float* aq = (const float*)d_in[5];
    const float* ak = (const float*)d_in[6];
    const float* av = (const float*)d_in[7];
    const float* cl = (const float*)d_in[8];
    float* out = (float*)d_out;

    cudaFuncSetAttribute(gemmA_k, cudaFuncAttributeMaxDynamicSharedMemorySize, SMEM_G);
    cudaFuncSetAttribute(gemmO_k, cudaFuncAttributeMaxDynamicSharedMemorySize, SMEM_G);
    cudaFuncSetAttribute(attn_k, cudaFuncAttributeMaxDynamicSharedMemorySize, SMEM_ATTN);

    round_x_k<<<(MTOK * HIDD) / 256, 256>>>(x);
    build_weff_k<<<dim3((HD * HIDD) / 256, 3), 256>>>(Wq, Wk, Wv, aq, ak, av);
    build_woeff_k<<<(HIDD * HD) / 256, 256>>>(Wo, cl);

    // projections + head mixing (q/k/v via z)
    gemmA_k<<<dim3(NPROJ / 128, MTOK / 128, 3), 256, SMEM_G>>>();

    // causal SDPA over virtual positions
    attn_k<<<dim3(SVLEN / 128, NB * NH), 256, SMEM_ATTN>>>();

    // collapse + output projection
    gemmO_k<<<dim3(HIDD / 128, MTOK / 128), 256, SMEM_G>>>(out);
}

// round 11
// speedup vs baseline: 7.1386x; 1.3750x over previous
#include <cuda_runtime.h>
#include <cuda_fp16.h>
#include <cstdint>

// ---------------------------------------------------------------------------
// InterleavedHeadAttention — round 11: fp16 m16n8k16 + ldmatrix everywhere.
//   - natural layouts + XOR-swizzled smem (chunk ^ (row&7)), LDSM.x4 loads
//   - gemms: 3-stage cp.async, one barrier per chunk
//   - attention: Q fragments preloaded to registers; P in registers;
//     3-buffer KV ring
//   B=2, S=1024, HID=1024, H=16, P=2, D=64, sv=2048
// ---------------------------------------------------------------------------

#define NB 2
#define SEQ 1024
#define HIDD 1024
#define NH 16
#define NP 2
#define HD 64
#define SVLEN (SEQ * NP)        // 2048
#define MTOK (NB * SEQ)         // 2048
#define NPROJ (NH * NP * HD)    // 2048
#define ATTN_SCALE 0.125f

#define NEG_INF __int_as_float(0xff800000)

// fp16 storage, all natural layouts
__device__ __half g_Weff[3][NPROJ][HIDD];
__device__ __half g_Woeff[HIDD][NPROJ];      // [f][o*64+d]
__device__ __half g_Xr[MTOK][HIDD];
__device__ __half g_Q[NB * NH][SVLEN][HD];
__device__ __half g_K[NB * NH][SVLEN][HD];
__device__ __half g_Vt[NB * NH][HD][SVLEN];  // transposed
__device__ __half g_Aout[NB * NH][SVLEN][HD];

// ---------------------------------------------------------------------------
// helpers
// ---------------------------------------------------------------------------
__device__ __forceinline__ void cp16(uint32_t s, const void* g) {
    asm volatile("cp.async.cg.shared.global [%0], [%1], 16;" :: "r"(s), "l"(g));
}
__device__ __forceinline__ uint32_t smem_u32(const void* p) {
    uint32_t a;
    asm("{ .reg .u64 t; cvta.to.shared.u64 t, %1; cvt.u32.u64 %0, t; }"
        : "=r"(a) : "l"(p));
    return a;
}
#define CP_COMMIT() asm volatile("cp.async.commit_group;" ::: "memory")
#define CP_WAIT(n)  asm volatile("cp.async.wait_group %0;" :: "n"(n) : "memory")

__device__ __forceinline__ void st_h2(__half* p, float a, float b) {
    *(__half2*)p = __float22half2_rn(make_float2(a, b));
}
__device__ __forceinline__ uint32_t pack_h2(float a, float b) {
    __half2 h = __float22half2_rn(make_float2(a, b));
    return *(uint32_t*)&h;
}
// D(16x8) += A(16x16) * B(16x8), f16 in, f32 accum
__device__ __forceinline__ void mma_f16(float* c, const uint32_t* a,
                                        const uint32_t* b) {
    asm volatile(
        "mma.sync.aligned.m16n8k16.row.col.f32.f16.f16.f32 "
        "{%0,%1,%2,%3}, {%4,%5,%6,%7}, {%8,%9}, {%0,%1,%2,%3};"
        : "+f"(c[0]), "+f"(c[1]), "+f"(c[2]), "+f"(c[3])
        : "r"(a[0]), "r"(a[1]), "r"(a[2]), "r"(a[3]), "r"(b[0]), "r"(b[1]));
}
__device__ __forceinline__ void ldsm_x4(uint32_t& r0, uint32_t& r1,
                                        uint32_t& r2, uint32_t& r3, uint32_t a) {
    asm volatile("ldmatrix.sync.aligned.m8n8.x4.shared.b16 {%0,%1,%2,%3}, [%4];"
                 : "=r"(r0), "=r"(r1), "=r"(r2), "=r"(r3) : "r"(a));
}

// ---------------------------------------------------------------------------
// producers (natural layouts)
// ---------------------------------------------------------------------------
__global__ __launch_bounds__(256) void round_x_k(const float* __restrict__ x)
{
    int idx = blockIdx.x * 256 + threadIdx.x;
    (&g_Xr[0][0])[idx] = __float2half_rn(x[idx]);
}

__global__ __launch_bounds__(256) void build_weff_k(
    const float* __restrict__ Wq, const float* __restrict__ Wk,
    const float* __restrict__ Wv,
    const float* __restrict__ aq, const float* __restrict__ ak,
    const float* __restrict__ av)
{
    int w = blockIdx.y;
    const float* W = (w == 0) ? Wq : (w == 1) ? Wk : Wv;
    const float* A = (w == 0) ? aq : (w == 1) ? ak : av;
    __shared__ float sA[NH * 32];
    int tid = threadIdx.x;
    sA[tid] = A[tid];
    sA[tid + 256] = A[tid + 256];
    __syncthreads();

    int idx = blockIdx.x * 256 + tid;       // over 64*1024
    int d = idx >> 10, e = idx & 1023;
    float wv[NH];
#pragma unroll
    for (int m = 0; m < NH; m++)
        wv[m] = W[(m * HD + d) * HIDD + e];
    float scale = (w == 0) ? ATTN_SCALE : 1.0f;
#pragma unroll
    for (int hp = 0; hp < 32; hp++) {
        float acc = 0.f;
#pragma unroll
        for (int m = 0; m < NH; m++)
            acc += sA[m * 32 + hp] * wv[m];
        g_Weff[w][hp * HD + d][e] = __float2half_rn(acc * scale);
    }
}

__global__ __launch_bounds__(256) void build_woeff_k(
    const float* __restrict__ Wo, const float* __restrict__ cl)
{
    __shared__ float sC[NH * 32];
    int tid = threadIdx.x;
    sC[tid] = cl[tid];
    sC[tid + 256] = cl[tid + 256];
    __syncthreads();

    int idx = blockIdx.x * 256 + tid;       // over 1024*64
    int f = idx >> 6, d = idx & 63;
    float wv[NH];
#pragma unroll
    for (int h = 0; h < NH; h++)
        wv[h] = Wo[f * HIDD + h * HD + d];
#pragma unroll
    for (int o = 0; o < 32; o++) {
        float acc = 0.f;
#pragma unroll
        for (int h = 0; h < NH; h++)
            acc += sC[h * 32 + o] * wv[h];
        g_Woeff[f][o * HD + d] = __float2half_rn(acc);
    }
}

// ---------------------------------------------------------------------------
// GEMM tiles: 128 rows x 64 halves (128B rows), XOR chunk swizzle.
//   sw(row, chunk) = row*128 + ((chunk ^ (row&7))<<4)
// ---------------------------------------------------------------------------
#define G_TILEB 16384                    // bytes per operand tile
#define G_STGB (2 * G_TILEB)
#define NSTG 3
#define SMEM_G (NSTG * G_STGB)           // 96 KB

// ---------------------------------------------------------------------------
// Projection GEMM (fp16): C[2048,2048] = Xr * Weff[z]^T, K=1024.
//   CTA 128x128, 8 warps (4M x 2N), warp 32x64, KC=64, LDSM fragments.
// ---------------------------------------------------------------------------
__global__ __launch_bounds__(256, 2) void gemmA_k()
{
    extern __shared__ __align__(16) char smc[];
    const int tid = threadIdx.x, wid = tid >> 5, lane = tid & 31;
    const int wm = (wid & 3) * 32;
    const int wn = (wid >> 2) * 64;
    const int bn = blockIdx.x * 128, bm = blockIdx.y * 128;
    const int which = blockIdx.z;
    const __half* Aw = &g_Xr[0][0];
    const __half* Bw = &g_Weff[which][0][0];
    const uint32_t sb = smem_u32(smc);
    const int fr = lane >> 2, fc = lane & 3;
    const int lrow = tid >> 1;
    const int cb = (tid & 1) * 4;        // chunk base for loads

    // LDSM lane geometry
    const int li = lane & 7;
    const int g8 = (lane >> 3) & 1, g16 = lane >> 4;
    // A: rows wm + mt*16 + g8*8 + li, khalf = g16
    uint32_t rowOffA[2]; int rmA[2];
#pragma unroll
    for (int mt = 0; mt < 2; mt++) {
        int r = wm + mt * 16 + g8 * 8 + li;
        rowOffA[mt] = (uint32_t)r * 128; rmA[mt] = r & 7;
    }
    // B: rows wn + j*16 + g16*8 + li, khalf = g8
    uint32_t rowOffB[4]; int rmB[4];
#pragma unroll
    for (int j = 0; j < 4; j++) {
        int r = wn + j * 16 + g16 * 8 + li;
        rowOffB[j] = (uint32_t)r * 128; rmB[j] = r & 7;
    }

    auto issue = [&](int kc) {
        int s = kc % NSTG;
        int k0 = kc * 64;
        uint32_t sa = sb + (uint32_t)s * G_STGB;
        uint32_t sbB = sa + G_TILEB;
        uint32_t dstrow = (uint32_t)lrow * 128;
        int swm = lrow & 7;
        const __half* asrc = Aw + (size_t)(bm + lrow) * HIDD + k0;
        const __half* bsrc = Bw + (size_t)(bn + lrow) * HIDD + k0;
#pragma unroll
        for (int c = 0; c < 4; c++) {
            int cc = cb + c;
            uint32_t off = dstrow + (uint32_t)((cc ^ swm) << 4);
            cp16(sa + off, asrc + cc * 8);
            cp16(sbB + off, bsrc + cc * 8);
        }
    };

    float acc[2][8][4];
#pragma unroll
    for (int mt = 0; mt < 2; mt++)
#pragma unroll
        for (int nt = 0; nt < 8; nt++)
#pragma unroll
            for (int j = 0; j < 4; j++) acc[mt][nt][j] = 0.f;

    issue(0); CP_COMMIT();
    issue(1); CP_COMMIT();

    const int NKC = HIDD / 64;
    for (int kc = 0; kc < NKC; kc++) {
        CP_WAIT(1);
        __syncthreads();
        if (kc + 2 < NKC) issue(kc + 2);
        CP_COMMIT();
        uint32_t Ab = sb + (uint32_t)(kc % NSTG) * G_STGB;
        uint32_t Bb = Ab + G_TILEB;
#pragma unroll
        for (int k16 = 0; k16 < 4; k16++) {
            uint32_t afr[2][4], bfr[8][2];
#pragma unroll
            for (int mt = 0; mt < 2; mt++) {
                uint32_t a = Ab + rowOffA[mt] +
                    (uint32_t)((((2 * k16) + g16) ^ rmA[mt]) << 4);
                ldsm_x4(afr[mt][0], afr[mt][1], afr[mt][2], afr[mt][3], a);
            }
#pragma unroll
            for (int j = 0; j < 4; j++) {
                uint32_t a = Bb + rowOffB[j] +
                    (uint32_t)((((2 * k16) + g8) ^ rmB[j]) << 4);
                ldsm_x4(bfr[2 * j][0], bfr[2 * j][1],
                        bfr[2 * j + 1][0], bfr[2 * j + 1][1], a);
            }
#pragma unroll
            for (int mt = 0; mt < 2; mt++)
#pragma unroll
                for (int nt = 0; nt < 8; nt++)
                    mma_f16(acc[mt][nt], afr[mt], bfr[nt]);
        }
    }

    // ---- epilogue (natural layouts) ----
    if (which == 2) {
        int h = bn >> 7, p = (wn >> 6) & 1;
#pragma unroll
        for (int mt = 0; mt < 2; mt++) {
#pragma unroll
            for (int half_ = 0; half_ < 2; half_++) {
                int row = bm + wm + mt * 16 + fr + half_ * 8;
                int b = row >> 10, n = row & 1023;
                int kv = n * NP + p;
                __half* Vt = &g_Vt[b * NH + h][0][0];
#pragma unroll
                for (int nt = 0; nt < 8; nt++) {
                    int d = nt * 8 + 2 * fc;
                    Vt[(size_t)d * SVLEN + kv] =
                        __float2half_rn(acc[mt][nt][half_ * 2 + 0]);
                    Vt[(size_t)(d + 1) * SVLEN + kv] =
                        __float2half_rn(acc[mt][nt][half_ * 2 + 1]);
                }
            }
        }
    } else {
        __half* dst0 = (which == 0) ? &g_Q[0][0][0] : &g_K[0][0][0];
#pragma unroll
        for (int mt = 0; mt < 2; mt++) {
#pragma unroll
            for (int half_ = 0; half_ < 2; half_++) {
                int row = bm + wm + mt * 16 + fr + half_ * 8;
                int b = row >> 10, n = row & 1023;
#pragma unroll
                for (int nt = 0; nt < 8; nt++) {
                    int col = bn + wn + nt * 8 + 2 * fc;
                    int h = col >> 7, p = (col >> 6) & 1, d = col & 63;
                    __half* dst = dst0 +
                        ((size_t)(b * NH + h) * SVLEN + n * NP + p) * HD + d;
                    st_h2(dst, acc[mt][nt][half_ * 2 + 0],
                               acc[mt][nt][half_ * 2 + 1]);
                }
            }
        }
    }
}

// ---------------------------------------------------------------------------
// Output GEMM (fp16): out[2048,1024] = gather(g_Aout) * Woeff^T, K=2048.
// ---------------------------------------------------------------------------
__global__ __launch_bounds__(256, 2) void gemmO_k(float* __restrict__ Cout)
{
    extern __shared__ __align__(16) char smc[];
    const int tid = threadIdx.x, wid = tid >> 5, lane = tid & 31;
    const int wm = (wid & 3) * 32;
    const int wn = (wid >> 2) * 64;
    const int bn = blockIdx.x * 128, bm = blockIdx.y * 128;
    const __half* Bw = &g_Woeff[0][0];
    const uint32_t sb = smem_u32(smc);
    const int fr = lane >> 2, fc = lane & 3;
    const int lrow = tid >> 1;
    const int cb = (tid & 1) * 4;

    const int li = lane & 7;
    const int g8 = (lane >> 3) & 1, g16 = lane >> 4;
    uint32_t rowOffA[2]; int rmA[2];
#pragma unroll
    for (int mt = 0; mt < 2; mt++) {
        int r = wm + mt * 16 + g8 * 8 + li;
        rowOffA[mt] = (uint32_t)r * 128; rmA[mt] = r & 7;
    }
    uint32_t rowOffB[4]; int rmB[4];
#pragma unroll
    for (int j = 0; j < 4; j++) {
        int r = wn + j * 16 + g16 * 8 + li;
        rowOffB[j] = (uint32_t)r * 128; rmB[j] = r & 7;
    }

    int t = bm + lrow;
    int gb = t >> 10, gn = t & 1023;

    auto issue = [&](int kc) {
        int s = kc % NSTG;
        int k0 = kc * 64;
        uint32_t sa = sb + (uint32_t)s * G_STGB;
        uint32_t sbB = sa + G_TILEB;
        uint32_t dstrow = (uint32_t)lrow * 128;
        int swm = lrow & 7;
        const __half* bsrc = Bw + (size_t)(bn + lrow) * NPROJ + k0;
#pragma unroll
        for (int c = 0; c < 4; c++) {
            int cc = cb + c;
            uint32_t off = dstrow + (uint32_t)((cc ^ swm) << 4);
            int col = k0 + cc * 8;
            int o = col >> 6, dd = col & 63;
            cp16(sa + off,
                 &g_Aout[gb * NH + (o >> 1)][gn * NP + (o & 1)][dd]);
            cp16(sbB + off, bsrc + cc * 8);
        }
    };

    float acc[2][8][4];
#pragma unroll
    for (int mt = 0; mt < 2; mt++)
#pragma unroll
        for (int nt = 0; nt < 8; nt++)
#pragma unroll
            for (int j = 0; j < 4; j++) acc[mt][nt][j] = 0.f;

    issue(0); CP_COMMIT();
    issue(1); CP_COMMIT();

    const int NKC = NPROJ / 64;
    for (int kc = 0; kc < NKC; kc++) {
        CP_WAIT(1);
        __syncthreads();
        if (kc + 2 < NKC) issue(kc + 2);
        CP_COMMIT();
        uint32_t Ab = sb + (uint32_t)(kc % NSTG) * G_STGB;
        uint32_t Bb = Ab + G_TILEB;
#pragma unroll
        for (int k16 = 0; k16 < 4; k16++) {
            uint32_t afr[2][4], bfr[8][2];
#pragma unroll
            for (int mt = 0; mt < 2; mt++) {
                uint32_t a = Ab + rowOffA[mt] +
                    (uint32_t)((((2 * k16) + g16) ^ rmA[mt]) << 4);
                ldsm_x4(afr[mt][0], afr[mt][1], afr[mt][2], afr[mt][3], a);
            }
#pragma unroll
            for (int j = 0; j < 4; j++) {
                uint32_t a = Bb + rowOffB[j] +
                    (uint32_t)((((2 * k16) + g8) ^ rmB[j]) << 4);
                ldsm_x4(bfr[2 * j][0], bfr[2 * j][1],
                        bfr[2 * j + 1][0], bfr[2 * j + 1][1], a);
            }
#pragma unroll
            for (int mt = 0; mt < 2; mt++)
#pragma unroll
                for (int nt = 0; nt < 8; nt++)
                    mma_f16(acc[mt][nt], afr[mt], bfr[nt]);
        }
    }

#pragma unroll
    for (int mt = 0; mt < 2; mt++) {
#pragma unroll
        for (int half_ = 0; half_ < 2; half_++) {
            int row = bm + wm + mt * 16 + fr + half_ * 8;
#pragma unroll
            for (int nt = 0; nt < 8; nt++) {
                int col = bn + wn + nt * 8 + 2 * fc;
                *(float2*)(Cout + (size_t)row * HIDD + col) = make_float2(
                    acc[mt][nt][half_ * 2 + 0], acc[mt][nt][half_ * 2 + 1]);
            }
        }
    }
}

// ---------------------------------------------------------------------------
// Causal flash attention (fp16 MMA + LDSM): q-tile 128 (warp 16 rows),
//   k-tile 64, 3-buffer KV ring, Q fragments preloaded, P in registers.
//   Smem: Qs[128][64] + 3 x (Ks[64][64], Vts[64][64]), all swizzled.
// ---------------------------------------------------------------------------
#define Q_B 16384
#define KV_B 8192
#define SMEM_ATTN (Q_B + 3 * 2 * KV_B)   // 65,536 B

__global__ __launch_bounds__(256, 2) void attn_k()
{
    extern __shared__ __align__(16) char smc[];
    const uint32_t sQ = smem_u32(smc);
    const uint32_t sKV = sQ + Q_B;

    const int bh = blockIdx.y;
    const int qt = (gridDim.x - 1) - blockIdx.x;   // heavy tiles first
    const int qstart = qt * 128;
    const __half* Qg = &g_Q[bh][0][0];
    const __half* Kg = &g_K[bh][0][0];
    const __half* Vtg = &g_Vt[bh][0][0];

    const int tid = threadIdx.x;
    const int wq = tid >> 5;
    const int lane = tid & 31;
    const int fr = lane >> 2;
    const int fc = lane & 3;
    const int r0 = wq * 16 + fr, r1 = r0 + 8;

    const int li = lane & 7;
    const int g8 = (lane >> 3) & 1, g16 = lane >> 4;
    // Q A-frag rows (1 m16 per warp): khalf = g16
    const int rowQ = wq * 16 + g8 * 8 + li;
    const uint32_t rowOffQ = (uint32_t)rowQ * 128;
    const int rmQ = rowQ & 7;
    // K/V B-frag rows: j*16 + g16*8 + li, khalf = g8
    uint32_t rowOffKV[4]; int rmKV[4];
#pragma unroll
    for (int j = 0; j < 4; j++) {
        int r = j * 16 + g16 * 8 + li;
        rowOffKV[j] = (uint32_t)r * 128; rmKV[j] = r & 7;
    }

    auto issue_kv = [&](int jt) {
        int buf = jt % 3;
        uint32_t sK = sKV + (uint32_t)buf * (2 * KV_B);
        uint32_t sV = sK + KV_B;
        int kstart = jt * 64;
#pragma unroll
        for (int it = 0; it < 2; it++) {
            int chunk = tid + 256 * it;
            int row = chunk >> 3;
            int cc = chunk & 7;
            uint32_t off = (uint32_t)row * 128 +
                           (uint32_t)((cc ^ (row & 7)) << 4);
            cp16(sK + off, Kg + (size_t)(kstart + row) * HD + cc * 8);
            cp16(sV + off, Vtg + (size_t)row * SVLEN + kstart + cc * 8);
        }
    };

    // prologue: Q + kv0 group 0, kv1 group 1
#pragma unroll
    for (int it = 0; it < 4; it++) {
        int chunk = tid + 256 * it;
        int row = chunk >> 3;
        int cc = chunk & 7;
        uint32_t off = (uint32_t)row * 128 + (uint32_t)((cc ^ (row & 7)) << 4);
        cp16(sQ + off, Qg + (size_t)(qstart + row) * HD + cc * 8);
    }
    issue_kv(0); CP_COMMIT();
    issue_kv(1); CP_COMMIT();

    float O[8][4];
    float m0 = NEG_INF, m1 = NEG_INF, l0 = 0.f, l1 = 0.f;
#pragma unroll
    for (int nt = 0; nt < 8; nt++)
#pragma unroll
        for (int j = 0; j < 4; j++) O[nt][j] = 0.f;

    uint32_t qfr[4][4];      // Q fragments, loaded once at jt==0

    const int jmax = 2 * qt + 1;
    for (int jt = 0; jt <= jmax; jt++) {
        const int kstart = jt * 64;
        CP_WAIT(1);           // tile jt (and Q at jt=0) complete
        __syncthreads();
        if (jt + 2 <= jmax) issue_kv(jt + 2);
        CP_COMMIT();
        uint32_t Kb = sKV + (uint32_t)(jt % 3) * (2 * KV_B);
        uint32_t Vb = Kb + KV_B;

        if (jt == 0) {
#pragma unroll
            for (int k16 = 0; k16 < 4; k16++) {
                uint32_t a = sQ + rowOffQ +
                    (uint32_t)((((2 * k16) + g16) ^ rmQ) << 4);
                ldsm_x4(qfr[k16][0], qfr[k16][1], qfr[k16][2], qfr[k16][3], a);
            }
        }

        // ---- S = Q K^T ----
        float s[8][4];
#pragma unroll
        for (int nt = 0; nt < 8; nt++)
#pragma unroll
            for (int j = 0; j < 4; j++) s[nt][j] = 0.f;
#pragma unroll
        for (int k16 = 0; k16 < 4; k16++) {
            uint32_t bfr[8][2];
#pragma unroll
            for (int j = 0; j < 4; j++) {
                uint32_t a = Kb + rowOffKV[j] +
                    (uint32_t)((((2 * k16) + g8) ^ rmKV[j]) << 4);
                ldsm_x4(bfr[2 * j][0], bfr[2 * j][1],
                        bfr[2 * j + 1][0], bfr[2 * j + 1][1], a);
            }
#pragma unroll
            for (int nt = 0; nt < 8; nt++)
                mma_f16(s[nt], qfr[k16], bfr[nt]);
        }

        // causal mask
        if (kstart + 63 > qstart + wq * 16) {
            int gr0 = qstart + r0, gr1 = gr0 + 8;
#pragma unroll
            for (int nt = 0; nt < 8; nt++) {
                int c0 = kstart + nt * 8 + 2 * fc;
                if (c0 > gr0)     s[nt][0] = NEG_INF;
                if (c0 + 1 > gr0) s[nt][1] = NEG_INF;
                if (c0 > gr1)     s[nt][2] = NEG_INF;
                if (c0 + 1 > gr1) s[nt][3] = NEG_INF;
            }
        }

        // ---- online softmax; P packed straight into MMA A-fragments ----
        float mx0 = NEG_INF, mx1 = NEG_INF;
#pragma unroll
        for (int nt = 0; nt < 8; nt++) {
            mx0 = fmaxf(mx0, fmaxf(s[nt][0], s[nt][1]));
            mx1 = fmaxf(mx1, fmaxf(s[nt][2], s[nt][3]));
        }
        mx0 = fmaxf(mx0, __shfl_xor_sync(0xffffffffu, mx0, 1));
        mx0 = fmaxf(mx0, __shfl_xor_sync(0xffffffffu, mx0, 2));
        mx1 = fmaxf(mx1, __shfl_xor_sync(0xffffffffu, mx1, 1));
        mx1 = fmaxf(mx1, __shfl_xor_sync(0xffffffffu, mx1, 2));
        float newm0 = fmaxf(m0, mx0), newm1 = fmaxf(m1, mx1);
        float al0 = __expf(m0 - newm0), al1 = __expf(m1 - newm1);

        uint32_t pfr[4][4];           // [k16][4 regs] PV A-fragments
        float rs0 = 0.f, rs1 = 0.f;
#pragma unroll
        for (int nt = 0; nt < 8; nt++) {
            float p0 = __expf(s[nt][0] - newm0);
            float p1 = __expf(s[nt][1] - newm0);
            float p2 = __expf(s[nt][2] - newm1);
            float p3 = __expf(s[nt][3] - newm1);
            rs0 += p0 + p1; rs1 += p2 + p3;
            int t16 = nt >> 1, hi = nt & 1;
            pfr[t16][hi * 2 + 0] = pack_h2(p0, p1);   // row r0
            pfr[t16][hi * 2 + 1] = pack_h2(p2, p3);   // row r1
        }
        rs0 += __shfl_xor_sync(0xffffffffu, rs0, 1);
        rs0 += __shfl_xor_sync(0xffffffffu, rs0, 2);
        rs1 += __shfl_xor_sync(0xffffffffu, rs1, 1);
        rs1 += __shfl_xor_sync(0xffffffffu, rs1, 2);
        l0 = l0 * al0 + rs0; l1 = l1 * al1 + rs1;
        m0 = newm0; m1 = newm1;
#pragma unroll
        for (int nt = 0; nt < 8; nt++) {
            O[nt][0] *= al0; O[nt][1] *= al0;
            O[nt][2] *= al1; O[nt][3] *= al1;
        }

        // ---- O += P V (A in regs; B via LDSM from Vts[d][kv]) ----
#pragma unroll
        for (int k16 = 0; k16 < 4; k16++) {
            uint32_t bfr[8][2];
#pragma unroll
            for (int j = 0; j < 4; j++) {
                uint32_t a = Vb + rowOffKV[j] +
                    (uint32_t)((((2 * k16) + g8) ^ rmKV[j]) << 4);
                ldsm_x4(bfr[2 * j][0], bfr[2 * j][1],
                        bfr[2 * j + 1][0], bfr[2 * j + 1][1], a);
            }
#pragma unroll
            for (int nt = 0; nt < 8; nt++)
                mma_f16(O[nt], pfr[k16], bfr[nt]);
        }
        // next iteration's barrier protects buffer reuse
    }

    // epilogue: normalize, store natural fp16 into g_Aout
    __half* Ag = &g_Aout[bh][0][0];
    float inv0 = 1.f / l0, inv1 = 1.f / l1;
#pragma unroll
    for (int nt = 0; nt < 8; nt++) {
        int pos = nt * 8 + 2 * fc;
        st_h2(Ag + (size_t)(qstart + r0) * HD + pos,
              O[nt][0] * inv0, O[nt][1] * inv0);
        st_h2(Ag + (size_t)(qstart + r1) * HD + pos,
              O[nt][2] * inv1, O[nt][3] * inv1);
    }
}

// ---------------------------------------------------------------------------
// launch
// ---------------------------------------------------------------------------
extern "C" void kernel_launch(void* const* d_in, const int* in_sizes, int n_in,
                              void* d_out, int out_size)
{
    const float* x  = (const float*)d_in[0];
    const float* Wq = (const float*)d_in[1];
    const float* Wk = (const float*)d_in[2];
    const float* Wv = (const float*)d_in[3];
    const float* Wo = (const float*)d_in[4];
    const float* aq = (const float*)d_in[5];
    const float* ak = (const float*)d_in[6];
    const float* av = (const float*)d_in[7];
    const float* cl = (const float*)d_in[8];
    float* out = (float*)d_out;

    cudaFuncSetAttribute(gemmA_k, cudaFuncAttributeMaxDynamicSharedMemorySize, SMEM_G);
    cudaFuncSetAttribute(gemmO_k, cudaFuncAttributeMaxDynamicSharedMemorySize, SMEM_G);
    cudaFuncSetAttribute(attn_k, cudaFuncAttributeMaxDynamicSharedMemorySize, SMEM_ATTN);

    round_x_k<<<(MTOK * HIDD) / 256, 256>>>(x);
    build_weff_k<<<dim3((HD * HIDD) / 256, 3), 256>>>(Wq, Wk, Wv, aq, ak, av);
    build_woeff_k<<<(HIDD * HD) / 256, 256>>>(Wo, cl);

    // projections + head mixing (q/k/v via z)
    gemmA_k<<<dim3(NPROJ / 128, MTOK / 128, 3), 256, SMEM_G>>>();

    // causal SDPA over virtual positions
    attn_k<<<dim3(SVLEN / 128, NB * NH), 256, SMEM_ATTN>>>();

    // collapse + output projection
    gemmO_k<<<dim3(HIDD / 128, MTOK / 128), 256, SMEM_G>>>(out);
}

// round 12
// speedup vs baseline: 7.4024x; 1.0370x over previous
#include <cuda_runtime.h>
#include <cuda_fp16.h>
#include <cstdint>

// ---------------------------------------------------------------------------
// InterleavedHeadAttention — round 12
//   - fused prologue kernel (round_x + weight builds run concurrently)
//   - gemmO: M-tile 64 -> 256 CTAs (was 128; chip was half idle)
//   - attention softmax in log2 domain (log2e folded into Weff_q, raw ex2)
//   - gemmA / attn structure unchanged from round 11 (LDSM + ring pipelines)
//   B=2, S=1024, HID=1024, H=16, P=2, D=64, sv=2048
// ---------------------------------------------------------------------------

#define NB 2
#define SEQ 1024
#define HIDD 1024
#define NH 16
#define NP 2
#define HD 64
#define SVLEN (SEQ * NP)        // 2048
#define MTOK (NB * SEQ)         // 2048
#define NPROJ (NH * NP * HD)    // 2048
#define ATTN_SCALE 0.125f
#define LOG2E 1.4426950408889634f

#define NEG_INF __int_as_float(0xff800000)

// fp16 storage, all natural layouts
__device__ __half g_Weff[3][NPROJ][HIDD];
__device__ __half g_Woeff[HIDD][NPROJ];      // [f][o*64+d]
__device__ __half g_Xr[MTOK][HIDD];
__device__ __half g_Q[NB * NH][SVLEN][HD];
__device__ __half g_K[NB * NH][SVLEN][HD];
__device__ __half g_Vt[NB * NH][HD][SVLEN];  // transposed
__device__ __half g_Aout[NB * NH][SVLEN][HD];

// ---------------------------------------------------------------------------
// helpers
// ---------------------------------------------------------------------------
__device__ __forceinline__ void cp16(uint32_t s, const void* g) {
    asm volatile("cp.async.cg.shared.global [%0], [%1], 16;" :: "r"(s), "l"(g));
}
__device__ __forceinline__ uint32_t smem_u32(const void* p) {
    uint32_t a;
    asm("{ .reg .u64 t; cvta.to.shared.u64 t, %1; cvt.u32.u64 %0, t; }"
        : "=r"(a) : "l"(p));
    return a;
}
#define CP_COMMIT() asm volatile("cp.async.commit_group;" ::: "memory")
#define CP_WAIT(n)  asm volatile("cp.async.wait_group %0;" :: "n"(n) : "memory")

__device__ __forceinline__ void st_h2(__half* p, float a, float b) {
    *(__half2*)p = __float22half2_rn(make_float2(a, b));
}
__device__ __forceinline__ uint32_t pack_h2(float a, float b) {
    __half2 h = __float22half2_rn(make_float2(a, b));
    return *(uint32_t*)&h;
}
__device__ __forceinline__ float ex2(float x) {
    float r;
    asm("ex2.approx.f32 %0, %1;" : "=f"(r) : "f"(x));
    return r;
}
// D(16x8) += A(16x16) * B(16x8), f16 in, f32 accum
__device__ __forceinline__ void mma_f16(float* c, const uint32_t* a,
                                        const uint32_t* b) {
    asm volatile(
        "mma.sync.aligned.m16n8k16.row.col.f32.f16.f16.f32 "
        "{%0,%1,%2,%3}, {%4,%5,%6,%7}, {%8,%9}, {%0,%1,%2,%3};"
        : "+f"(c[0]), "+f"(c[1]), "+f"(c[2]), "+f"(c[3])
        : "r"(a[0]), "r"(a[1]), "r"(a[2]), "r"(a[3]), "r"(b[0]), "r"(b[1]));
}
__device__ __forceinline__ void ldsm_x4(uint32_t& r0, uint32_t& r1,
                                        uint32_t& r2, uint32_t& r3, uint32_t a) {
    asm volatile("ldmatrix.sync.aligned.m8n8.x4.shared.b16 {%0,%1,%2,%3}, [%4];"
                 : "=r"(r0), "=r"(r1), "=r"(r2), "=r"(r3) : "r"(a));
}

// ---------------------------------------------------------------------------
// Fused prologue: y=0..2 build_weff(q/k/v), y=3 build_woeff, y=4 round_x.
//   ATTN_SCALE*LOG2E folded into Weff_q (softmax runs in log2 domain).
// ---------------------------------------------------------------------------
__global__ __launch_bounds__(256) void prep_k(
    const float* __restrict__ x,
    const float* __restrict__ Wq, const float* __restrict__ Wk,
    const float* __restrict__ Wv, const float* __restrict__ Wo,
    const float* __restrict__ aq, const float* __restrict__ ak,
    const float* __restrict__ av, const float* __restrict__ cl)
{
    __shared__ float sS[512];
    const int tid = threadIdx.x;
    const int y = blockIdx.y;

    if (y < 3) {
        const float* W = (y == 0) ? Wq : (y == 1) ? Wk : Wv;
        const float* A = (y == 0) ? aq : (y == 1) ? ak : av;
        sS[tid] = A[tid];
        sS[tid + 256] = A[tid + 256];
        __syncthreads();
        int idx = blockIdx.x * 256 + tid;       // over 64*1024
        int d = idx >> 10, e = idx & 1023;
        float wv[NH];
#pragma unroll
        for (int m = 0; m < NH; m++)
            wv[m] = W[(m * HD + d) * HIDD + e];
        float scale = (y == 0) ? ATTN_SCALE * LOG2E : 1.0f;
#pragma unroll
        for (int hp = 0; hp < 32; hp++) {
            float acc = 0.f;
#pragma unroll
            for (int m = 0; m < NH; m++)
                acc += sS[m * 32 + hp] * wv[m];
            g_Weff[y][hp * HD + d][e] = __float2half_rn(acc * scale);
        }
    } else if (y == 3) {
        sS[tid] = cl[tid];
        sS[tid + 256] = cl[tid + 256];
        __syncthreads();
        int idx = blockIdx.x * 256 + tid;       // over 1024*64
        int f = idx >> 6, d = idx & 63;
        float wv[NH];
#pragma unroll
        for (int h = 0; h < NH; h++)
            wv[h] = Wo[f * HIDD + h * HD + d];
#pragma unroll
        for (int o = 0; o < 32; o++) {
            float acc = 0.f;
#pragma unroll
            for (int h = 0; h < NH; h++)
                acc += sS[h * 32 + o] * wv[h];
            g_Woeff[f][o * HD + d] = __float2half_rn(acc);
        }
    } else {
        // round_x: 524288 float4s over 65536 threads, 8 each
        const float4* x4 = (const float4*)x;
        uint2* dst = (uint2*)&g_Xr[0][0];
#pragma unroll
        for (int it = 0; it < 8; it++) {
            int idx4 = it * 65536 + blockIdx.x * 256 + tid;
            float4 v = x4[idx4];
            uint2 o;
            o.x = pack_h2(v.x, v.y);
            o.y = pack_h2(v.z, v.w);
            dst[idx4] = o;
        }
    }
}

// ---------------------------------------------------------------------------
// GEMM smem tiles: rows of 64 halves (128B), XOR chunk swizzle
//   sw(row, chunk) = row*128 + ((chunk ^ (row&7))<<4)
// ---------------------------------------------------------------------------
#define G_TILEB 16384                    // 128-row tile bytes
#define G_STGB (2 * G_TILEB)
#define NSTG 3
#define SMEM_G (NSTG * G_STGB)           // 96 KB

// ---------------------------------------------------------------------------
// Projection GEMM (fp16): C[2048,2048] = Xr * Weff[z]^T, K=1024.
//   CTA 128x128, 8 warps (4M x 2N), warp 32x64, KC=64, LDSM fragments.
// ---------------------------------------------------------------------------
__global__ __launch_bounds__(256, 2) void gemmA_k()
{
    extern __shared__ __align__(16) char smc[];
    const int tid = threadIdx.x, wid = tid >> 5, lane = tid & 31;
    const int wm = (wid & 3) * 32;
    const int wn = (wid >> 2) * 64;
    const int bn = blockIdx.x * 128, bm = blockIdx.y * 128;
    const int which = blockIdx.z;
    const __half* Aw = &g_Xr[0][0];
    const __half* Bw = &g_Weff[which][0][0];
    const uint32_t sb = smem_u32(smc);
    const int fr = lane >> 2, fc = lane & 3;
    const int lrow = tid >> 1;
    const int cb = (tid & 1) * 4;

    const int li = lane & 7;
    const int g8 = (lane >> 3) & 1, g16 = lane >> 4;
    uint32_t rowOffA[2]; int rmA[2];
#pragma unroll
    for (int mt = 0; mt < 2; mt++) {
        int r = wm + mt * 16 + g8 * 8 + li;
        rowOffA[mt] = (uint32_t)r * 128; rmA[mt] = r & 7;
    }
    uint32_t rowOffB[4]; int rmB[4];
#pragma unroll
    for (int j = 0; j < 4; j++) {
        int r = wn + j * 16 + g16 * 8 + li;
        rowOffB[j] = (uint32_t)r * 128; rmB[j] = r & 7;
    }

    auto issue = [&](int kc) {
        int s = kc % NSTG;
        int k0 = kc * 64;
        uint32_t sa = sb + (uint32_t)s * G_STGB;
        uint32_t sbB = sa + G_TILEB;
        uint32_t dstrow = (uint32_t)lrow * 128;
        int swm = lrow & 7;
        const __half* asrc = Aw + (size_t)(bm + lrow) * HIDD + k0;
        const __half* bsrc = Bw + (size_t)(bn + lrow) * HIDD + k0;
#pragma unroll
        for (int c = 0; c < 4; c++) {
            int cc = cb + c;
            uint32_t off = dstrow + (uint32_t)((cc ^ swm) << 4);
            cp16(sa + off, asrc + cc * 8);
            cp16(sbB + off, bsrc + cc * 8);
        }
    };

    float acc[2][8][4];
#pragma unroll
    for (int mt = 0; mt < 2; mt++)
#pragma unroll
        for (int nt = 0; nt < 8; nt++)
#pragma unroll
            for (int j = 0; j < 4; j++) acc[mt][nt][j] = 0.f;

    issue(0); CP_COMMIT();
    issue(1); CP_COMMIT();

    const int NKC = HIDD / 64;
    for (int kc = 0; kc < NKC; kc++) {
        CP_WAIT(1);
        __syncthreads();
        if (kc + 2 < NKC) issue(kc + 2);
        CP_COMMIT();
        uint32_t Ab = sb + (uint32_t)(kc % NSTG) * G_STGB;
        uint32_t Bb = Ab + G_TILEB;
#pragma unroll
        for (int k16 = 0; k16 < 4; k16++) {
            uint32_t afr[2][4], bfr[8][2];
#pragma unroll
            for (int mt = 0; mt < 2; mt++) {
                uint32_t a = Ab + rowOffA[mt] +
                    (uint32_t)((((2 * k16) + g16) ^ rmA[mt]) << 4);
                ldsm_x4(afr[mt][0], afr[mt][1], afr[mt][2], afr[mt][3], a);
            }
#pragma unroll
            for (int j = 0; j < 4; j++) {
                uint32_t a = Bb + rowOffB[j] +
                    (uint32_t)((((2 * k16) + g8) ^ rmB[j]) << 4);
                ldsm_x4(bfr[2 * j][0], bfr[2 * j][1],
                        bfr[2 * j + 1][0], bfr[2 * j + 1][1], a);
            }
#pragma unroll
            for (int mt = 0; mt < 2; mt++)
#pragma unroll
                for (int nt = 0; nt < 8; nt++)
                    mma_f16(acc[mt][nt], afr[mt], bfr[nt]);
        }
    }

    // ---- epilogue (natural layouts) ----
    if (which == 2) {
        int h = bn >> 7, p = (wn >> 6) & 1;
#pragma unroll
        for (int mt = 0; mt < 2; mt++) {
#pragma unroll
            for (int half_ = 0; half_ < 2; half_++) {
                int row = bm + wm + mt * 16 + fr + half_ * 8;
                int b = row >> 10, n = row & 1023;
                int kv = n * NP + p;
                __half* Vt = &g_Vt[b * NH + h][0][0];
#pragma unroll
                for (int nt = 0; nt < 8; nt++) {
                    int d = nt * 8 + 2 * fc;
                    Vt[(size_t)d * SVLEN + kv] =
                        __float2half_rn(acc[mt][nt][half_ * 2 + 0]);
                    Vt[(size_t)(d + 1) * SVLEN + kv] =
                        __float2half_rn(acc[mt][nt][half_ * 2 + 1]);
                }
            }
        }
    } else {
        __half* dst0 = (which == 0) ? &g_Q[0][0][0] : &g_K[0][0][0];
#pragma unroll
        for (int mt = 0; mt < 2; mt++) {
#pragma unroll
            for (int half_ = 0; half_ < 2; half_++) {
                int row = bm + wm + mt * 16 + fr + half_ * 8;
                int b = row >> 10, n = row & 1023;
#pragma unroll
                for (int nt = 0; nt < 8; nt++) {
                    int col = bn + wn + nt * 8 + 2 * fc;
                    int h = col >> 7, p = (col >> 6) & 1, d = col & 63;
                    __half* dst = dst0 +
                        ((size_t)(b * NH + h) * SVLEN + n * NP + p) * HD + d;
                    st_h2(dst, acc[mt][nt][half_ * 2 + 0],
                               acc[mt][nt][half_ * 2 + 1]);
                }
            }
        }
    }
}

// ---------------------------------------------------------------------------
// Output GEMM (fp16): out[2048,1024] = gather(g_Aout) * Woeff^T, K=2048.
//   CTA 64x128 -> 256 CTAs (fills the chip). 8 warps (2M x 4N), warp 32x32.
// ---------------------------------------------------------------------------
#define O_AB 8192                        // A tile bytes (64 rows)
#define O_STGB (O_AB + G_TILEB)          // 24 KB / stage
#define SMEM_O (NSTG * O_STGB)           // 72 KB

__global__ __launch_bounds__(256, 2) void gemmO_k(float* __restrict__ Cout)
{
    extern __shared__ __align__(16) char smc[];
    const int tid = threadIdx.x, wid = tid >> 5, lane = tid & 31;
    const int wm = (wid & 1) * 32;
    const int wn = (wid >> 1) * 32;
    const int bn = blockIdx.x * 128, bm = blockIdx.y * 64;
    const __half* Bw = &g_Woeff[0][0];
    const uint32_t sb = smem_u32(smc);
    const int fr = lane >> 2, fc = lane & 3;

    const int li = lane & 7;
    const int g8 = (lane >> 3) & 1, g16 = lane >> 4;
    uint32_t rowOffA[2]; int rmA[2];
#pragma unroll
    for (int mt = 0; mt < 2; mt++) {
        int r = wm + mt * 16 + g8 * 8 + li;
        rowOffA[mt] = (uint32_t)r * 128; rmA[mt] = r & 7;
    }
    uint32_t rowOffB[2]; int rmB[2];
#pragma unroll
    for (int j = 0; j < 2; j++) {
        int r = wn + j * 16 + g16 * 8 + li;
        rowOffB[j] = (uint32_t)r * 128; rmB[j] = r & 7;
    }

    // A loads: 64 rows x 8 chunks = 512 -> 2/thread
    const int arow = tid >> 2;
    const int acb = (tid & 3) * 2;
    // B loads: 128 rows x 8 chunks = 1024 -> 4/thread
    const int brow = tid >> 1;
    const int bcb = (tid & 1) * 4;

    int ta = bm + arow;
    int gb = ta >> 10, gn = ta & 1023;

    auto issue = [&](int kc) {
        int s = kc % NSTG;
        int k0 = kc * 64;
        uint32_t sa = sb + (uint32_t)s * O_STGB;
        uint32_t sbB = sa + O_AB;
        {
            uint32_t dstrow = (uint32_t)arow * 128;
            int swm = arow & 7;
#pragma unroll
            for (int c = 0; c < 2; c++) {
                int cc = acb + c;
                uint32_t off = dstrow + (uint32_t)((cc ^ swm) << 4);
                int col = k0 + cc * 8;
                int o = col >> 6, dd = col & 63;
                cp16(sa + off,
                     &g_Aout[gb * NH + (o >> 1)][gn * NP + (o & 1)][dd]);
            }
        }
        {
            uint32_t dstrow = (uint32_t)brow * 128;
            int swm = brow & 7;
            const __half* bsrc = Bw + (size_t)(bn + brow) * NPROJ + k0;
#pragma unroll
            for (int c = 0; c < 4; c++) {
                int cc = bcb + c;
                uint32_t off = dstrow + (uint32_t)((cc ^ swm) << 4);
                cp16(sbB + off, bsrc + cc * 8);
            }
        }
    };

    float acc[2][4][4];
#pragma unroll
    for (int mt = 0; mt < 2; mt++)
#pragma unroll
        for (int nt = 0; nt < 4; nt++)
#pragma unroll
            for (int j = 0; j < 4; j++) acc[mt][nt][j] = 0.f;

    issue(0); CP_COMMIT();
    issue(1); CP_COMMIT();

    const int NKC = NPROJ / 64;
    for (int kc = 0; kc < NKC; kc++) {
        CP_WAIT(1);
        __syncthreads();
        if (kc + 2 < NKC) issue(kc + 2);
        CP_COMMIT();
        uint32_t Ab = sb + (uint32_t)(kc % NSTG) * O_STGB;
        uint32_t Bb = Ab + O_AB;
#pragma unroll
        for (int k16 = 0; k16 < 4; k16++) {
            uint32_t afr[2][4], bfr[4][2];
#pragma unroll
            for (int mt = 0; mt < 2; mt++) {
                uint32_t a = Ab + rowOffA[mt] +
                    (uint32_t)((((2 * k16) + g16) ^ rmA[mt]) << 4);
                ldsm_x4(afr[mt][0], afr[mt][1], afr[mt][2], afr[mt][3], a);
            }
#pragma unroll
            for (int j = 0; j < 2; j++) {
                uint32_t a = Bb + rowOffB[j] +
                    (uint32_t)((((2 * k16) + g8) ^ rmB[j]) << 4);
                ldsm_x4(bfr[2 * j][0], bfr[2 * j][1],
                        bfr[2 * j + 1][0], bfr[2 * j + 1][1], a);
            }
#pragma unroll
            for (int mt = 0; mt < 2; mt++)
#pragma unroll
                for (int nt = 0; nt < 4; nt++)
                    mma_f16(acc[mt][nt], afr[mt], bfr[nt]);
        }
    }

#pragma unroll
    for (int mt = 0; mt < 2; mt++) {
#pragma unroll
        for (int half_ = 0; half_ < 2; half_++) {
            int row = bm + wm + mt * 16 + fr + half_ * 8;
#pragma unroll
            for (int nt = 0; nt < 4; nt++) {
                int col = bn + wn + nt * 8 + 2 * fc;
                *(float2*)(Cout + (size_t)row * HIDD + col) = make_float2(
                    acc[mt][nt][half_ * 2 + 0], acc[mt][nt][half_ * 2 + 1]);
            }
        }
    }
}

// ---------------------------------------------------------------------------
// Causal flash attention (fp16 MMA + LDSM, log2-domain softmax):
//   q-tile 128 (warp 16 rows), k-tile 64, 3-buffer KV ring, Q fragments
//   preloaded, P in registers. Scores arrive pre-scaled by scale*log2e.
// ---------------------------------------------------------------------------
#define Q_B 16384
#define KV_B 8192
#define SMEM_ATTN (Q_B + 3 * 2 * KV_B)   // 65,536 B

__global__ __launch_bounds__(256, 2) void attn_k()
{
    extern __shared__ __align__(16) char smc[];
    const uint32_t sQ = smem_u32(smc);
    const uint32_t sKV = sQ + Q_B;

    const int bh = blockIdx.y;
    const int qt = (gridDim.x - 1) - blockIdx.x;   // heavy tiles first
    const int qstart = qt * 128;
    const __half* Qg = &g_Q[bh][0][0];
    const __half* Kg = &g_K[bh][0][0];
    const __half* Vtg = &g_Vt[bh][0][0];

    const int tid = threadIdx.x;
    const int wq = tid >> 5;
    const int lane = tid & 31;
    const int fr = lane >> 2;
    const int fc = lane & 3;
    const int r0 = wq * 16 + fr, r1 = r0 + 8;

    const int li = lane & 7;
    const int g8 = (lane >> 3) & 1, g16 = lane >> 4;
    const int rowQ = wq * 16 + g8 * 8 + li;
    const uint32_t rowOffQ = (uint32_t)rowQ * 128;
    const int rmQ = rowQ & 7;
    uint32_t rowOffKV[4]; int rmKV[4];
#pragma unroll
    for (int j = 0; j < 4; j++) {
        int r = j * 16 + g16 * 8 + li;
        rowOffKV[j] = (uint32_t)r * 128; rmKV[j] = r & 7;
    }

    auto issue_kv = [&](int jt) {
        int buf = jt % 3;
        uint32_t sK = sKV + (uint32_t)buf * (2 * KV_B);
        uint32_t sV = sK + KV_B;
        int kstart = jt * 64;
#pragma unroll
        for (int it = 0; it < 2; it++) {
            int chunk = tid + 256 * it;
            int row = chunk >> 3;
            int cc = chunk & 7;
            uint32_t off = (uint32_t)row * 128 +
                           (uint32_t)((cc ^ (row & 7)) << 4);
            cp16(sK + off, Kg + (size_t)(kstart + row) * HD + cc * 8);
            cp16(sV + off, Vtg + (size_t)row * SVLEN + kstart + cc * 8);
        }
    };

    // prologue: Q + kv0 group 0, kv1 group 1
#pragma unroll
    for (int it = 0; it < 4; it++) {
        int chunk = tid + 256 * it;
        int row = chunk >> 3;
        int cc = chunk & 7;
        uint32_t off = (uint32_t)row * 128 + (uint32_t)((cc ^ (row & 7)) << 4);
        cp16(sQ + off, Qg + (size_t)(qstart + row) * HD + cc * 8);
    }
    issue_kv(0); CP_COMMIT();
    issue_kv(1); CP_COMMIT();

    float O[8][4];
    float m0 = NEG_INF, m1 = NEG_INF, l0 = 0.f, l1 = 0.f;
#pragma unroll
    for (int nt = 0; nt < 8; nt++)
#pragma unroll
        for (int j = 0; j < 4; j++) O[nt][j] = 0.f;

    uint32_t qfr[4][4];

    const int jmax = 2 * qt + 1;
    for (int jt = 0; jt <= jmax; jt++) {
        const int kstart = jt * 64;
        CP_WAIT(1);
        __syncthreads();
        if (jt + 2 <= jmax) issue_kv(jt + 2);
        CP_COMMIT();
        uint32_t Kb = sKV + (uint32_t)(jt % 3) * (2 * KV_B);
        uint32_t Vb = Kb + KV_B;

        if (jt == 0) {
#pragma unroll
            for (int k16 = 0; k16 < 4; k16++) {
                uint32_t a = sQ + rowOffQ +
                    (uint32_t)((((2 * k16) + g16) ^ rmQ) << 4);
                ldsm_x4(qfr[k16][0], qfr[k16][1], qfr[k16][2], qfr[k16][3], a);
            }
        }

        // ---- S = Q K^T (pre-scaled by scale*log2e) ----
        float s[8][4];
#pragma unroll
        for (int nt = 0; nt < 8; nt++)
#pragma unroll
            for (int j = 0; j < 4; j++) s[nt][j] = 0.f;
#pragma unroll
        for (int k16 = 0; k16 < 4; k16++) {
            uint32_t bfr[8][2];
#pragma unroll
            for (int j = 0; j < 4; j++) {
                uint32_t a = Kb + rowOffKV[j] +
                    (uint32_t)((((2 * k16) + g8) ^ rmKV[j]) << 4);
                ldsm_x4(bfr[2 * j][0], bfr[2 * j][1],
                        bfr[2 * j + 1][0], bfr[2 * j + 1][1], a);
            }
#pragma unroll
            for (int nt = 0; nt < 8; nt++)
                mma_f16(s[nt], qfr[k16], bfr[nt]);
        }

        // causal mask
        if (kstart + 63 > qstart + wq * 16) {
            int gr0 = qstart + r0, gr1 = gr0 + 8;
#pragma unroll
            for (int nt = 0; nt < 8; nt++) {
                int c0 = kstart + nt * 8 + 2 * fc;
                if (c0 > gr0)     s[nt][0] = NEG_INF;
                if (c0 + 1 > gr0) s[nt][1] = NEG_INF;
                if (c0 > gr1)     s[nt][2] = NEG_INF;
                if (c0 + 1 > gr1) s[nt][3] = NEG_INF;
            }
        }

        // ---- online softmax in log2 domain ----
        float mx0 = NEG_INF, mx1 = NEG_INF;
#pragma unroll
        for (int nt = 0; nt < 8; nt++) {
            mx0 = fmaxf(mx0, fmaxf(s[nt][0], s[nt][1]));
            mx1 = fmaxf(mx1, fmaxf(s[nt][2], s[nt][3]));
        }
        mx0 = fmaxf(mx0, __shfl_xor_sync(0xffffffffu, mx0, 1));
        mx0 = fmaxf(mx0, __shfl_xor_sync(0xffffffffu, mx0, 2));
        mx1 = fmaxf(mx1, __shfl_xor_sync(0xffffffffu, mx1, 1));
        mx1 = fmaxf(mx1, __shfl_xor_sync(0xffffffffu, mx1, 2));
        float newm0 = fmaxf(m0, mx0), newm1 = fmaxf(m1, mx1);
        float al0 = ex2(m0 - newm0), al1 = ex2(m1 - newm1);

        uint32_t pfr[4][4];
        float rs0 = 0.f, rs1 = 0.f;
#pragma unroll
        for (int nt = 0; nt < 8; nt++) {
            float p0 = ex2(s[nt][0] - newm0);
            float p1 = ex2(s[nt][1] - newm0);
            float p2 = ex2(s[nt][2] - newm1);
            float p3 = ex2(s[nt][3] - newm1);
            rs0 += p0 + p1; rs1 += p2 + p3;
            int t16 = nt >> 1, hi = nt & 1;
            pfr[t16][hi * 2 + 0] = pack_h2(p0, p1);   // row r0
            pfr[t16][hi * 2 + 1] = pack_h2(p2, p3);   // row r1
        }
        rs0 += __shfl_xor_sync(0xffffffffu, rs0, 1);
        rs0 += __shfl_xor_sync(0xffffffffu, rs0, 2);
        rs1 += __shfl_xor_sync(0xffffffffu, rs1, 1);
        rs1 += __shfl_xor_sync(0xffffffffu, rs1, 2);
        l0 = l0 * al0 + rs0; l1 = l1 * al1 + rs1;
        m0 = newm0; m1 = newm1;
#pragma unroll
        for (int nt = 0; nt < 8; nt++) {
            O[nt][0] *= al0; O[nt][1] *= al0;
            O[nt][2] *= al1; O[nt][3] *= al1;
        }

        // ---- O += P V (A in regs; B via LDSM from Vts[d][kv]) ----
#pragma unroll
        for (int k16 = 0; k16 < 4; k16++) {
            uint32_t bfr[8][2];
#pragma unroll
            for (int j = 0; j < 4; j++) {
                uint32_t a = Vb + rowOffKV[j] +
                    (uint32_t)((((2 * k16) + g8) ^ rmKV[j]) << 4);
                ldsm_x4(bfr[2 * j][0], bfr[2 * j][1],
                        bfr[2 * j + 1][0], bfr[2 * j + 1][1], a);
            }
#pragma unroll
            for (int nt = 0; nt < 8; nt++)
                mma_f16(O[nt], pfr[k16], bfr[nt]);
        }
    }

    // epilogue: normalize, store natural fp16 into g_Aout
    __half* Ag = &g_Aout[bh][0][0];
    float inv0 = 1.f / l0, inv1 = 1.f / l1;
#pragma unroll
    for (int nt = 0; nt < 8; nt++) {
        int pos = nt * 8 + 2 * fc;
        st_h2(Ag + (size_t)(qstart + r0) * HD + pos,
              O[nt][0] * inv0, O[nt][1] * inv0);
        st_h2(Ag + (size_t)(qstart + r1) * HD + pos,
              O[nt][2] * inv1, O[nt][3] * inv1);
    }
}

// ---------------------------------------------------------------------------
// launch
// ---------------------------------------------------------------------------
extern "C" void kernel_launch(void* const* d_in, const int* in_sizes, int n_in,
                              void* d_out, int out_size)
{
    const float* x  = (const float*)d_in[0];
    const float* Wq = (const float*)d_in[1];
    const float* Wk = (const float*)d_in[2];
    const float* Wv = (const float*)d_in[3];
    const float* Wo = (const float*)d_in[4];
    const float* aq = (const float*)d_in[5];
    const float* ak = (const float*)d_in[6];
    const float* av = (const float*)d_in[7];
    const float* cl = (const float*)d_in[8];
    float* out = (float*)d_out;

    cudaFuncSetAttribute(gemmA_k, cudaFuncAttributeMaxDynamicSharedMemorySize, SMEM_G);
    cudaFuncSetAttribute(gemmO_k, cudaFuncAttributeMaxDynamicSharedMemorySize, SMEM_O);
    cudaFuncSetAttribute(attn_k, cudaFuncAttributeMaxDynamicSharedMemorySize, SMEM_ATTN);

    // fused prologue: weight builds + x rounding, all concurrent
    prep_k<<<dim3(256, 5), 256>>>(x, Wq, Wk, Wv, Wo, aq, ak, av, cl);

    // projections + head mixing (q/k/v via z)
    gemmA_k<<<dim3(NPROJ / 128, MTOK / 128, 3), 256, SMEM_G>>>();

    // causal SDPA over virtual positions
    attn_k<<<dim3(SVLEN / 128, NB * NH), 256, SMEM_ATTN>>>();

    // collapse + output projection (256 CTAs)
    gemmO_k<<<dim3(HIDD / 128, MTOK / 64), 256, SMEM_O>>>(out);
}

// round 13
// speedup vs baseline: 7.5109x; 1.0147x over previous
#include <cuda_runtime.h>
#include <cuda_fp16.h>
#include <cstdint>

// ---------------------------------------------------------------------------
// InterleavedHeadAttention — round 13
//   - gemmO: KC=128, NSTG=2, depth-1 prefetch (halves the serial chunk chain)
//   - attention: 4-buffer KV ring, prefetch depth 3
//   - gemmA / prep unchanged from round 12
//   B=2, S=1024, HID=1024, H=16, P=2, D=64, sv=2048
// ---------------------------------------------------------------------------

#define NB 2
#define SEQ 1024
#define HIDD 1024
#define NH 16
#define NP 2
#define HD 64
#define SVLEN (SEQ * NP)        // 2048
#define MTOK (NB * SEQ)         // 2048
#define NPROJ (NH * NP * HD)    // 2048
#define ATTN_SCALE 0.125f
#define LOG2E 1.4426950408889634f

#define NEG_INF __int_as_float(0xff800000)

// fp16 storage, all natural layouts
__device__ __half g_Weff[3][NPROJ][HIDD];
__device__ __half g_Woeff[HIDD][NPROJ];      // [f][o*64+d]
__device__ __half g_Xr[MTOK][HIDD];
__device__ __half g_Q[NB * NH][SVLEN][HD];
__device__ __half g_K[NB * NH][SVLEN][HD];
__device__ __half g_Vt[NB * NH][HD][SVLEN];  // transposed
__device__ __half g_Aout[NB * NH][SVLEN][HD];

// ---------------------------------------------------------------------------
// helpers
// ---------------------------------------------------------------------------
__device__ __forceinline__ void cp16(uint32_t s, const void* g) {
    asm volatile("cp.async.cg.shared.global [%0], [%1], 16;" :: "r"(s), "l"(g));
}
__device__ __forceinline__ uint32_t smem_u32(const void* p) {
    uint32_t a;
    asm("{ .reg .u64 t; cvta.to.shared.u64 t, %1; cvt.u32.u64 %0, t; }"
        : "=r"(a) : "l"(p));
    return a;
}
#define CP_COMMIT() asm volatile("cp.async.commit_group;" ::: "memory")
#define CP_WAIT(n)  asm volatile("cp.async.wait_group %0;" :: "n"(n) : "memory")

__device__ __forceinline__ void st_h2(__half* p, float a, float b) {
    *(__half2*)p = __float22half2_rn(make_float2(a, b));
}
__device__ __forceinline__ uint32_t pack_h2(float a, float b) {
    __half2 h = __float22half2_rn(make_float2(a, b));
    return *(uint32_t*)&h;
}
__device__ __forceinline__ float ex2(float x) {
    float r;
    asm("ex2.approx.f32 %0, %1;" : "=f"(r) : "f"(x));
    return r;
}
// D(16x8) += A(16x16) * B(16x8), f16 in, f32 accum
__device__ __forceinline__ void mma_f16(float* c, const uint32_t* a,
                                        const uint32_t* b) {
    asm volatile(
        "mma.sync.aligned.m16n8k16.row.col.f32.f16.f16.f32 "
        "{%0,%1,%2,%3}, {%4,%5,%6,%7}, {%8,%9}, {%0,%1,%2,%3};"
        : "+f"(c[0]), "+f"(c[1]), "+f"(c[2]), "+f"(c[3])
        : "r"(a[0]), "r"(a[1]), "r"(a[2]), "r"(a[3]), "r"(b[0]), "r"(b[1]));
}
__device__ __forceinline__ void ldsm_x4(uint32_t& r0, uint32_t& r1,
                                        uint32_t& r2, uint32_t& r3, uint32_t a) {
    asm volatile("ldmatrix.sync.aligned.m8n8.x4.shared.b16 {%0,%1,%2,%3}, [%4];"
                 : "=r"(r0), "=r"(r1), "=r"(r2), "=r"(r3) : "r"(a));
}

// ---------------------------------------------------------------------------
// Fused prologue: y=0..2 build_weff(q/k/v), y=3 build_woeff, y=4 round_x.
// ---------------------------------------------------------------------------
__global__ __launch_bounds__(256) void prep_k(
    const float* __restrict__ x,
    const float* __restrict__ Wq, const float* __restrict__ Wk,
    const float* __restrict__ Wv, const float* __restrict__ Wo,
    const float* __restrict__ aq, const float* __restrict__ ak,
    const float* __restrict__ av, const float* __restrict__ cl)
{
    __shared__ float sS[512];
    const int tid = threadIdx.x;
    const int y = blockIdx.y;

    if (y < 3) {
        const float* W = (y == 0) ? Wq : (y == 1) ? Wk : Wv;
        const float* A = (y == 0) ? aq : (y == 1) ? ak : av;
        sS[tid] = A[tid];
        sS[tid + 256] = A[tid + 256];
        __syncthreads();
        int idx = blockIdx.x * 256 + tid;       // over 64*1024
        int d = idx >> 10, e = idx & 1023;
        float wv[NH];
#pragma unroll
        for (int m = 0; m < NH; m++)
            wv[m] = W[(m * HD + d) * HIDD + e];
        float scale = (y == 0) ? ATTN_SCALE * LOG2E : 1.0f;
#pragma unroll
        for (int hp = 0; hp < 32; hp++) {
            float acc = 0.f;
#pragma unroll
            for (int m = 0; m < NH; m++)
                acc += sS[m * 32 + hp] * wv[m];
            g_Weff[y][hp * HD + d][e] = __float2half_rn(acc * scale);
        }
    } else if (y == 3) {
        sS[tid] = cl[tid];
        sS[tid + 256] = cl[tid + 256];
        __syncthreads();
        int idx = blockIdx.x * 256 + tid;       // over 1024*64
        int f = idx >> 6, d = idx & 63;
        float wv[NH];
#pragma unroll
        for (int h = 0; h < NH; h++)
            wv[h] = Wo[f * HIDD + h * HD + d];
#pragma unroll
        for (int o = 0; o < 32; o++) {
            float acc = 0.f;
#pragma unroll
            for (int h = 0; h < NH; h++)
                acc += sS[h * 32 + o] * wv[h];
            g_Woeff[f][o * HD + d] = __float2half_rn(acc);
        }
    } else {
        const float4* x4 = (const float4*)x;
        uint2* dst = (uint2*)&g_Xr[0][0];
#pragma unroll
        for (int it = 0; it < 8; it++) {
            int idx4 = it * 65536 + blockIdx.x * 256 + tid;
            float4 v = x4[idx4];
            uint2 o;
            o.x = pack_h2(v.x, v.y);
            o.y = pack_h2(v.z, v.w);
            dst[idx4] = o;
        }
    }
}

// ---------------------------------------------------------------------------
// gemmA smem tiles: rows of 64 halves (128B), XOR chunk swizzle
// ---------------------------------------------------------------------------
#define G_TILEB 16384
#define G_STGB (2 * G_TILEB)
#define NSTG 3
#define SMEM_G (NSTG * G_STGB)           // 96 KB

// ---------------------------------------------------------------------------
// Projection GEMM (fp16): C[2048,2048] = Xr * Weff[z]^T, K=1024.
//   CTA 128x128, 8 warps (4M x 2N), warp 32x64, KC=64, LDSM fragments.
// ---------------------------------------------------------------------------
__global__ __launch_bounds__(256, 2) void gemmA_k()
{
    extern __shared__ __align__(16) char smc[];
    const int tid = threadIdx.x, wid = tid >> 5, lane = tid & 31;
    const int wm = (wid & 3) * 32;
    const int wn = (wid >> 2) * 64;
    const int bn = blockIdx.x * 128, bm = blockIdx.y * 128;
    const int which = blockIdx.z;
    const __half* Aw = &g_Xr[0][0];
    const __half* Bw = &g_Weff[which][0][0];
    const uint32_t sb = smem_u32(smc);
    const int fr = lane >> 2, fc = lane & 3;
    const int lrow = tid >> 1;
    const int cb = (tid & 1) * 4;

    const int li = lane & 7;
    const int g8 = (lane >> 3) & 1, g16 = lane >> 4;
    uint32_t rowOffA[2]; int rmA[2];
#pragma unroll
    for (int mt = 0; mt < 2; mt++) {
        int r = wm + mt * 16 + g8 * 8 + li;
        rowOffA[mt] = (uint32_t)r * 128; rmA[mt] = r & 7;
    }
    uint32_t rowOffB[4]; int rmB[4];
#pragma unroll
    for (int j = 0; j < 4; j++) {
        int r = wn + j * 16 + g16 * 8 + li;
        rowOffB[j] = (uint32_t)r * 128; rmB[j] = r & 7;
    }

    auto issue = [&](int kc) {
        int s = kc % NSTG;
        int k0 = kc * 64;
        uint32_t sa = sb + (uint32_t)s * G_STGB;
        uint32_t sbB = sa + G_TILEB;
        uint32_t dstrow = (uint32_t)lrow * 128;
        int swm = lrow & 7;
        const __half* asrc = Aw + (size_t)(bm + lrow) * HIDD + k0;
        const __half* bsrc = Bw + (size_t)(bn + lrow) * HIDD + k0;
#pragma unroll
        for (int c = 0; c < 4; c++) {
            int cc = cb + c;
            uint32_t off = dstrow + (uint32_t)((cc ^ swm) << 4);
            cp16(sa + off, asrc + cc * 8);
            cp16(sbB + off, bsrc + cc * 8);
        }
    };

    float acc[2][8][4];
#pragma unroll
    for (int mt = 0; mt < 2; mt++)
#pragma unroll
        for (int nt = 0; nt < 8; nt++)
#pragma unroll
            for (int j = 0; j < 4; j++) acc[mt][nt][j] = 0.f;

    issue(0); CP_COMMIT();
    issue(1); CP_COMMIT();

    const int NKC = HIDD / 64;
    for (int kc = 0; kc < NKC; kc++) {
        CP_WAIT(1);
        __syncthreads();
        if (kc + 2 < NKC) issue(kc + 2);
        CP_COMMIT();
        uint32_t Ab = sb + (uint32_t)(kc % NSTG) * G_STGB;
        uint32_t Bb = Ab + G_TILEB;
#pragma unroll
        for (int k16 = 0; k16 < 4; k16++) {
            uint32_t afr[2][4], bfr[8][2];
#pragma unroll
            for (int mt = 0; mt < 2; mt++) {
                uint32_t a = Ab + rowOffA[mt] +
                    (uint32_t)((((2 * k16) + g16) ^ rmA[mt]) << 4);
                ldsm_x4(afr[mt][0], afr[mt][1], afr[mt][2], afr[mt][3], a);
            }
#pragma unroll
            for (int j = 0; j < 4; j++) {
                uint32_t a = Bb + rowOffB[j] +
                    (uint32_t)((((2 * k16) + g8) ^ rmB[j]) << 4);
                ldsm_x4(bfr[2 * j][0], bfr[2 * j][1],
                        bfr[2 * j + 1][0], bfr[2 * j + 1][1], a);
            }
#pragma unroll
            for (int mt = 0; mt < 2; mt++)
#pragma unroll
                for (int nt = 0; nt < 8; nt++)
                    mma_f16(acc[mt][nt], afr[mt], bfr[nt]);
        }
    }

    // ---- epilogue (natural layouts) ----
    if (which == 2) {
        int h = bn >> 7, p = (wn >> 6) & 1;
#pragma unroll
        for (int mt = 0; mt < 2; mt++) {
#pragma unroll
            for (int half_ = 0; half_ < 2; half_++) {
                int row = bm + wm + mt * 16 + fr + half_ * 8;
                int b = row >> 10, n = row & 1023;
                int kv = n * NP + p;
                __half* Vt = &g_Vt[b * NH + h][0][0];
#pragma unroll
                for (int nt = 0; nt < 8; nt++) {
                    int d = nt * 8 + 2 * fc;
                    Vt[(size_t)d * SVLEN + kv] =
                        __float2half_rn(acc[mt][nt][half_ * 2 + 0]);
                    Vt[(size_t)(d + 1) * SVLEN + kv] =
                        __float2half_rn(acc[mt][nt][half_ * 2 + 1]);
                }
            }
        }
    } else {
        __half* dst0 = (which == 0) ? &g_Q[0][0][0] : &g_K[0][0][0];
#pragma unroll
        for (int mt = 0; mt < 2; mt++) {
#pragma unroll
            for (int half_ = 0; half_ < 2; half_++) {
                int row = bm + wm + mt * 16 + fr + half_ * 8;
                int b = row >> 10, n = row & 1023;
#pragma unroll
                for (int nt = 0; nt < 8; nt++) {
                    int col = bn + wn + nt * 8 + 2 * fc;
                    int h = col >> 7, p = (col >> 6) & 1, d = col & 63;
                    __half* dst = dst0 +
                        ((size_t)(b * NH + h) * SVLEN + n * NP + p) * HD + d;
                    st_h2(dst, acc[mt][nt][half_ * 2 + 0],
                               acc[mt][nt][half_ * 2 + 1]);
                }
            }
        }
    }
}

// ---------------------------------------------------------------------------
// Output GEMM (fp16): out[2048,1024] = gather(g_Aout) * Woeff^T, K=2048.
//   CTA 64x128, KC=128 (16 chunks), NSTG=2 depth-1 prefetch, 256 CTAs.
//   Rows of 128 halves (256B); swizzle flips low 3 chunk bits only.
// ---------------------------------------------------------------------------
#define O_AB 16384                       // A tile: 64 rows x 256B
#define O_BB 32768                       // B tile: 128 rows x 256B
#define O_STGB (O_AB + O_BB)             // 48 KB / stage
#define SMEM_O (2 * O_STGB)              // 96 KB

__global__ __launch_bounds__(256, 2) void gemmO_k(float* __restrict__ Cout)
{
    extern __shared__ __align__(16) char smc[];
    const int tid = threadIdx.x, wid = tid >> 5, lane = tid & 31;
    const int wm = (wid & 1) * 32;
    const int wn = (wid >> 1) * 32;
    const int bn = blockIdx.x * 128, bm = blockIdx.y * 64;
    const __half* Bw = &g_Woeff[0][0];
    const uint32_t sb = smem_u32(smc);
    const int fr = lane >> 2, fc = lane & 3;

    const int li = lane & 7;
    const int g8 = (lane >> 3) & 1, g16 = lane >> 4;
    uint32_t rowOffA[2]; int rmA[2];
#pragma unroll
    for (int mt = 0; mt < 2; mt++) {
        int r = wm + mt * 16 + g8 * 8 + li;
        rowOffA[mt] = (uint32_t)r * 256; rmA[mt] = r & 7;
    }
    uint32_t rowOffB[2]; int rmB[2];
#pragma unroll
    for (int j = 0; j < 2; j++) {
        int r = wn + j * 16 + g16 * 8 + li;
        rowOffB[j] = (uint32_t)r * 256; rmB[j] = r & 7;
    }

    // A: 64 rows x 16 chunks = 1024 cp16 -> 4/thread (conflict-spread mapping)
    const int arow = tid >> 2;
    const int ab2 = (tid & 3) * 2;
    // B: 128 rows x 16 chunks = 2048 -> 8/thread
    const int brow = tid >> 1;
    const int bb4 = (tid & 1) * 4;

    int ta = bm + arow;
    int gb = ta >> 10, gn = ta & 1023;

    auto issue = [&](int kc) {
        int s = kc & 1;
        int k0 = kc * 128;
        uint32_t sa = sb + (uint32_t)s * O_STGB;
        uint32_t sbB = sa + O_AB;
        {
            uint32_t dstrow = (uint32_t)arow * 256;
            int swm = arow & 7;
#pragma unroll
            for (int c = 0; c < 4; c++) {
                int cc = ab2 + (c & 1) + (c >> 1) * 8;  // lanes 16 banks apart
                uint32_t off = dstrow + (uint32_t)((cc ^ swm) << 4);
                int col = k0 + cc * 8;
                int o = col >> 6, dd = col & 63;
                cp16(sa + off,
                     &g_Aout[gb * NH + (o >> 1)][gn * NP + (o & 1)][dd]);
            }
        }
        {
            uint32_t dstrow = (uint32_t)brow * 256;
            int swm = brow & 7;
            const __half* bsrc = Bw + (size_t)(bn + brow) * NPROJ + k0;
#pragma unroll
            for (int c = 0; c < 8; c++) {
                int cc = bb4 + (c & 3) + (c >> 2) * 8;
                uint32_t off = dstrow + (uint32_t)((cc ^ swm) << 4);
                cp16(sbB + off, bsrc + cc * 8);
            }
        }
    };

    float acc[2][4][4];
#pragma unroll
    for (int mt = 0; mt < 2; mt++)
#pragma unroll
        for (int nt = 0; nt < 4; nt++)
#pragma unroll
            for (int j = 0; j < 4; j++) acc[mt][nt][j] = 0.f;

    issue(0); CP_COMMIT();

    const int NKC = NPROJ / 128;   // 16
    for (int kc = 0; kc < NKC; kc++) {
        CP_WAIT(0);                // chunk kc fully landed
        __syncthreads();           // visible to all; all done with kc-1's buf
        if (kc + 1 < NKC) issue(kc + 1);
        CP_COMMIT();
        uint32_t Ab = sb + (uint32_t)(kc & 1) * O_STGB;
        uint32_t Bb = Ab + O_AB;
#pragma unroll
        for (int k16 = 0; k16 < 8; k16++) {
            uint32_t afr[2][4], bfr[4][2];
#pragma unroll
            for (int mt = 0; mt < 2; mt++) {
                uint32_t a = Ab + rowOffA[mt] +
                    (uint32_t)((((2 * k16) + g16) ^ rmA[mt]) << 4);
                ldsm_x4(afr[mt][0], afr[mt][1], afr[mt][2], afr[mt][3], a);
            }
#pragma unroll
            for (int j = 0; j < 2; j++) {
                uint32_t a = Bb + rowOffB[j] +
                    (uint32_t)((((2 * k16) + g8) ^ rmB[j]) << 4);
                ldsm_x4(bfr[2 * j][0], bfr[2 * j][1],
                        bfr[2 * j + 1][0], bfr[2 * j + 1][1], a);
            }
#pragma unroll
            for (int mt = 0; mt < 2; mt++)
#pragma unroll
                for (int nt = 0; nt < 4; nt++)
                    mma_f16(acc[mt][nt], afr[mt], bfr[nt]);
        }
    }

#pragma unroll
    for (int mt = 0; mt < 2; mt++) {
#pragma unroll
        for (int half_ = 0; half_ < 2; half_++) {
            int row = bm + wm + mt * 16 + fr + half_ * 8;
#pragma unroll
            for (int nt = 0; nt < 4; nt++) {
                int col = bn + wn + nt * 8 + 2 * fc;
                *(float2*)(Cout + (size_t)row * HIDD + col) = make_float2(
                    acc[mt][nt][half_ * 2 + 0], acc[mt][nt][half_ * 2 + 1]);
            }
        }
    }
}

// ---------------------------------------------------------------------------
// Causal flash attention (fp16 MMA + LDSM, log2-domain softmax):
//   q-tile 128 (warp 16 rows), k-tile 64, 4-buffer KV ring (prefetch depth 3),
//   Q fragments preloaded, P in registers.
// ---------------------------------------------------------------------------
#define Q_B 16384
#define KV_B 8192
#define ATTN_NBUF 4
#define SMEM_ATTN (Q_B + ATTN_NBUF * 2 * KV_B)   // 81,920 B

__global__ __launch_bounds__(256, 2) void attn_k()
{
    extern __shared__ __align__(16) char smc[];
    const uint32_t sQ = smem_u32(smc);
    const uint32_t sKV = sQ + Q_B;

    const int bh = blockIdx.y;
    const int qt = (gridDim.x - 1) - blockIdx.x;   // heavy tiles first
    const int qstart = qt * 128;
    const __half* Qg = &g_Q[bh][0][0];
    const __half* Kg = &g_K[bh][0][0];
    const __half* Vtg = &g_Vt[bh][0][0];

    const int tid = threadIdx.x;
    const int wq = tid >> 5;
    const int lane = tid & 31;
    const int fr = lane >> 2;
    const int fc = lane & 3;
    const int r0 = wq * 16 + fr, r1 = r0 + 8;

    const int li = lane & 7;
    const int g8 = (lane >> 3) & 1, g16 = lane >> 4;
    const int rowQ = wq * 16 + g8 * 8 + li;
    const uint32_t rowOffQ = (uint32_t)rowQ * 128;
    const int rmQ = rowQ & 7;
    uint32_t rowOffKV[4]; int rmKV[4];
#pragma unroll
    for (int j = 0; j < 4; j++) {
        int r = j * 16 + g16 * 8 + li;
        rowOffKV[j] = (uint32_t)r * 128; rmKV[j] = r & 7;
    }

    auto issue_kv = [&](int jt) {
        int buf = jt % ATTN_NBUF;
        uint32_t sK = sKV + (uint32_t)buf * (2 * KV_B);
        uint32_t sV = sK + KV_B;
        int kstart = jt * 64;
#pragma unroll
        for (int it = 0; it < 2; it++) {
            int chunk = tid + 256 * it;
            int row = chunk >> 3;
            int cc = chunk & 7;
            uint32_t off = (uint32_t)row * 128 +
                           (uint32_t)((cc ^ (row & 7)) << 4);
            cp16(sK + off, Kg + (size_t)(kstart + row) * HD + cc * 8);
            cp16(sV + off, Vtg + (size_t)row * SVLEN + kstart + cc * 8);
        }
    };

    // prologue: (Q + kv0) group, kv1 group, kv2 group
#pragma unroll
    for (int it = 0; it < 4; it++) {
        int chunk = tid + 256 * it;
        int row = chunk >> 3;
        int cc = chunk & 7;
        uint32_t off = (uint32_t)row * 128 + (uint32_t)((cc ^ (row & 7)) << 4);
        cp16(sQ + off, Qg + (size_t)(qstart + row) * HD + cc * 8);
    }
    issue_kv(0); CP_COMMIT();
    issue_kv(1); CP_COMMIT();
    issue_kv(2); CP_COMMIT();      // may overrun jmax; in-bounds (sv=2048)

    float O[8][4];
    float m0 = NEG_INF, m1 = NEG_INF, l0 = 0.f, l1 = 0.f;
#pragma unroll
    for (int nt = 0; nt < 8; nt++)
#pragma unroll
        for (int j = 0; j < 4; j++) O[nt][j] = 0.f;

    uint32_t qfr[4][4];

    const int jmax = 2 * qt + 1;
    for (int jt = 0; jt <= jmax; jt++) {
        const int kstart = jt * 64;
        CP_WAIT(2);           // tile jt (and Q at jt=0) complete
        __syncthreads();      // all warps finished with buf (jt-1)
        if (jt + 3 <= jmax) issue_kv(jt + 3);   // writes buf (jt-1)%4 — safe
        CP_COMMIT();
        uint32_t Kb = sKV + (uint32_t)(jt % ATTN_NBUF) * (2 * KV_B);
        uint32_t Vb = Kb + KV_B;

        if (jt == 0) {
#pragma unroll
            for (int k16 = 0; k16 < 4; k16++) {
                uint32_t a = sQ + rowOffQ +
                    (uint32_t)((((2 * k16) + g16) ^ rmQ) << 4);
                ldsm_x4(qfr[k16][0], qfr[k16][1], qfr[k16][2], qfr[k16][3], a);
            }
        }

        // ---- S = Q K^T (pre-scaled by scale*log2e) ----
        float s[8][4];
#pragma unroll
        for (int nt = 0; nt < 8; nt++)
#pragma unroll
            for (int j = 0; j < 4; j++) s[nt][j] = 0.f;
#pragma unroll
        for (int k16 = 0; k16 < 4; k16++) {
            uint32_t bfr[8][2];
#pragma unroll
            for (int j = 0; j < 4; j++) {
                uint32_t a = Kb + rowOffKV[j] +
                    (uint32_t)((((2 * k16) + g8) ^ rmKV[j]) << 4);
                ldsm_x4(bfr[2 * j][0], bfr[2 * j][1],
                        bfr[2 * j + 1][0], bfr[2 * j + 1][1], a);
            }
#pragma unroll
            for (int nt = 0; nt < 8; nt++)
                mma_f16(s[nt], qfr[k16], bfr[nt]);
        }

        // causal mask
        if (kstart + 63 > qstart + wq * 16) {
            int gr0 = qstart + r0, gr1 = gr0 + 8;
#pragma unroll
            for (int nt = 0; nt < 8; nt++) {
                int c0 = kstart + nt * 8 + 2 * fc;
                if (c0 > gr0)     s[nt][0] = NEG_INF;
                if (c0 + 1 > gr0) s[nt][1] = NEG_INF;
                if (c0 > gr1)     s[nt][2] = NEG_INF;
                if (c0 + 1 > gr1) s[nt][3] = NEG_INF;
            }
        }

        // ---- online softmax in log2 domain ----
        float mx0 = NEG_INF, mx1 = NEG_INF;
#pragma unroll
        for (int nt = 0; nt < 8; nt++) {
            mx0 = fmaxf(mx0, fmaxf(s[nt][0], s[nt][1]));
            mx1 = fmaxf(mx1, fmaxf(s[nt][2], s[nt][3]));
        }
        mx0 = fmaxf(mx0, __shfl_xor_sync(0xffffffffu, mx0, 1));
        mx0 = fmaxf(mx0, __shfl_xor_sync(0xffffffffu, mx0, 2));
        mx1 = fmaxf(mx1, __shfl_xor_sync(0xffffffffu, mx1, 1));
        mx1 = fmaxf(mx1, __shfl_xor_sync(0xffffffffu, mx1, 2));
        float newm0 = fmaxf(m0, mx0), newm1 = fmaxf(m1, mx1);
        float al0 = ex2(m0 - newm0), al1 = ex2(m1 - newm1);

        uint32_t pfr[4][4];
        float rs0 = 0.f, rs1 = 0.f;
#pragma unroll
        for (int nt = 0; nt < 8; nt++) {
            float p0 = ex2(s[nt][0] - newm0);
            float p1 = ex2(s[nt][1] - newm0);
            float p2 = ex2(s[nt][2] - newm1);
            float p3 = ex2(s[nt][3] - newm1);
            rs0 += p0 + p1; rs1 += p2 + p3;
            int t16 = nt >> 1, hi = nt & 1;
            pfr[t16][hi * 2 + 0] = pack_h2(p0, p1);   // row r0
            pfr[t16][hi * 2 + 1] = pack_h2(p2, p3);   // row r1
        }
        rs0 += __shfl_xor_sync(0xffffffffu, rs0, 1);
        rs0 += __shfl_xor_sync(0xffffffffu, rs0, 2);
        rs1 += __shfl_xor_sync(0xffffffffu, rs1, 1);
        rs1 += __shfl_xor_sync(0xffffffffu, rs1, 2);
        l0 = l0 * al0 + rs0; l1 = l1 * al1 + rs1;
        m0 = newm0; m1 = newm1;
#pragma unroll
        for (int nt = 0; nt < 8; nt++) {
            O[nt][0] *= al0; O[nt][1] *= al0;
            O[nt][2] *= al1; O[nt][3] *= al1;
        }

        // ---- O += P V (A in regs; B via LDSM from Vts[d][kv]) ----
#pragma unroll
        for (int k16 = 0; k16 < 4; k16++) {
            uint32_t bfr[8][2];
#pragma unroll
            for (int j = 0; j < 4; j++) {
                uint32_t a = Vb + rowOffKV[j] +
                    (uint32_t)((((2 * k16) + g8) ^ rmKV[j]) << 4);
                ldsm_x4(bfr[2 * j][0], bfr[2 * j][1],
                        bfr[2 * j + 1][0], bfr[2 * j + 1][1], a);
            }
#pragma unroll
            for (int nt = 0; nt < 8; nt++)
                mma_f16(O[nt], pfr[k16], bfr[nt]);
        }
    }

    // epilogue: normalize, store natural fp16 into g_Aout
    __half* Ag = &g_Aout[bh][0][0];
    float inv0 = 1.f / l0, inv1 = 1.f / l1;
#pragma unroll
    for (int nt = 0; nt < 8; nt++) {
        int pos = nt * 8 + 2 * fc;
        st_h2(Ag + (size_t)(qstart + r0) * HD + pos,
              O[nt][0] * inv0, O[nt][1] * inv0);
        st_h2(Ag + (size_t)(qstart + r1) * HD + pos,
              O[nt][2] * inv1, O[nt][3] * inv1);
    }
}

// ---------------------------------------------------------------------------
// launch
// ---------------------------------------------------------------------------
extern "C" void kernel_launch(void* const* d_in, const int* in_sizes, int n_in,
                              void* d_out, int out_size)
{
    const float* x  = (const float*)d_in[0];
    const float* Wq = (const float*)d_in[1];
    const float* Wk = (const float*)d_in[2];
    const float* Wv = (const float*)d_in[3];
    const float* Wo = (const float*)d_in[4];
    const float* aq = (const float*)d_in[5];
    const float* ak = (const float*)d_in[6];
    const float* av = (const float*)d_in[7];
    const float* cl = (const float*)d_in[8];
    float* out = (float*)d_out;

    cudaFuncSetAttribute(gemmA_k, cudaFuncAttributeMaxDynamicSharedMemorySize, SMEM_G);
    cudaFuncSetAttribute(gemmO_k, cudaFuncAttributeMaxDynamicSharedMemorySize, SMEM_O);
    cudaFuncSetAttribute(attn_k, cudaFuncAttributeMaxDynamicSharedMemorySize, SMEM_ATTN);

    // fused prologue: weight builds + x rounding, all concurrent
    prep_k<<<dim3(256, 5), 256>>>(x, Wq, Wk, Wv, Wo, aq, ak, av, cl);

    // projections + head mixing (q/k/v via z)
    gemmA_k<<<dim3(NPROJ / 128, MTOK / 128, 3), 256, SMEM_G>>>();

    // causal SDPA over virtual positions
    attn_k<<<dim3(SVLEN / 128, NB * NH), 256, SMEM_ATTN>>>();

    // collapse + output projection (256 CTAs, KC=128)
    gemmO_k<<<dim3(HIDD / 128, MTOK / 64), 256, SMEM_O>>>(out);
}